// round 8
// baseline (speedup 1.0000x reference)
#include <cuda_runtime.h>
#include <math.h>
#include <stdint.h>

#define B_   8
#define NQ   8192
#define MK   2048
typedef unsigned short ushortT;
typedef unsigned int   uintT;

// ===================== helpers =====================
__device__ __forceinline__ uint32_t smem_to_u32(const void* p) {
    uint32_t a;
    asm("{ .reg .u64 t; cvta.to.shared.u64 t, %1; cvt.u32.u64 %0, t; }" : "=r"(a) : "l"(p));
    return a;
}
#define CP_ASYNC16(s, g) \
    asm volatile("cp.async.cg.shared.global [%0], [%1], 16;" :: "r"(s), "l"(g))
#define CP_COMMIT() asm volatile("cp.async.commit_group;")
#define CP_WAIT2()  asm volatile("cp.async.wait_group 2;")

__device__ __forceinline__ void ldsm4(uint32_t& r0, uint32_t& r1, uint32_t& r2, uint32_t& r3,
                                      uint32_t addr) {
    asm volatile("ldmatrix.sync.aligned.m8n8.x4.shared.b16 {%0,%1,%2,%3}, [%4];"
                 : "=r"(r0), "=r"(r1), "=r"(r2), "=r"(r3) : "r"(addr));
}
__device__ __forceinline__ void mma16816(float* d, const uint32_t* a, const uint32_t* b) {
    asm volatile(
        "mma.sync.aligned.m16n8k16.row.col.f32.bf16.bf16.f32 "
        "{%0,%1,%2,%3}, {%4,%5,%6,%7}, {%8,%9}, {%0,%1,%2,%3};"
        : "+f"(d[0]), "+f"(d[1]), "+f"(d[2]), "+f"(d[3])
        : "r"(a[0]), "r"(a[1]), "r"(a[2]), "r"(a[3]), "r"(b[0]), "r"(b[1]));
}

// fp32 -> bf16 hi + bf16 lo (RNE)
__device__ __forceinline__ void split_bf(float v, ushortT& h, ushortT& l) {
    uintT u = __float_as_uint(v);
    uintT hb = (u + 0x7fffu + ((u >> 16) & 1u)) >> 16;
    h = (ushortT)hb;
    float r = v - __uint_as_float(hb << 16);
    uintT u2 = __float_as_uint(r);
    l = (ushortT)((u2 + 0x7fffu + ((u2 >> 16) & 1u)) >> 16);
}

__device__ __forceinline__ void ins3(float& d0, int& i0, float& d1, int& i1,
                                     float& d2, int& i2, float dd, int m) {
    if (dd < d2) {
        if (dd < d1) {
            d2 = d1; i2 = i1;
            if (dd < d0) { d1 = d0; i1 = i0; d0 = dd; i0 = m; }
            else          { d1 = dd; i1 = m; }
        } else { d2 = dd; i2 = m; }
    }
}

// ===================== scratch =====================
__device__ ushortT gA1[(size_t)8 * 8192 * 1024];  // [H(512) | L(512)]
__device__ ushortT gA2[(size_t)8 * 8192 * 512];   // [H(256) | L(256)]
__device__ ushortT gW1[256 * 1536];               // [Wh | Wl | Wh]
__device__ ushortT gW2[256 * 768];
__device__ float g_h  [(size_t)8 * 8192 * 256];
__device__ float g_kfT[(size_t)8 * 2048 * 256];
__device__ int   g_idx[8 * 8192 * 3];
__device__ float g_wgt[8 * 8192 * 3];
__device__ float g_E  [8 * 8192];
__device__ float g_En [8 * 8192];
__device__ float g_sumA[8 * 32];
__device__ float g_ctx[8 * 256];
__device__ float g_al1[256], g_be1[256], g_al2[256], g_be2[256];
__device__ float g_c2[32];

// ===================== prep =====================
__global__ void prep_kernel(const float* __restrict__ cb1, const float* __restrict__ gg1,
                            const float* __restrict__ bb1, const float* __restrict__ mm1,
                            const float* __restrict__ vv1,
                            const float* __restrict__ cb2, const float* __restrict__ gg2,
                            const float* __restrict__ bb2, const float* __restrict__ mm2,
                            const float* __restrict__ vv2,
                            const float* __restrict__ cw)
{
    int i = blockIdx.x * blockDim.x + threadIdx.x;
    if (i < 256) {
        float s1 = gg1[i] * rsqrtf(vv1[i] + 1e-5f);
        g_al1[i] = s1;
        g_be1[i] = s1 * (cb1[i] - mm1[i]) + bb1[i];
        float s2 = gg2[i] * rsqrtf(vv2[i] + 1e-5f);
        g_al2[i] = s2;
        g_be2[i] = s2 * (cb2[i] - mm2[i]) + bb2[i];
    }
    if (i < 32) {
        float s = 0.f;
        const float* c = cw + i * 256;
        for (int d = 0; d < 256; d++) s += c[d] * c[d];
        g_c2[i] = s;
    }
    if (i < 8 * 32) g_sumA[i] = 0.f;
    if (i < 8 * 8192) g_E[i] = 0.f;
}

__global__ void expand_w_kernel(const float* __restrict__ w1, const float* __restrict__ w2)
{
    int i = blockIdx.x * 256 + threadIdx.x;
    if (i < 256 * 512) {
        int n = i >> 9, k = i & 511;
        ushortT h, l; split_bf(w1[i], h, l);
        gW1[n * 1536 + k] = h; gW1[n * 1536 + 512 + k] = l; gW1[n * 1536 + 1024 + k] = h;
    }
    if (i < 256 * 256) {
        int n = i >> 8, k = i & 255;
        ushortT h, l; split_bf(w2[i], h, l);
        gW2[n * 768 + k] = h; gW2[n * 768 + 256 + k] = l; gW2[n * 768 + 512 + k] = h;
    }
}

// ---------------- transpose known_feats (B,256,2048) -> (B,2048,256) ----------------
__global__ void tr_kf_kernel(const float* __restrict__ kf)
{
    __shared__ float tile[32][33];
    int b = blockIdx.z;
    int m0 = blockIdx.x * 32, c0 = blockIdx.y * 32;
    int tx = threadIdx.x, ty = threadIdx.y;
    const float* in = kf + (size_t)b * 256 * MK;
#pragma unroll
    for (int j = 0; j < 32; j += 8)
        tile[ty + j][tx] = in[(size_t)(c0 + ty + j) * MK + m0 + tx];
    __syncthreads();
    float* out = g_kfT + (size_t)b * MK * 256;
#pragma unroll
    for (int j = 0; j < 32; j += 8)
        out[(size_t)(m0 + ty + j) * 256 + c0 + tx] = tile[tx][ty + j];
}

// ---------------- transpose unknow_feats -> gA1 cols [256,512) H, [768,1024) L -------
__global__ void tr_unk_kernel(const float* __restrict__ uf)
{
    __shared__ float tile[32][33];
    int b = blockIdx.z;
    int n0 = blockIdx.x * 32, c0 = blockIdx.y * 32;
    int tx = threadIdx.x, ty = threadIdx.y;
    const float* in = uf + (size_t)b * 256 * NQ;
#pragma unroll
    for (int j = 0; j < 32; j += 8)
        tile[ty + j][tx] = in[(size_t)(c0 + ty + j) * NQ + n0 + tx];
    __syncthreads();
#pragma unroll
    for (int j = 0; j < 32; j += 8) {
        float v = tile[tx][ty + j];
        ushortT h, l; split_bf(v, h, l);
        size_t row = ((size_t)b * NQ + n0 + ty + j) * 1024;
        gA1[row + 256 + c0 + tx] = h;
        gA1[row + 768 + c0 + tx] = l;
    }
}

// ---------------- three_nn: 4 threads/query, padded chunks, 3-FMA inner loop --------
#define CHPAD 513
__global__ __launch_bounds__(256) void three_nn_kernel(const float* __restrict__ unknown,
                                                       const float* __restrict__ known)
{
    __shared__ float4 kp[4 * CHPAD];
    int bz = blockIdx.y;
    int t  = threadIdx.x;
    int q  = blockIdx.x * 64 + (t >> 2);
    int ck = t & 3;

    const float* kb = known + (size_t)bz * MK * 3;
    for (int i = t; i < MK; i += 256) {
        float kx = kb[i * 3 + 0];
        float ky = kb[i * 3 + 1];
        float kz = kb[i * 3 + 2];
        kp[(i >> 9) * CHPAD + (i & 511)] = make_float4(kx, ky, kz, kx * kx + ky * ky + kz * kz);
    }
    __syncthreads();

    const float* u = unknown + ((size_t)bz * NQ + q) * 3;
    float ux = u[0], uy = u[1], uz = u[2];
    float x2 = ux * ux + uy * uy + uz * uz;
    float mux = -2.f * ux, muy = -2.f * uy, muz = -2.f * uz;

    float d0 = 1e30f, d1 = 1e30f, d2 = 1e30f;
    int   i0 = 0, i1 = 0, i2 = 0;
    const float4* base = kp + ck * CHPAD;
    int m0 = ck * 512;
#pragma unroll 4
    for (int j = 0; j < 512; j++) {
        float4 p = base[j];
        float dd = fmaf(mux, p.x, p.w);
        dd = fmaf(muy, p.y, dd);
        dd = fmaf(muz, p.z, dd);
        ins3(d0, i0, d1, i1, d2, i2, dd, m0 + j);
    }

#pragma unroll
    for (int off = 1; off <= 2; off <<= 1) {
        float e0 = __shfl_xor_sync(0xffffffffu, d0, off);
        float e1 = __shfl_xor_sync(0xffffffffu, d1, off);
        float e2 = __shfl_xor_sync(0xffffffffu, d2, off);
        int   j0 = __shfl_xor_sync(0xffffffffu, i0, off);
        int   j1 = __shfl_xor_sync(0xffffffffu, i1, off);
        int   j2 = __shfl_xor_sync(0xffffffffu, i2, off);
        ins3(d0, i0, d1, i1, d2, i2, e0, j0);
        ins3(d0, i0, d1, i1, d2, i2, e1, j1);
        ins3(d0, i0, d1, i1, d2, i2, e2, j2);
    }

    if (ck == 0) {
        float r0 = 1.f / (sqrtf(fmaxf(d0 + x2, 1e-12f)) + 1e-8f);
        float r1 = 1.f / (sqrtf(fmaxf(d1 + x2, 1e-12f)) + 1e-8f);
        float r2 = 1.f / (sqrtf(fmaxf(d2 + x2, 1e-12f)) + 1e-8f);
        float rs = 1.f / (r0 + r1 + r2);
        size_t base2 = ((size_t)bz * NQ + q) * 3;
        g_idx[base2 + 0] = i0; g_idx[base2 + 1] = i1; g_idx[base2 + 2] = i2;
        g_wgt[base2 + 0] = r0 * rs; g_wgt[base2 + 1] = r1 * rs; g_wgt[base2 + 2] = r2 * rs;
    }
}

// ---------------- interpolate -> gA1 cols [0,256) H, [512,768) L (4-wide) -----------
__global__ __launch_bounds__(256) void interp_kernel()
{
    int bz = blockIdx.y, t = threadIdx.x;
    int n = blockIdx.x * 4 + (t >> 6);
    int d = (t & 63) * 4;
    size_t base = ((size_t)bz * NQ + n) * 3;
    int i0 = g_idx[base], i1 = g_idx[base + 1], i2 = g_idx[base + 2];
    float w0 = g_wgt[base], w1 = g_wgt[base + 1], w2 = g_wgt[base + 2];
    const float* kf = g_kfT + (size_t)bz * MK * 256;
    float4 a = *(const float4*)&kf[(size_t)i0 * 256 + d];
    float4 b = *(const float4*)&kf[(size_t)i1 * 256 + d];
    float4 c = *(const float4*)&kf[(size_t)i2 * 256 + d];
    float v0 = w0 * a.x + w1 * b.x + w2 * c.x;
    float v1 = w0 * a.y + w1 * b.y + w2 * c.y;
    float v2 = w0 * a.z + w1 * b.z + w2 * c.z;
    float v3 = w0 * a.w + w1 * b.w + w2 * c.w;
    ushortT h0, l0, h1, l1, h2, l2, h3, l3;
    split_bf(v0, h0, l0); split_bf(v1, h1, l1);
    split_bf(v2, h2, l2); split_bf(v3, h3, l3);
    size_t row = ((size_t)bz * NQ + n) * 1024;
    uint2 hp = make_uint2((uintT)h0 | ((uintT)h1 << 16), (uintT)h2 | ((uintT)h3 << 16));
    uint2 lp = make_uint2((uintT)l0 | ((uintT)l1 << 16), (uintT)l2 | ((uintT)l3 << 16));
    *(uint2*)&gA1[row + d]       = hp;
    *(uint2*)&gA1[row + 512 + d] = lp;
}

// ===================== HMMA GEMM: 128x256 CTA tile, 64x64 warp tiles =====================
// 8 warps (2m x 4n); per k16: 4 ldsm4 (A) + 4 ldsm4 (B pairs) for 32 HMMA.
template <int L>
__global__ __launch_bounds__(256, 1) void gemm_mma()
{
    constexpr int K   = (L == 1) ? 512 : 256;
    constexpr int CPB = K / 32;
    constexpr int NCH = 3 * CPB;
    constexpr int KA  = 2 * K;
    constexpr int KW  = 3 * K;
    const ushortT* Ag = (L == 1) ? gA1 : gA2;
    const ushortT* Wg = (L == 1) ? gW1 : gW2;
    const float* alpha = (L == 1) ? g_al1 : g_al2;
    const float* beta  = (L == 1) ? g_be1 : g_be2;

    extern __shared__ __align__(16) ushortT dyn[];
    // layout: A stages 4 x 4096 ushort (8KB), B stages 4 x 8192 ushort (16KB), alpha/beta
    ushortT* sA = dyn;
    ushortT* sB = dyn + 4 * 4096;
    float* s_al = (float*)(dyn + 4 * 4096 + 4 * 8192);
    float* s_be = s_al + 256;

    int tid = threadIdx.x, wid = tid >> 5, lane = tid & 31;
    int bm = blockIdx.x * 128;
    s_al[tid] = alpha[tid];
    s_be[tid] = beta[tid];

    uint32_t sAb = smem_to_u32(sA);
    uint32_t sBb = smem_to_u32(sB);

    // A loader: 128 rows x 4 segs, 2 segs per thread
    int lr = tid >> 1;
    int ls = (tid & 1) * 2;
    uint32_t aoff0 = lr * 64 + (((ls)     ^ (lr & 3)) << 4);
    uint32_t aoff1 = lr * 64 + (((ls + 1) ^ (lr & 3)) << 4);
    const ushortT* Arow = Ag + (size_t)(bm + lr) * KA;

    // B loader: 256 rows x 4 segs, 4 segs per thread (row = tid)
    int brow = tid;
    uint32_t boff0 = brow * 64 + (((0) ^ (brow & 3)) << 4);
    uint32_t boff1 = brow * 64 + (((1) ^ (brow & 3)) << 4);
    uint32_t boff2 = brow * 64 + (((2) ^ (brow & 3)) << 4);
    uint32_t boff3 = brow * 64 + (((3) ^ (brow & 3)) << 4);
    const ushortT* Wrow = Wg + (size_t)brow * KW;

#define LOAD_CHUNK(p) do { \
    int _blk = (p) / CPB; \
    int _acol = (_blk == 2 ? K : 0) + ((p) % CPB) * 32; \
    int _wcol = (p) * 32; \
    uint32_t _as = sAb + ((p) & 3) * 8192; \
    uint32_t _ws = sBb + ((p) & 3) * 16384; \
    CP_ASYNC16(_as + aoff0, Arow + _acol + ls * 8); \
    CP_ASYNC16(_as + aoff1, Arow + _acol + ls * 8 + 8); \
    CP_ASYNC16(_ws + boff0, Wrow + _wcol + 0); \
    CP_ASYNC16(_ws + boff1, Wrow + _wcol + 8); \
    CP_ASYNC16(_ws + boff2, Wrow + _wcol + 16); \
    CP_ASYNC16(_ws + boff3, Wrow + _wcol + 24); \
    CP_COMMIT(); } while (0)

    // prologue: 3 chunks in flight
    LOAD_CHUNK(0);
    LOAD_CHUNK(1);
    LOAD_CHUNK(2);

    float c[4][8][4];
#pragma unroll
    for (int i = 0; i < 4; i++)
#pragma unroll
        for (int j = 0; j < 8; j++)
#pragma unroll
            for (int q = 0; q < 4; q++) c[i][j][q] = 0.f;

    int wm = wid >> 2, wn = wid & 3;

    for (int kc = 0; kc < NCH; kc++) {
        CP_WAIT2();
        __syncthreads();
        int kn = kc + 3;
        if (kn < NCH) LOAD_CHUNK(kn);
        uint32_t aBase = sAb + (kc & 3) * 8192;
        uint32_t bBase = sBb + (kc & 3) * 16384;
#pragma unroll
        for (int kk = 0; kk < 2; kk++) {
            uint32_t afr[4][4], bfr[8][2];
#pragma unroll
            for (int mt = 0; mt < 4; mt++) {
                int r = wm * 64 + mt * 16 + (lane & 15);
                int s = kk * 2 + (lane >> 4);
                ldsm4(afr[mt][0], afr[mt][1], afr[mt][2], afr[mt][3],
                      aBase + r * 64 + ((s ^ (r & 3)) << 4));
            }
#pragma unroll
            for (int np = 0; np < 4; np++) {
                int r = wn * 64 + np * 16 + (lane & 7) + ((lane >> 4) << 3);
                int s = kk * 2 + ((lane >> 3) & 1);
                ldsm4(bfr[2 * np][0], bfr[2 * np][1], bfr[2 * np + 1][0], bfr[2 * np + 1][1],
                      bBase + r * 64 + ((s ^ (r & 3)) << 4));
            }
#pragma unroll
            for (int mt = 0; mt < 4; mt++)
#pragma unroll
                for (int nt = 0; nt < 8; nt++)
                    mma16816(c[mt][nt], afr[mt], bfr[nt]);
        }
    }
#undef LOAD_CHUNK

    // epilogue: BN + ReLU (+ re-split for layer 1)
#pragma unroll
    for (int mt = 0; mt < 4; mt++) {
#pragma unroll
        for (int nt = 0; nt < 8; nt++) {
            int cl = wn * 64 + nt * 8 + (lane & 3) * 2;   // global col (bn = 0)
            int rl = wm * 64 + mt * 16 + (lane >> 2);
#pragma unroll
            for (int hh = 0; hh < 2; hh++) {
                int grow = bm + rl + hh * 8;
                float v0 = fmaxf(fmaf(c[mt][nt][hh * 2 + 0], s_al[cl],     s_be[cl]),     0.f);
                float v1 = fmaxf(fmaf(c[mt][nt][hh * 2 + 1], s_al[cl + 1], s_be[cl + 1]), 0.f);
                if (L == 1) {
                    ushortT h0, l0, h1, l1;
                    split_bf(v0, h0, l0); split_bf(v1, h1, l1);
                    *(uintT*)&gA2[(size_t)grow * 512 + cl]       = (uintT)h0 | ((uintT)h1 << 16);
                    *(uintT*)&gA2[(size_t)grow * 512 + 256 + cl] = (uintT)l0 | ((uintT)l1 << 16);
                } else {
                    float2 o = make_float2(v0, v1);
                    *(float2*)&g_h[(size_t)grow * 256 + cl] = o;
                }
            }
        }
    }
}

// ---------------- encoding ----------------
__global__ __launch_bounds__(256) void encoding_kernel(const float* __restrict__ cw,
                                                       const float* __restrict__ scale)
{
    __shared__ float cwT[256][32];
    __shared__ float Ash[64][32];
    __shared__ float c2s[32], scs[32];
    int bz = blockIdx.y;
    int n0 = blockIdx.x * 64;
    int t = threadIdx.x, warp = t >> 5, lane = t & 31;
    for (int i = t; i < 32 * 256; i += 256) cwT[i & 255][i >> 8] = cw[i];
    if (t < 32) { c2s[t] = g_c2[t]; scs[t] = scale[t]; }
    __syncthreads();
    const float* Xb = g_h + ((size_t)bz * NQ + n0) * 256;
    for (int pi = 0; pi < 8; pi++) {
        int p = warp * 8 + pi;
        const float* xp = Xb + (size_t)p * 256;
        float xr[8];
#pragma unroll
        for (int j = 0; j < 8; j++) xr[j] = xp[j * 32 + lane];
        float xn2 = 0.f;
#pragma unroll
        for (int j = 0; j < 8; j++) xn2 = fmaf(xr[j], xr[j], xn2);
#pragma unroll
        for (int o = 16; o > 0; o >>= 1) xn2 += __shfl_xor_sync(0xffffffffu, xn2, o);
        float dotv = 0.f;
#pragma unroll
        for (int j = 0; j < 8; j++) {
            float xj = xr[j];
#pragma unroll
            for (int l2 = 0; l2 < 32; l2++) {
                float x = __shfl_sync(0xffffffffu, xj, l2);
                dotv = fmaf(x, cwT[j * 32 + l2][lane], dotv);
            }
        }
        float sl = scs[lane] * (xn2 - 2.f * dotv + c2s[lane]);
        float mx = sl;
#pragma unroll
        for (int o = 16; o > 0; o >>= 1) mx = fmaxf(mx, __shfl_xor_sync(0xffffffffu, mx, o));
        float e = __expf(sl - mx);
        float se = e;
#pragma unroll
        for (int o = 16; o > 0; o >>= 1) se += __shfl_xor_sync(0xffffffffu, se, o);
        Ash[p][lane] = e / se;
    }
    __syncthreads();
    if (t < 32) {
        float s = 0.f;
        for (int p = 0; p < 64; p++) s += Ash[p][t];
        atomicAdd(&g_sumA[bz * 32 + t], s);
    }
    float acc[32];
#pragma unroll
    for (int k = 0; k < 32; k++) acc[k] = 0.f;
    for (int p = 0; p < 64; p++) {
        float x = Xb[(size_t)p * 256 + t];
#pragma unroll
        for (int k = 0; k < 32; k++) acc[k] = fmaf(Ash[p][k], x, acc[k]);
    }
    float* Eb = g_E + (size_t)bz * 8192;
#pragma unroll
    for (int k = 0; k < 32; k++) atomicAdd(&Eb[k * 256 + t], acc[k]);
}

__global__ __launch_bounds__(256) void enc_fin_kernel(const float* __restrict__ cw)
{
    __shared__ float red[256];
    int bz = blockIdx.x, t = threadIdx.x;
    float ss = 0.f;
    for (int j = t; j < 8192; j += 256) {
        float v = g_E[bz * 8192 + j] - g_sumA[bz * 32 + (j >> 8)] * cw[j];
        v = fmaxf(v, 0.f);
        g_En[bz * 8192 + j] = v;
        ss += v * v;
    }
    red[t] = ss;
    __syncthreads();
    for (int s = 128; s > 0; s >>= 1) {
        if (t < s) red[t] += red[t + s];
        __syncthreads();
    }
    float rinv = 1.f / fmaxf(sqrtf(red[0]), 1e-12f);
    for (int j = t; j < 8192; j += 256) g_En[bz * 8192 + j] *= rinv;
}

__global__ __launch_bounds__(256) void ctx_gemv_kernel(const float* __restrict__ lin_w,
                                                       const float* __restrict__ lin_b)
{
    __shared__ float red[8][256];
    int o = blockIdx.x, t = threadIdx.x;
    float acc[8];
#pragma unroll
    for (int b = 0; b < 8; b++) acc[b] = 0.f;
    const float* wrow = lin_w + (size_t)o * 8192;
    for (int j = t; j < 8192; j += 256) {
        float w = wrow[j];
#pragma unroll
        for (int b = 0; b < 8; b++) acc[b] = fmaf(w, g_En[b * 8192 + j], acc[b]);
    }
#pragma unroll
    for (int b = 0; b < 8; b++) red[b][t] = acc[b];
    __syncthreads();
    for (int s = 128; s > 0; s >>= 1) {
        if (t < s) {
#pragma unroll
            for (int b = 0; b < 8; b++) red[b][t] += red[b][t + s];
        }
        __syncthreads();
    }
    if (t < 8) {
        float z = red[t][0] + lin_b[o];
        g_ctx[t * 256 + o] = 1.f / (1.f + expf(-z));
    }
}

__global__ void final_kernel(float* __restrict__ out)
{
    __shared__ float tile[32][33];
    int bz = blockIdx.z;
    int d0 = blockIdx.x * 32, n0 = blockIdx.y * 32;
    int tx = threadIdx.x, ty = threadIdx.y;
    const float* h = g_h + (size_t)bz * NQ * 256;
#pragma unroll
    for (int j = 0; j < 32; j += 8)
        tile[ty + j][tx] = h[(size_t)(n0 + ty + j) * 256 + d0 + tx];
    __syncthreads();
    float* ob = out + (size_t)bz * 256 * NQ;
#pragma unroll
    for (int j = 0; j < 32; j += 8)
        ob[(size_t)(d0 + ty + j) * NQ + n0 + tx] = tile[tx][ty + j] * g_ctx[bz * 256 + d0 + ty + j];
}

// ===================== launcher =====================
extern "C" void kernel_launch(void* const* d_in, const int* in_sizes, int n_in,
                              void* d_out, int out_size)
{
    (void)in_sizes; (void)n_in; (void)out_size;
    const float* unknown      = (const float*)d_in[0];
    const float* known        = (const float*)d_in[1];
    const float* unknow_feats = (const float*)d_in[2];
    const float* known_feats  = (const float*)d_in[3];
    const float* conv_w1 = (const float*)d_in[4];
    const float* conv_b1 = (const float*)d_in[5];
    const float* bn_g1 = (const float*)d_in[6];
    const float* bn_b1 = (const float*)d_in[7];
    const float* bn_m1 = (const float*)d_in[8];
    const float* bn_v1 = (const float*)d_in[9];
    const float* conv_w2 = (const float*)d_in[10];
    const float* conv_b2 = (const float*)d_in[11];
    const float* bn_g2 = (const float*)d_in[12];
    const float* bn_b2 = (const float*)d_in[13];
    const float* bn_m2 = (const float*)d_in[14];
    const float* bn_v2 = (const float*)d_in[15];
    const float* enc_cw    = (const float*)d_in[16];
    const float* enc_scale = (const float*)d_in[17];
    const float* lin_w     = (const float*)d_in[18];
    const float* lin_b     = (const float*)d_in[19];
    float* out = (float*)d_out;

    const int SMEMSZ = 4 * (8192 + 16384) + 2048;   // 4 stages (A 8KB + B 16KB) + alpha/beta
    static int attr_done = 0;
    if (!attr_done) {
        cudaFuncSetAttribute(gemm_mma<1>, cudaFuncAttributeMaxDynamicSharedMemorySize, SMEMSZ);
        cudaFuncSetAttribute(gemm_mma<2>, cudaFuncAttributeMaxDynamicSharedMemorySize, SMEMSZ);
        attr_done = 1;
    }

    prep_kernel<<<256, 256>>>(conv_b1, bn_g1, bn_b1, bn_m1, bn_v1,
                              conv_b2, bn_g2, bn_b2, bn_m2, bn_v2, enc_cw);
    expand_w_kernel<<<512, 256>>>(conv_w1, conv_w2);
    tr_kf_kernel<<<dim3(64, 8, 8), dim3(32, 8)>>>(known_feats);
    three_nn_kernel<<<dim3(NQ / 64, B_), 256>>>(unknown, known);
    interp_kernel<<<dim3(NQ / 4, B_), 256>>>();
    tr_unk_kernel<<<dim3(NQ / 32, 8, B_), dim3(32, 8)>>>(unknow_feats);
    gemm_mma<1><<<512, 256, SMEMSZ>>>();
    gemm_mma<2><<<512, 256, SMEMSZ>>>();
    encoding_kernel<<<dim3(NQ / 64, B_), 256>>>(enc_cw, enc_scale);
    enc_fin_kernel<<<B_, 256>>>(enc_cw);
    ctx_gemv_kernel<<<256, 256>>>(lin_w, lin_b);
    final_kernel<<<dim3(8, NQ / 32, B_), dim3(32, 8)>>>(out);
}

// round 9
// speedup vs baseline: 1.3130x; 1.3130x over previous
#include <cuda_runtime.h>
#include <cuda_fp16.h>
#include <math.h>
#include <stdint.h>

#define B_   8
#define NQ   8192
#define MK   2048
typedef unsigned short ushortT;
typedef unsigned int   uintT;

// ===================== helpers =====================
__device__ __forceinline__ uint32_t smem_to_u32(const void* p) {
    uint32_t a;
    asm("{ .reg .u64 t; cvta.to.shared.u64 t, %1; cvt.u32.u64 %0, t; }" : "=r"(a) : "l"(p));
    return a;
}
#define CP_ASYNC16(s, g) \
    asm volatile("cp.async.cg.shared.global [%0], [%1], 16;" :: "r"(s), "l"(g))
#define CP_COMMIT() asm volatile("cp.async.commit_group;")
#define CP_WAIT2()  asm volatile("cp.async.wait_group 2;")

__device__ __forceinline__ void ldsm4(uint32_t& r0, uint32_t& r1, uint32_t& r2, uint32_t& r3,
                                      uint32_t addr) {
    asm volatile("ldmatrix.sync.aligned.m8n8.x4.shared.b16 {%0,%1,%2,%3}, [%4];"
                 : "=r"(r0), "=r"(r1), "=r"(r2), "=r"(r3) : "r"(addr));
}
__device__ __forceinline__ void ldsm2(uint32_t& r0, uint32_t& r1, uint32_t addr) {
    asm volatile("ldmatrix.sync.aligned.m8n8.x2.shared.b16 {%0,%1}, [%2];"
                 : "=r"(r0), "=r"(r1) : "r"(addr));
}
__device__ __forceinline__ void mma16816(float* d, const uint32_t* a, const uint32_t* b) {
    asm volatile(
        "mma.sync.aligned.m16n8k16.row.col.f32.f16.f16.f32 "
        "{%0,%1,%2,%3}, {%4,%5,%6,%7}, {%8,%9}, {%0,%1,%2,%3};"
        : "+f"(d[0]), "+f"(d[1]), "+f"(d[2]), "+f"(d[3])
        : "r"(a[0]), "r"(a[1]), "r"(a[2]), "r"(a[3]), "r"(b[0]), "r"(b[1]));
}

// fp32 -> fp16 hi + fp16 lo (RNE); h+l carries ~22 mantissa bits
__device__ __forceinline__ void split_hf(float v, ushortT& h, ushortT& l) {
    __half hh = __float2half_rn(v);
    h = __half_as_ushort(hh);
    __half ll = __float2half_rn(v - __half2float(hh));
    l = __half_as_ushort(ll);
}

__device__ __forceinline__ void ins3(float& d0, int& i0, float& d1, int& i1,
                                     float& d2, int& i2, float dd, int m) {
    if (dd < d2) {
        if (dd < d1) {
            d2 = d1; i2 = i1;
            if (dd < d0) { d1 = d0; i1 = i0; d0 = dd; i0 = m; }
            else          { d1 = dd; i1 = m; }
        } else { d2 = dd; i2 = m; }
    }
}

// ===================== scratch =====================
__device__ ushortT gA1[(size_t)8 * 8192 * 1024];  // fp16 [H(512) | L(512)]
__device__ ushortT gA2[(size_t)8 * 8192 * 512];   // fp16 [H(256) | L(256)]
__device__ ushortT gW1[256 * 1024];               // fp16 [Wh | Wh]
__device__ ushortT gW2[256 * 512];
__device__ float g_h  [(size_t)8 * 8192 * 256];
__device__ float g_kfT[(size_t)8 * 2048 * 256];
__device__ int   g_idx[8 * 8192 * 3];
__device__ float g_wgt[8 * 8192 * 3];
__device__ float g_E  [8 * 8192];
__device__ float g_En [8 * 8192];
__device__ float g_sumA[8 * 32];
__device__ float g_ctx[8 * 256];
__device__ float g_al1[256], g_be1[256], g_al2[256], g_be2[256];
__device__ float g_c2[32];

// ===================== prep =====================
__global__ void prep_kernel(const float* __restrict__ cb1, const float* __restrict__ gg1,
                            const float* __restrict__ bb1, const float* __restrict__ mm1,
                            const float* __restrict__ vv1,
                            const float* __restrict__ cb2, const float* __restrict__ gg2,
                            const float* __restrict__ bb2, const float* __restrict__ mm2,
                            const float* __restrict__ vv2,
                            const float* __restrict__ cw)
{
    int i = blockIdx.x * blockDim.x + threadIdx.x;
    if (i < 256) {
        float s1 = gg1[i] * rsqrtf(vv1[i] + 1e-5f);
        g_al1[i] = s1;
        g_be1[i] = s1 * (cb1[i] - mm1[i]) + bb1[i];
        float s2 = gg2[i] * rsqrtf(vv2[i] + 1e-5f);
        g_al2[i] = s2;
        g_be2[i] = s2 * (cb2[i] - mm2[i]) + bb2[i];
    }
    if (i < 32) {
        float s = 0.f;
        const float* c = cw + i * 256;
        for (int d = 0; d < 256; d++) s += c[d] * c[d];
        g_c2[i] = s;
    }
    if (i < 8 * 32) g_sumA[i] = 0.f;
    if (i < 8 * 8192) g_E[i] = 0.f;
}

__global__ void expand_w_kernel(const float* __restrict__ w1, const float* __restrict__ w2)
{
    int i = blockIdx.x * 256 + threadIdx.x;
    if (i < 256 * 512) {
        int n = i >> 9, k = i & 511;
        ushortT h = __half_as_ushort(__float2half_rn(w1[i]));
        gW1[n * 1024 + k] = h; gW1[n * 1024 + 512 + k] = h;
    }
    if (i < 256 * 256) {
        int n = i >> 8, k = i & 255;
        ushortT h = __half_as_ushort(__float2half_rn(w2[i]));
        gW2[n * 512 + k] = h; gW2[n * 512 + 256 + k] = h;
    }
}

// ---------------- transpose known_feats (B,256,2048) -> (B,2048,256) ----------------
__global__ void tr_kf_kernel(const float* __restrict__ kf)
{
    __shared__ float tile[32][33];
    int b = blockIdx.z;
    int m0 = blockIdx.x * 32, c0 = blockIdx.y * 32;
    int tx = threadIdx.x, ty = threadIdx.y;
    const float* in = kf + (size_t)b * 256 * MK;
#pragma unroll
    for (int j = 0; j < 32; j += 8)
        tile[ty + j][tx] = in[(size_t)(c0 + ty + j) * MK + m0 + tx];
    __syncthreads();
    float* out = g_kfT + (size_t)b * MK * 256;
#pragma unroll
    for (int j = 0; j < 32; j += 8)
        out[(size_t)(m0 + ty + j) * 256 + c0 + tx] = tile[tx][ty + j];
}

// ---------------- transpose unknow_feats -> gA1 cols [256,512) H, [768,1024) L -------
__global__ void tr_unk_kernel(const float* __restrict__ uf)
{
    __shared__ float tile[32][33];
    int b = blockIdx.z;
    int n0 = blockIdx.x * 32, c0 = blockIdx.y * 32;
    int tx = threadIdx.x, ty = threadIdx.y;
    const float* in = uf + (size_t)b * 256 * NQ;
#pragma unroll
    for (int j = 0; j < 32; j += 8)
        tile[ty + j][tx] = in[(size_t)(c0 + ty + j) * NQ + n0 + tx];
    __syncthreads();
#pragma unroll
    for (int j = 0; j < 32; j += 8) {
        float v = tile[tx][ty + j];
        ushortT h, l; split_hf(v, h, l);
        size_t row = ((size_t)b * NQ + n0 + ty + j) * 1024;
        gA1[row + 256 + c0 + tx] = h;
        gA1[row + 768 + c0 + tx] = l;
    }
}

// ---------------- three_nn: 4 threads/query, padded chunks, 3-FMA inner loop --------
#define CHPAD 513
__global__ __launch_bounds__(256) void three_nn_kernel(const float* __restrict__ unknown,
                                                       const float* __restrict__ known)
{
    __shared__ float4 kp[4 * CHPAD];
    int bz = blockIdx.y;
    int t  = threadIdx.x;
    int q  = blockIdx.x * 64 + (t >> 2);
    int ck = t & 3;

    const float* kb = known + (size_t)bz * MK * 3;
    for (int i = t; i < MK; i += 256) {
        float kx = kb[i * 3 + 0];
        float ky = kb[i * 3 + 1];
        float kz = kb[i * 3 + 2];
        kp[(i >> 9) * CHPAD + (i & 511)] = make_float4(kx, ky, kz, kx * kx + ky * ky + kz * kz);
    }
    __syncthreads();

    const float* u = unknown + ((size_t)bz * NQ + q) * 3;
    float ux = u[0], uy = u[1], uz = u[2];
    float x2 = ux * ux + uy * uy + uz * uz;
    float mux = -2.f * ux, muy = -2.f * uy, muz = -2.f * uz;

    float d0 = 1e30f, d1 = 1e30f, d2 = 1e30f;
    int   i0 = 0, i1 = 0, i2 = 0;
    const float4* base = kp + ck * CHPAD;
    int m0 = ck * 512;
#pragma unroll 4
    for (int j = 0; j < 512; j++) {
        float4 p = base[j];
        float dd = fmaf(mux, p.x, p.w);
        dd = fmaf(muy, p.y, dd);
        dd = fmaf(muz, p.z, dd);
        ins3(d0, i0, d1, i1, d2, i2, dd, m0 + j);
    }

#pragma unroll
    for (int off = 1; off <= 2; off <<= 1) {
        float e0 = __shfl_xor_sync(0xffffffffu, d0, off);
        float e1 = __shfl_xor_sync(0xffffffffu, d1, off);
        float e2 = __shfl_xor_sync(0xffffffffu, d2, off);
        int   j0 = __shfl_xor_sync(0xffffffffu, i0, off);
        int   j1 = __shfl_xor_sync(0xffffffffu, i1, off);
        int   j2 = __shfl_xor_sync(0xffffffffu, i2, off);
        ins3(d0, i0, d1, i1, d2, i2, e0, j0);
        ins3(d0, i0, d1, i1, d2, i2, e1, j1);
        ins3(d0, i0, d1, i1, d2, i2, e2, j2);
    }

    if (ck == 0) {
        float r0 = 1.f / (sqrtf(fmaxf(d0 + x2, 1e-12f)) + 1e-8f);
        float r1 = 1.f / (sqrtf(fmaxf(d1 + x2, 1e-12f)) + 1e-8f);
        float r2 = 1.f / (sqrtf(fmaxf(d2 + x2, 1e-12f)) + 1e-8f);
        float rs = 1.f / (r0 + r1 + r2);
        size_t base2 = ((size_t)bz * NQ + q) * 3;
        g_idx[base2 + 0] = i0; g_idx[base2 + 1] = i1; g_idx[base2 + 2] = i2;
        g_wgt[base2 + 0] = r0 * rs; g_wgt[base2 + 1] = r1 * rs; g_wgt[base2 + 2] = r2 * rs;
    }
}

// ---------------- interpolate -> gA1 cols [0,256) H, [512,768) L (4-wide) -----------
__global__ __launch_bounds__(256) void interp_kernel()
{
    int bz = blockIdx.y, t = threadIdx.x;
    int n = blockIdx.x * 4 + (t >> 6);
    int d = (t & 63) * 4;
    size_t base = ((size_t)bz * NQ + n) * 3;
    int i0 = g_idx[base], i1 = g_idx[base + 1], i2 = g_idx[base + 2];
    float w0 = g_wgt[base], w1 = g_wgt[base + 1], w2 = g_wgt[base + 2];
    const float* kf = g_kfT + (size_t)bz * MK * 256;
    float4 a = *(const float4*)&kf[(size_t)i0 * 256 + d];
    float4 b = *(const float4*)&kf[(size_t)i1 * 256 + d];
    float4 c = *(const float4*)&kf[(size_t)i2 * 256 + d];
    float v0 = w0 * a.x + w1 * b.x + w2 * c.x;
    float v1 = w0 * a.y + w1 * b.y + w2 * c.y;
    float v2 = w0 * a.z + w1 * b.z + w2 * c.z;
    float v3 = w0 * a.w + w1 * b.w + w2 * c.w;
    ushortT h0, l0, h1, l1, h2, l2, h3, l3;
    split_hf(v0, h0, l0); split_hf(v1, h1, l1);
    split_hf(v2, h2, l2); split_hf(v3, h3, l3);
    size_t row = ((size_t)bz * NQ + n) * 1024;
    uint2 hp = make_uint2((uintT)h0 | ((uintT)h1 << 16), (uintT)h2 | ((uintT)h3 << 16));
    uint2 lp = make_uint2((uintT)l0 | ((uintT)l1 << 16), (uintT)l2 | ((uintT)l3 << 16));
    *(uint2*)&gA1[row + d]       = hp;
    *(uint2*)&gA1[row + 512 + d] = lp;
}

// ===================== HMMA GEMM (fp16 2-term split, 4-stage cp.async) =====================
// C(65536,256) = relu(alpha .* ([H|L] @ [Wh|Wh]^T) + beta), K' = 2K, linear columns.
template <int L>
__global__ __launch_bounds__(256) void gemm_mma()
{
    constexpr int K   = (L == 1) ? 512 : 256;
    constexpr int KX  = 2 * K;           // expanded K (physical == logical)
    constexpr int NCH = KX / 32;         // 32 / 16
    const ushortT* Ag = (L == 1) ? gA1 : gA2;
    const ushortT* Wg = (L == 1) ? gW1 : gW2;
    const float* alpha = (L == 1) ? g_al1 : g_al2;
    const float* beta  = (L == 1) ? g_be1 : g_be2;

    extern __shared__ __align__(16) ushortT dyn[];
    ushortT* sA = dyn;                 // 4 stages x 4096 ushort = 8KB each
    ushortT* sB = dyn + 4 * 4096;
    float* s_al = (float*)(dyn + 8 * 4096);
    float* s_be = s_al + 128;

    int tid = threadIdx.x, wid = tid >> 5, lane = tid & 31;
    int bm = blockIdx.x * 128, bn = blockIdx.y * 128;
    if (tid < 128) { s_al[tid] = alpha[bn + tid]; s_be[tid] = beta[bn + tid]; }

    uint32_t sAb = smem_to_u32(sA);
    uint32_t sBb = smem_to_u32(sB);

    int lr = tid >> 1;
    int ls = (tid & 1) * 2;
    uint32_t off0 = lr * 64 + (((ls)     ^ (lr & 3)) << 4);
    uint32_t off1 = lr * 64 + (((ls + 1) ^ (lr & 3)) << 4);

    const ushortT* Arow = Ag + (size_t)(bm + lr) * KX;
    const ushortT* Wrow = Wg + (size_t)(bn + lr) * KX;

#define LOAD_CHUNK(p) do { \
    int _col = (p) * 32; \
    uint32_t _as = sAb + ((p) & 3) * 8192; \
    uint32_t _ws = sBb + ((p) & 3) * 8192; \
    CP_ASYNC16(_as + off0, Arow + _col + ls * 8); \
    CP_ASYNC16(_as + off1, Arow + _col + ls * 8 + 8); \
    CP_ASYNC16(_ws + off0, Wrow + _col + ls * 8); \
    CP_ASYNC16(_ws + off1, Wrow + _col + ls * 8 + 8); \
    CP_COMMIT(); } while (0)

    LOAD_CHUNK(0);
    LOAD_CHUNK(1);
    LOAD_CHUNK(2);

    float c[4][4][4];
#pragma unroll
    for (int i = 0; i < 4; i++)
#pragma unroll
        for (int j = 0; j < 4; j++)
#pragma unroll
            for (int q = 0; q < 4; q++) c[i][j][q] = 0.f;

    int wm = wid >> 2, wn = wid & 3;

    for (int kc = 0; kc < NCH; kc++) {
        CP_WAIT2();
        __syncthreads();
        int kn = kc + 3;
        if (kn < NCH) LOAD_CHUNK(kn);
        uint32_t aBase = sAb + (kc & 3) * 8192;
        uint32_t bBase = sBb + (kc & 3) * 8192;
#pragma unroll
        for (int kk = 0; kk < 2; kk++) {
            uint32_t afr[4][4], bfr[4][2];
#pragma unroll
            for (int mt = 0; mt < 4; mt++) {
                int r = wm * 64 + mt * 16 + (lane & 15);
                int s = kk * 2 + (lane >> 4);
                ldsm4(afr[mt][0], afr[mt][1], afr[mt][2], afr[mt][3],
                      aBase + r * 64 + ((s ^ (r & 3)) << 4));
            }
#pragma unroll
            for (int nt = 0; nt < 4; nt++) {
                int r = wn * 32 + nt * 8 + (lane & 7);
                int s = kk * 2 + ((lane >> 3) & 1);
                ldsm2(bfr[nt][0], bfr[nt][1],
                      bBase + r * 64 + ((s ^ (r & 3)) << 4));
            }
#pragma unroll
            for (int mt = 0; mt < 4; mt++)
#pragma unroll
                for (int nt = 0; nt < 4; nt++)
                    mma16816(c[mt][nt], afr[mt], bfr[nt]);
        }
    }
#undef LOAD_CHUNK

    // epilogue: BN + ReLU (+ re-split for layer 1)
#pragma unroll
    for (int mt = 0; mt < 4; mt++) {
#pragma unroll
        for (int nt = 0; nt < 4; nt++) {
            int cl = wn * 32 + nt * 8 + (lane & 3) * 2;
            int gcol = bn + cl;
            int rl = wm * 64 + mt * 16 + (lane >> 2);
#pragma unroll
            for (int hh = 0; hh < 2; hh++) {
                int grow = bm + rl + hh * 8;
                float v0 = fmaxf(fmaf(c[mt][nt][hh * 2 + 0], s_al[cl],     s_be[cl]),     0.f);
                float v1 = fmaxf(fmaf(c[mt][nt][hh * 2 + 1], s_al[cl + 1], s_be[cl + 1]), 0.f);
                if (L == 1) {
                    ushortT h0, l0, h1, l1;
                    split_hf(v0, h0, l0); split_hf(v1, h1, l1);
                    *(uintT*)&gA2[(size_t)grow * 512 + gcol]       = (uintT)h0 | ((uintT)h1 << 16);
                    *(uintT*)&gA2[(size_t)grow * 512 + 256 + gcol] = (uintT)l0 | ((uintT)l1 << 16);
                } else {
                    float2 o = make_float2(v0, v1);
                    *(float2*)&g_h[(size_t)grow * 256 + gcol] = o;
                }
            }
        }
    }
}

// ---------------- encoding ----------------
__global__ __launch_bounds__(256) void encoding_kernel(const float* __restrict__ cw,
                                                       const float* __restrict__ scale)
{
    __shared__ float cwT[256][32];
    __shared__ float Ash[64][32];
    __shared__ float c2s[32], scs[32];
    int bz = blockIdx.y;
    int n0 = blockIdx.x * 64;
    int t = threadIdx.x, warp = t >> 5, lane = t & 31;
    for (int i = t; i < 32 * 256; i += 256) cwT[i & 255][i >> 8] = cw[i];
    if (t < 32) { c2s[t] = g_c2[t]; scs[t] = scale[t]; }
    __syncthreads();
    const float* Xb = g_h + ((size_t)bz * NQ + n0) * 256;
    for (int pi = 0; pi < 8; pi++) {
        int p = warp * 8 + pi;
        const float* xp = Xb + (size_t)p * 256;
        float xr[8];
#pragma unroll
        for (int j = 0; j < 8; j++) xr[j] = xp[j * 32 + lane];
        float xn2 = 0.f;
#pragma unroll
        for (int j = 0; j < 8; j++) xn2 = fmaf(xr[j], xr[j], xn2);
#pragma unroll
        for (int o = 16; o > 0; o >>= 1) xn2 += __shfl_xor_sync(0xffffffffu, xn2, o);
        float dotv = 0.f;
#pragma unroll
        for (int j = 0; j < 8; j++) {
            float xj = xr[j];
#pragma unroll
            for (int l2 = 0; l2 < 32; l2++) {
                float x = __shfl_sync(0xffffffffu, xj, l2);
                dotv = fmaf(x, cwT[j * 32 + l2][lane], dotv);
            }
        }
        float sl = scs[lane] * (xn2 - 2.f * dotv + c2s[lane]);
        float mx = sl;
#pragma unroll
        for (int o = 16; o > 0; o >>= 1) mx = fmaxf(mx, __shfl_xor_sync(0xffffffffu, mx, o));
        float e = __expf(sl - mx);
        float se = e;
#pragma unroll
        for (int o = 16; o > 0; o >>= 1) se += __shfl_xor_sync(0xffffffffu, se, o);
        Ash[p][lane] = e / se;
    }
    __syncthreads();
    if (t < 32) {
        float s = 0.f;
        for (int p = 0; p < 64; p++) s += Ash[p][t];
        atomicAdd(&g_sumA[bz * 32 + t], s);
    }
    float acc[32];
#pragma unroll
    for (int k = 0; k < 32; k++) acc[k] = 0.f;
    for (int p = 0; p < 64; p++) {
        float x = Xb[(size_t)p * 256 + t];
#pragma unroll
        for (int k = 0; k < 32; k++) acc[k] = fmaf(Ash[p][k], x, acc[k]);
    }
    float* Eb = g_E + (size_t)bz * 8192;
#pragma unroll
    for (int k = 0; k < 32; k++) atomicAdd(&Eb[k * 256 + t], acc[k]);
}

__global__ __launch_bounds__(256) void enc_fin_kernel(const float* __restrict__ cw)
{
    __shared__ float red[256];
    int bz = blockIdx.x, t = threadIdx.x;
    float ss = 0.f;
    for (int j = t; j < 8192; j += 256) {
        float v = g_E[bz * 8192 + j] - g_sumA[bz * 32 + (j >> 8)] * cw[j];
        v = fmaxf(v, 0.f);
        g_En[bz * 8192 + j] = v;
        ss += v * v;
    }
    red[t] = ss;
    __syncthreads();
    for (int s = 128; s > 0; s >>= 1) {
        if (t < s) red[t] += red[t + s];
        __syncthreads();
    }
    float rinv = 1.f / fmaxf(sqrtf(red[0]), 1e-12f);
    for (int j = t; j < 8192; j += 256) g_En[bz * 8192 + j] *= rinv;
}

__global__ __launch_bounds__(256) void ctx_gemv_kernel(const float* __restrict__ lin_w,
                                                       const float* __restrict__ lin_b)
{
    __shared__ float red[8][256];
    int o = blockIdx.x, t = threadIdx.x;
    float acc[8];
#pragma unroll
    for (int b = 0; b < 8; b++) acc[b] = 0.f;
    const float* wrow = lin_w + (size_t)o * 8192;
    for (int j = t; j < 8192; j += 256) {
        float w = wrow[j];
#pragma unroll
        for (int b = 0; b < 8; b++) acc[b] = fmaf(w, g_En[b * 8192 + j], acc[b]);
    }
#pragma unroll
    for (int b = 0; b < 8; b++) red[b][t] = acc[b];
    __syncthreads();
    for (int s = 128; s > 0; s >>= 1) {
        if (t < s) {
#pragma unroll
            for (int b = 0; b < 8; b++) red[b][t] += red[b][t + s];
        }
        __syncthreads();
    }
    if (t < 8) {
        float z = red[t][0] + lin_b[o];
        g_ctx[t * 256 + o] = 1.f / (1.f + expf(-z));
    }
}

__global__ void final_kernel(float* __restrict__ out)
{
    __shared__ float tile[32][33];
    int bz = blockIdx.z;
    int d0 = blockIdx.x * 32, n0 = blockIdx.y * 32;
    int tx = threadIdx.x, ty = threadIdx.y;
    const float* h = g_h + (size_t)bz * NQ * 256;
#pragma unroll
    for (int j = 0; j < 32; j += 8)
        tile[ty + j][tx] = h[(size_t)(n0 + ty + j) * 256 + d0 + tx];
    __syncthreads();
    float* ob = out + (size_t)bz * 256 * NQ;
#pragma unroll
    for (int j = 0; j < 32; j += 8)
        ob[(size_t)(d0 + ty + j) * NQ + n0 + tx] = tile[tx][ty + j] * g_ctx[bz * 256 + d0 + ty + j];
}

// ===================== launcher =====================
extern "C" void kernel_launch(void* const* d_in, const int* in_sizes, int n_in,
                              void* d_out, int out_size)
{
    (void)in_sizes; (void)n_in; (void)out_size;
    const float* unknown      = (const float*)d_in[0];
    const float* known        = (const float*)d_in[1];
    const float* unknow_feats = (const float*)d_in[2];
    const float* known_feats  = (const float*)d_in[3];
    const float* conv_w1 = (const float*)d_in[4];
    const float* conv_b1 = (const float*)d_in[5];
    const float* bn_g1 = (const float*)d_in[6];
    const float* bn_b1 = (const float*)d_in[7];
    const float* bn_m1 = (const float*)d_in[8];
    const float* bn_v1 = (const float*)d_in[9];
    const float* conv_w2 = (const float*)d_in[10];
    const float* conv_b2 = (const float*)d_in[11];
    const float* bn_g2 = (const float*)d_in[12];
    const float* bn_b2 = (const float*)d_in[13];
    const float* bn_m2 = (const float*)d_in[14];
    const float* bn_v2 = (const float*)d_in[15];
    const float* enc_cw    = (const float*)d_in[16];
    const float* enc_scale = (const float*)d_in[17];
    const float* lin_w     = (const float*)d_in[18];
    const float* lin_b     = (const float*)d_in[19];
    float* out = (float*)d_out;

    const int SMEMSZ = 4 * 16384 + 1024;   // 4 stages (A+B) + alpha/beta
    static int attr_done = 0;
    if (!attr_done) {
        cudaFuncSetAttribute(gemm_mma<1>, cudaFuncAttributeMaxDynamicSharedMemorySize, SMEMSZ);
        cudaFuncSetAttribute(gemm_mma<2>, cudaFuncAttributeMaxDynamicSharedMemorySize, SMEMSZ);
        attr_done = 1;
    }

    prep_kernel<<<256, 256>>>(conv_b1, bn_g1, bn_b1, bn_m1, bn_v1,
                              conv_b2, bn_g2, bn_b2, bn_m2, bn_v2, enc_cw);
    expand_w_kernel<<<512, 256>>>(conv_w1, conv_w2);
    tr_kf_kernel<<<dim3(64, 8, 8), dim3(32, 8)>>>(known_feats);
    three_nn_kernel<<<dim3(NQ / 64, B_), 256>>>(unknown, known);
    interp_kernel<<<dim3(NQ / 4, B_), 256>>>();
    tr_unk_kernel<<<dim3(NQ / 32, 8, B_), dim3(32, 8)>>>(unknow_feats);
    gemm_mma<1><<<dim3(512, 2), 256, SMEMSZ>>>();
    gemm_mma<2><<<dim3(512, 2), 256, SMEMSZ>>>();
    encoding_kernel<<<dim3(NQ / 64, B_), 256>>>(enc_cw, enc_scale);
    enc_fin_kernel<<<B_, 256>>>(enc_cw);
    ctx_gemv_kernel<<<256, 256>>>(lin_w, lin_b);
    final_kernel<<<dim3(8, NQ / 32, B_), dim3(32, 8)>>>(out);
}

// round 10
// speedup vs baseline: 1.3201x; 1.0054x over previous
#include <cuda_runtime.h>
#include <cuda_fp16.h>
#include <math.h>
#include <stdint.h>

#define B_   8
#define NQ   8192
#define MK   2048
typedef unsigned short ushortT;
typedef unsigned int   uintT;

// ===================== helpers =====================
__device__ __forceinline__ uint32_t smem_to_u32(const void* p) {
    uint32_t a;
    asm("{ .reg .u64 t; cvta.to.shared.u64 t, %1; cvt.u32.u64 %0, t; }" : "=r"(a) : "l"(p));
    return a;
}
#define CP_ASYNC16(s, g) \
    asm volatile("cp.async.cg.shared.global [%0], [%1], 16;" :: "r"(s), "l"(g))
#define CP_COMMIT() asm volatile("cp.async.commit_group;")
#define CP_WAIT2()  asm volatile("cp.async.wait_group 2;")

__device__ __forceinline__ void ldsm4(uint32_t& r0, uint32_t& r1, uint32_t& r2, uint32_t& r3,
                                      uint32_t addr) {
    asm volatile("ldmatrix.sync.aligned.m8n8.x4.shared.b16 {%0,%1,%2,%3}, [%4];"
                 : "=r"(r0), "=r"(r1), "=r"(r2), "=r"(r3) : "r"(addr));
}
__device__ __forceinline__ void mma16816(float* d, const uint32_t* a, const uint32_t* b) {
    asm volatile(
        "mma.sync.aligned.m16n8k16.row.col.f32.f16.f16.f32 "
        "{%0,%1,%2,%3}, {%4,%5,%6,%7}, {%8,%9}, {%0,%1,%2,%3};"
        : "+f"(d[0]), "+f"(d[1]), "+f"(d[2]), "+f"(d[3])
        : "r"(a[0]), "r"(a[1]), "r"(a[2]), "r"(a[3]), "r"(b[0]), "r"(b[1]));
}

// fp32 -> fp16 hi + fp16 lo (RNE); h+l carries ~22 mantissa bits
__device__ __forceinline__ void split_hf(float v, ushortT& h, ushortT& l) {
    __half hh = __float2half_rn(v);
    h = __half_as_ushort(hh);
    __half ll = __float2half_rn(v - __half2float(hh));
    l = __half_as_ushort(ll);
}

__device__ __forceinline__ void ins3(float& d0, int& i0, float& d1, int& i1,
                                     float& d2, int& i2, float dd, int m) {
    if (dd < d2) {
        if (dd < d1) {
            d2 = d1; i2 = i1;
            if (dd < d0) { d1 = d0; i1 = i0; d0 = dd; i0 = m; }
            else          { d1 = dd; i1 = m; }
        } else { d2 = dd; i2 = m; }
    }
}

// ===================== scratch =====================
__device__ ushortT gA1[(size_t)8 * 8192 * 1024];  // fp16 [H(512) | L(512)]
__device__ ushortT gA2[(size_t)8 * 8192 * 512];   // fp16 [H(256) | L(256)]
__device__ ushortT gW1[256 * 1024];               // fp16 [Wh | Wh]
__device__ ushortT gW2[256 * 512];
__device__ float g_h  [(size_t)8 * 8192 * 256];
__device__ float g_kfT[(size_t)8 * 2048 * 256];
__device__ int   g_idx[8 * 8192 * 3];
__device__ float g_wgt[8 * 8192 * 3];
__device__ float g_E  [8 * 8192];
__device__ float g_En [8 * 8192];
__device__ float g_sumA[8 * 32];
__device__ float g_ctx[8 * 256];
__device__ float g_al1[256], g_be1[256], g_al2[256], g_be2[256];
__device__ float g_c2[32];

// ===================== prep =====================
__global__ void prep_kernel(const float* __restrict__ cb1, const float* __restrict__ gg1,
                            const float* __restrict__ bb1, const float* __restrict__ mm1,
                            const float* __restrict__ vv1,
                            const float* __restrict__ cb2, const float* __restrict__ gg2,
                            const float* __restrict__ bb2, const float* __restrict__ mm2,
                            const float* __restrict__ vv2,
                            const float* __restrict__ cw)
{
    int i = blockIdx.x * blockDim.x + threadIdx.x;
    if (i < 256) {
        float s1 = gg1[i] * rsqrtf(vv1[i] + 1e-5f);
        g_al1[i] = s1;
        g_be1[i] = s1 * (cb1[i] - mm1[i]) + bb1[i];
        float s2 = gg2[i] * rsqrtf(vv2[i] + 1e-5f);
        g_al2[i] = s2;
        g_be2[i] = s2 * (cb2[i] - mm2[i]) + bb2[i];
    }
    if (i < 32) {
        float s = 0.f;
        const float* c = cw + i * 256;
        for (int d = 0; d < 256; d++) s += c[d] * c[d];
        g_c2[i] = s;
    }
    if (i < 8 * 32) g_sumA[i] = 0.f;
    if (i < 8 * 8192) g_E[i] = 0.f;
}

__global__ void expand_w_kernel(const float* __restrict__ w1, const float* __restrict__ w2)
{
    int i = blockIdx.x * 256 + threadIdx.x;
    if (i < 256 * 512) {
        int n = i >> 9, k = i & 511;
        ushortT h = __half_as_ushort(__float2half_rn(w1[i]));
        gW1[n * 1024 + k] = h; gW1[n * 1024 + 512 + k] = h;
    }
    if (i < 256 * 256) {
        int n = i >> 8, k = i & 255;
        ushortT h = __half_as_ushort(__float2half_rn(w2[i]));
        gW2[n * 512 + k] = h; gW2[n * 512 + 256 + k] = h;
    }
}

// ---------------- transpose known_feats (B,256,2048) -> (B,2048,256) ----------------
__global__ void tr_kf_kernel(const float* __restrict__ kf)
{
    __shared__ float tile[32][33];
    int b = blockIdx.z;
    int m0 = blockIdx.x * 32, c0 = blockIdx.y * 32;
    int tx = threadIdx.x, ty = threadIdx.y;
    const float* in = kf + (size_t)b * 256 * MK;
#pragma unroll
    for (int j = 0; j < 32; j += 8)
        tile[ty + j][tx] = in[(size_t)(c0 + ty + j) * MK + m0 + tx];
    __syncthreads();
    float* out = g_kfT + (size_t)b * MK * 256;
#pragma unroll
    for (int j = 0; j < 32; j += 8)
        out[(size_t)(m0 + ty + j) * 256 + c0 + tx] = tile[tx][ty + j];
}

// ---------------- transpose unknow_feats -> gA1 cols [256,512) H, [768,1024) L -------
__global__ void tr_unk_kernel(const float* __restrict__ uf)
{
    __shared__ float tile[32][33];
    int b = blockIdx.z;
    int n0 = blockIdx.x * 32, c0 = blockIdx.y * 32;
    int tx = threadIdx.x, ty = threadIdx.y;
    const float* in = uf + (size_t)b * 256 * NQ;
#pragma unroll
    for (int j = 0; j < 32; j += 8)
        tile[ty + j][tx] = in[(size_t)(c0 + ty + j) * NQ + n0 + tx];
    __syncthreads();
#pragma unroll
    for (int j = 0; j < 32; j += 8) {
        float v = tile[tx][ty + j];
        ushortT h, l; split_hf(v, h, l);
        size_t row = ((size_t)b * NQ + n0 + ty + j) * 1024;
        gA1[row + 256 + c0 + tx] = h;
        gA1[row + 768 + c0 + tx] = l;
    }
}

// ---------------- three_nn: 4 threads/query, padded chunks, 3-FMA inner loop --------
#define CHPAD 513
__global__ __launch_bounds__(256) void three_nn_kernel(const float* __restrict__ unknown,
                                                       const float* __restrict__ known)
{
    __shared__ float4 kp[4 * CHPAD];
    int bz = blockIdx.y;
    int t  = threadIdx.x;
    int q  = blockIdx.x * 64 + (t >> 2);
    int ck = t & 3;

    const float* kb = known + (size_t)bz * MK * 3;
    for (int i = t; i < MK; i += 256) {
        float kx = kb[i * 3 + 0];
        float ky = kb[i * 3 + 1];
        float kz = kb[i * 3 + 2];
        kp[(i >> 9) * CHPAD + (i & 511)] = make_float4(kx, ky, kz, kx * kx + ky * ky + kz * kz);
    }
    __syncthreads();

    const float* u = unknown + ((size_t)bz * NQ + q) * 3;
    float ux = u[0], uy = u[1], uz = u[2];
    float x2 = ux * ux + uy * uy + uz * uz;
    float mux = -2.f * ux, muy = -2.f * uy, muz = -2.f * uz;

    float d0 = 1e30f, d1 = 1e30f, d2 = 1e30f;
    int   i0 = 0, i1 = 0, i2 = 0;
    const float4* base = kp + ck * CHPAD;
    int m0 = ck * 512;
#pragma unroll 4
    for (int j = 0; j < 512; j++) {
        float4 p = base[j];
        float dd = fmaf(mux, p.x, p.w);
        dd = fmaf(muy, p.y, dd);
        dd = fmaf(muz, p.z, dd);
        ins3(d0, i0, d1, i1, d2, i2, dd, m0 + j);
    }

#pragma unroll
    for (int off = 1; off <= 2; off <<= 1) {
        float e0 = __shfl_xor_sync(0xffffffffu, d0, off);
        float e1 = __shfl_xor_sync(0xffffffffu, d1, off);
        float e2 = __shfl_xor_sync(0xffffffffu, d2, off);
        int   j0 = __shfl_xor_sync(0xffffffffu, i0, off);
        int   j1 = __shfl_xor_sync(0xffffffffu, i1, off);
        int   j2 = __shfl_xor_sync(0xffffffffu, i2, off);
        ins3(d0, i0, d1, i1, d2, i2, e0, j0);
        ins3(d0, i0, d1, i1, d2, i2, e1, j1);
        ins3(d0, i0, d1, i1, d2, i2, e2, j2);
    }

    if (ck == 0) {
        float r0 = 1.f / (sqrtf(fmaxf(d0 + x2, 1e-12f)) + 1e-8f);
        float r1 = 1.f / (sqrtf(fmaxf(d1 + x2, 1e-12f)) + 1e-8f);
        float r2 = 1.f / (sqrtf(fmaxf(d2 + x2, 1e-12f)) + 1e-8f);
        float rs = 1.f / (r0 + r1 + r2);
        size_t base2 = ((size_t)bz * NQ + q) * 3;
        g_idx[base2 + 0] = i0; g_idx[base2 + 1] = i1; g_idx[base2 + 2] = i2;
        g_wgt[base2 + 0] = r0 * rs; g_wgt[base2 + 1] = r1 * rs; g_wgt[base2 + 2] = r2 * rs;
    }
}

// ---------------- interpolate -> gA1 cols [0,256) H, [512,768) L (4-wide) -----------
__global__ __launch_bounds__(256) void interp_kernel()
{
    int bz = blockIdx.y, t = threadIdx.x;
    int n = blockIdx.x * 4 + (t >> 6);
    int d = (t & 63) * 4;
    size_t base = ((size_t)bz * NQ + n) * 3;
    int i0 = g_idx[base], i1 = g_idx[base + 1], i2 = g_idx[base + 2];
    float w0 = g_wgt[base], w1 = g_wgt[base + 1], w2 = g_wgt[base + 2];
    const float* kf = g_kfT + (size_t)bz * MK * 256;
    float4 a = *(const float4*)&kf[(size_t)i0 * 256 + d];
    float4 b = *(const float4*)&kf[(size_t)i1 * 256 + d];
    float4 c = *(const float4*)&kf[(size_t)i2 * 256 + d];
    float v0 = w0 * a.x + w1 * b.x + w2 * c.x;
    float v1 = w0 * a.y + w1 * b.y + w2 * c.y;
    float v2 = w0 * a.z + w1 * b.z + w2 * c.z;
    float v3 = w0 * a.w + w1 * b.w + w2 * c.w;
    ushortT h0, l0, h1, l1, h2, l2, h3, l3;
    split_hf(v0, h0, l0); split_hf(v1, h1, l1);
    split_hf(v2, h2, l2); split_hf(v3, h3, l3);
    size_t row = ((size_t)bz * NQ + n) * 1024;
    uint2 hp = make_uint2((uintT)h0 | ((uintT)h1 << 16), (uintT)h2 | ((uintT)h3 << 16));
    uint2 lp = make_uint2((uintT)l0 | ((uintT)l1 << 16), (uintT)l2 | ((uintT)l3 << 16));
    *(uint2*)&gA1[row + d]       = hp;
    *(uint2*)&gA1[row + 512 + d] = lp;
}

// ===================== HMMA GEMM (fp16 2-term split, 32x64 warp tiles) =====================
// CTA 128x128x32, 8 warps as 4m x 2n, warp tile 32x64.
// Per k16: 2 ldsm4 (A) + 4 ldsm4 (B pairs) = 6 LDSM for 16 HMMA.
template <int L>
__global__ __launch_bounds__(256) void gemm_mma()
{
    constexpr int K   = (L == 1) ? 512 : 256;
    constexpr int KX  = 2 * K;
    constexpr int NCH = KX / 32;         // 32 / 16
    const ushortT* Ag = (L == 1) ? gA1 : gA2;
    const ushortT* Wg = (L == 1) ? gW1 : gW2;
    const float* alpha = (L == 1) ? g_al1 : g_al2;
    const float* beta  = (L == 1) ? g_be1 : g_be2;

    extern __shared__ __align__(16) ushortT dyn[];
    ushortT* sA = dyn;                 // 4 stages x 4096 ushort = 8KB each
    ushortT* sB = dyn + 4 * 4096;
    float* s_al = (float*)(dyn + 8 * 4096);
    float* s_be = s_al + 128;

    int tid = threadIdx.x, wid = tid >> 5, lane = tid & 31;
    int bm = blockIdx.x * 128, bn = blockIdx.y * 128;
    if (tid < 128) { s_al[tid] = alpha[bn + tid]; s_be[tid] = beta[bn + tid]; }

    uint32_t sAb = smem_to_u32(sA);
    uint32_t sBb = smem_to_u32(sB);

    int lr = tid >> 1;
    int ls = (tid & 1) * 2;
    uint32_t off0 = lr * 64 + (((ls)     ^ (lr & 3)) << 4);
    uint32_t off1 = lr * 64 + (((ls + 1) ^ (lr & 3)) << 4);

    const ushortT* Arow = Ag + (size_t)(bm + lr) * KX;
    const ushortT* Wrow = Wg + (size_t)(bn + lr) * KX;

#define LOAD_CHUNK(p) do { \
    int _col = (p) * 32; \
    uint32_t _as = sAb + ((p) & 3) * 8192; \
    uint32_t _ws = sBb + ((p) & 3) * 8192; \
    CP_ASYNC16(_as + off0, Arow + _col + ls * 8); \
    CP_ASYNC16(_as + off1, Arow + _col + ls * 8 + 8); \
    CP_ASYNC16(_ws + off0, Wrow + _col + ls * 8); \
    CP_ASYNC16(_ws + off1, Wrow + _col + ls * 8 + 8); \
    CP_COMMIT(); } while (0)

    LOAD_CHUNK(0);
    LOAD_CHUNK(1);
    LOAD_CHUNK(2);

    float c[2][8][4];
#pragma unroll
    for (int i = 0; i < 2; i++)
#pragma unroll
        for (int j = 0; j < 8; j++)
#pragma unroll
            for (int q = 0; q < 4; q++) c[i][j][q] = 0.f;

    int wm = wid & 3, wn = wid >> 2;   // 4 m-tiles x 2 n-tiles

    for (int kc = 0; kc < NCH; kc++) {
        CP_WAIT2();
        __syncthreads();
        int kn = kc + 3;
        if (kn < NCH) LOAD_CHUNK(kn);
        uint32_t aBase = sAb + (kc & 3) * 8192;
        uint32_t bBase = sBb + (kc & 3) * 8192;
#pragma unroll
        for (int kk = 0; kk < 2; kk++) {
            uint32_t afr[2][4], bfr[8][2];
#pragma unroll
            for (int mt = 0; mt < 2; mt++) {
                int r = wm * 32 + mt * 16 + (lane & 15);
                int s = kk * 2 + (lane >> 4);
                ldsm4(afr[mt][0], afr[mt][1], afr[mt][2], afr[mt][3],
                      aBase + r * 64 + ((s ^ (r & 3)) << 4));
            }
#pragma unroll
            for (int np = 0; np < 4; np++) {
                int r = wn * 64 + np * 16 + (lane & 7) + ((lane >> 4) << 3);
                int s = kk * 2 + ((lane >> 3) & 1);
                ldsm4(bfr[2 * np][0], bfr[2 * np][1], bfr[2 * np + 1][0], bfr[2 * np + 1][1],
                      bBase + r * 64 + ((s ^ (r & 3)) << 4));
            }
#pragma unroll
            for (int mt = 0; mt < 2; mt++)
#pragma unroll
                for (int nt = 0; nt < 8; nt++)
                    mma16816(c[mt][nt], afr[mt], bfr[nt]);
        }
    }
#undef LOAD_CHUNK

    // epilogue: BN + ReLU (+ re-split for layer 1)
#pragma unroll
    for (int mt = 0; mt < 2; mt++) {
#pragma unroll
        for (int nt = 0; nt < 8; nt++) {
            int cl = wn * 64 + nt * 8 + (lane & 3) * 2;
            int gcol = bn + cl;
            int rl = wm * 32 + mt * 16 + (lane >> 2);
#pragma unroll
            for (int hh = 0; hh < 2; hh++) {
                int grow = bm + rl + hh * 8;
                float v0 = fmaxf(fmaf(c[mt][nt][hh * 2 + 0], s_al[cl],     s_be[cl]),     0.f);
                float v1 = fmaxf(fmaf(c[mt][nt][hh * 2 + 1], s_al[cl + 1], s_be[cl + 1]), 0.f);
                if (L == 1) {
                    ushortT h0, l0, h1, l1;
                    split_hf(v0, h0, l0); split_hf(v1, h1, l1);
                    *(uintT*)&gA2[(size_t)grow * 512 + gcol]       = (uintT)h0 | ((uintT)h1 << 16);
                    *(uintT*)&gA2[(size_t)grow * 512 + 256 + gcol] = (uintT)l0 | ((uintT)l1 << 16);
                } else {
                    float2 o = make_float2(v0, v1);
                    *(float2*)&g_h[(size_t)grow * 256 + gcol] = o;
                }
            }
        }
    }
}

// ---------------- encoding ----------------
__global__ __launch_bounds__(256) void encoding_kernel(const float* __restrict__ cw,
                                                       const float* __restrict__ scale)
{
    __shared__ float cwT[256][32];
    __shared__ float Ash[64][32];
    __shared__ float c2s[32], scs[32];
    int bz = blockIdx.y;
    int n0 = blockIdx.x * 64;
    int t = threadIdx.x, warp = t >> 5, lane = t & 31;
    for (int i = t; i < 32 * 256; i += 256) cwT[i & 255][i >> 8] = cw[i];
    if (t < 32) { c2s[t] = g_c2[t]; scs[t] = scale[t]; }
    __syncthreads();
    const float* Xb = g_h + ((size_t)bz * NQ + n0) * 256;
    for (int pi = 0; pi < 8; pi++) {
        int p = warp * 8 + pi;
        const float* xp = Xb + (size_t)p * 256;
        float xr[8];
#pragma unroll
        for (int j = 0; j < 8; j++) xr[j] = xp[j * 32 + lane];
        float xn2 = 0.f;
#pragma unroll
        for (int j = 0; j < 8; j++) xn2 = fmaf(xr[j], xr[j], xn2);
#pragma unroll
        for (int o = 16; o > 0; o >>= 1) xn2 += __shfl_xor_sync(0xffffffffu, xn2, o);
        float dotv = 0.f;
#pragma unroll
        for (int j = 0; j < 8; j++) {
            float xj = xr[j];
#pragma unroll
            for (int l2 = 0; l2 < 32; l2++) {
                float x = __shfl_sync(0xffffffffu, xj, l2);
                dotv = fmaf(x, cwT[j * 32 + l2][lane], dotv);
            }
        }
        float sl = scs[lane] * (xn2 - 2.f * dotv + c2s[lane]);
        float mx = sl;
#pragma unroll
        for (int o = 16; o > 0; o >>= 1) mx = fmaxf(mx, __shfl_xor_sync(0xffffffffu, mx, o));
        float e = __expf(sl - mx);
        float se = e;
#pragma unroll
        for (int o = 16; o > 0; o >>= 1) se += __shfl_xor_sync(0xffffffffu, se, o);
        Ash[p][lane] = e / se;
    }
    __syncthreads();
    if (t < 32) {
        float s = 0.f;
        for (int p = 0; p < 64; p++) s += Ash[p][t];
        atomicAdd(&g_sumA[bz * 32 + t], s);
    }
    float acc[32];
#pragma unroll
    for (int k = 0; k < 32; k++) acc[k] = 0.f;
    for (int p = 0; p < 64; p++) {
        float x = Xb[(size_t)p * 256 + t];
#pragma unroll
        for (int k = 0; k < 32; k++) acc[k] = fmaf(Ash[p][k], x, acc[k]);
    }
    float* Eb = g_E + (size_t)bz * 8192;
#pragma unroll
    for (int k = 0; k < 32; k++) atomicAdd(&Eb[k * 256 + t], acc[k]);
}

__global__ __launch_bounds__(256) void enc_fin_kernel(const float* __restrict__ cw)
{
    __shared__ float red[256];
    int bz = blockIdx.x, t = threadIdx.x;
    float ss = 0.f;
    for (int j = t; j < 8192; j += 256) {
        float v = g_E[bz * 8192 + j] - g_sumA[bz * 32 + (j >> 8)] * cw[j];
        v = fmaxf(v, 0.f);
        g_En[bz * 8192 + j] = v;
        ss += v * v;
    }
    red[t] = ss;
    __syncthreads();
    for (int s = 128; s > 0; s >>= 1) {
        if (t < s) red[t] += red[t + s];
        __syncthreads();
    }
    float rinv = 1.f / fmaxf(sqrtf(red[0]), 1e-12f);
    for (int j = t; j < 8192; j += 256) g_En[bz * 8192 + j] *= rinv;
}

__global__ __launch_bounds__(256) void ctx_gemv_kernel(const float* __restrict__ lin_w,
                                                       const float* __restrict__ lin_b)
{
    __shared__ float red[8][256];
    int o = blockIdx.x, t = threadIdx.x;
    float acc[8];
#pragma unroll
    for (int b = 0; b < 8; b++) acc[b] = 0.f;
    const float* wrow = lin_w + (size_t)o * 8192;
    for (int j = t; j < 8192; j += 256) {
        float w = wrow[j];
#pragma unroll
        for (int b = 0; b < 8; b++) acc[b] = fmaf(w, g_En[b * 8192 + j], acc[b]);
    }
#pragma unroll
    for (int b = 0; b < 8; b++) red[b][t] = acc[b];
    __syncthreads();
    for (int s = 128; s > 0; s >>= 1) {
        if (t < s) {
#pragma unroll
            for (int b = 0; b < 8; b++) red[b][t] += red[b][t + s];
        }
        __syncthreads();
    }
    if (t < 8) {
        float z = red[t][0] + lin_b[o];
        g_ctx[t * 256 + o] = 1.f / (1.f + expf(-z));
    }
}

__global__ void final_kernel(float* __restrict__ out)
{
    __shared__ float tile[32][33];
    int bz = blockIdx.z;
    int d0 = blockIdx.x * 32, n0 = blockIdx.y * 32;
    int tx = threadIdx.x, ty = threadIdx.y;
    const float* h = g_h + (size_t)bz * NQ * 256;
#pragma unroll
    for (int j = 0; j < 32; j += 8)
        tile[ty + j][tx] = h[(size_t)(n0 + ty + j) * 256 + d0 + tx];
    __syncthreads();
    float* ob = out + (size_t)bz * 256 * NQ;
#pragma unroll
    for (int j = 0; j < 32; j += 8)
        ob[(size_t)(d0 + ty + j) * NQ + n0 + tx] = tile[tx][ty + j] * g_ctx[bz * 256 + d0 + ty + j];
}

// ===================== launcher =====================
extern "C" void kernel_launch(void* const* d_in, const int* in_sizes, int n_in,
                              void* d_out, int out_size)
{
    (void)in_sizes; (void)n_in; (void)out_size;
    const float* unknown      = (const float*)d_in[0];
    const float* known        = (const float*)d_in[1];
    const float* unknow_feats = (const float*)d_in[2];
    const float* known_feats  = (const float*)d_in[3];
    const float* conv_w1 = (const float*)d_in[4];
    const float* conv_b1 = (const float*)d_in[5];
    const float* bn_g1 = (const float*)d_in[6];
    const float* bn_b1 = (const float*)d_in[7];
    const float* bn_m1 = (const float*)d_in[8];
    const float* bn_v1 = (const float*)d_in[9];
    const float* conv_w2 = (const float*)d_in[10];
    const float* conv_b2 = (const float*)d_in[11];
    const float* bn_g2 = (const float*)d_in[12];
    const float* bn_b2 = (const float*)d_in[13];
    const float* bn_m2 = (const float*)d_in[14];
    const float* bn_v2 = (const float*)d_in[15];
    const float* enc_cw    = (const float*)d_in[16];
    const float* enc_scale = (const float*)d_in[17];
    const float* lin_w     = (const float*)d_in[18];
    const float* lin_b     = (const float*)d_in[19];
    float* out = (float*)d_out;

    const int SMEMSZ = 4 * 16384 + 1024;   // 4 stages (A+B) + alpha/beta
    static int attr_done = 0;
    if (!attr_done) {
        cudaFuncSetAttribute(gemm_mma<1>, cudaFuncAttributeMaxDynamicSharedMemorySize, SMEMSZ);
        cudaFuncSetAttribute(gemm_mma<2>, cudaFuncAttributeMaxDynamicSharedMemorySize, SMEMSZ);
        attr_done = 1;
    }

    prep_kernel<<<256, 256>>>(conv_b1, bn_g1, bn_b1, bn_m1, bn_v1,
                              conv_b2, bn_g2, bn_b2, bn_m2, bn_v2, enc_cw);
    expand_w_kernel<<<512, 256>>>(conv_w1, conv_w2);
    tr_kf_kernel<<<dim3(64, 8, 8), dim3(32, 8)>>>(known_feats);
    three_nn_kernel<<<dim3(NQ / 64, B_), 256>>>(unknown, known);
    interp_kernel<<<dim3(NQ / 4, B_), 256>>>();
    tr_unk_kernel<<<dim3(NQ / 32, 8, B_), dim3(32, 8)>>>(unknow_feats);
    gemm_mma<1><<<dim3(512, 2), 256, SMEMSZ>>>();
    gemm_mma<2><<<dim3(512, 2), 256, SMEMSZ>>>();
    encoding_kernel<<<dim3(NQ / 64, B_), 256>>>(enc_cw, enc_scale);
    enc_fin_kernel<<<B_, 256>>>(enc_cw);
    ctx_gemv_kernel<<<256, 256>>>(lin_w, lin_b);
    final_kernel<<<dim3(8, NQ / 32, B_), dim3(32, 8)>>>(out);
}

// round 11
// speedup vs baseline: 1.3294x; 1.0071x over previous
#include <cuda_runtime.h>
#include <cuda_fp16.h>
#include <math.h>
#include <stdint.h>

#define B_   8
#define NQ   8192
#define MK   2048
typedef unsigned short ushortT;
typedef unsigned int   uintT;

// ===================== helpers =====================
__device__ __forceinline__ uint32_t smem_to_u32(const void* p) {
    uint32_t a;
    asm("{ .reg .u64 t; cvta.to.shared.u64 t, %1; cvt.u32.u64 %0, t; }" : "=r"(a) : "l"(p));
    return a;
}
#define CP_ASYNC16(s, g) \
    asm volatile("cp.async.cg.shared.global [%0], [%1], 16;" :: "r"(s), "l"(g))
#define CP_COMMIT() asm volatile("cp.async.commit_group;")
#define CP_WAIT2()  asm volatile("cp.async.wait_group 2;")

__device__ __forceinline__ void ldsm4(uint32_t& r0, uint32_t& r1, uint32_t& r2, uint32_t& r3,
                                      uint32_t addr) {
    asm volatile("ldmatrix.sync.aligned.m8n8.x4.shared.b16 {%0,%1,%2,%3}, [%4];"
                 : "=r"(r0), "=r"(r1), "=r"(r2), "=r"(r3) : "r"(addr));
}
__device__ __forceinline__ void mma16816(float* d, const uint32_t* a, const uint32_t* b) {
    asm volatile(
        "mma.sync.aligned.m16n8k16.row.col.f32.f16.f16.f32 "
        "{%0,%1,%2,%3}, {%4,%5,%6,%7}, {%8,%9}, {%0,%1,%2,%3};"
        : "+f"(d[0]), "+f"(d[1]), "+f"(d[2]), "+f"(d[3])
        : "r"(a[0]), "r"(a[1]), "r"(a[2]), "r"(a[3]), "r"(b[0]), "r"(b[1]));
}

// fp32 -> fp16 hi + fp16 lo (RNE); h+l carries ~22 mantissa bits
__device__ __forceinline__ void split_hf(float v, ushortT& h, ushortT& l) {
    __half hh = __float2half_rn(v);
    h = __half_as_ushort(hh);
    __half ll = __float2half_rn(v - __half2float(hh));
    l = __half_as_ushort(ll);
}

__device__ __forceinline__ void ins3(float& d0, int& i0, float& d1, int& i1,
                                     float& d2, int& i2, float dd, int m) {
    if (dd < d2) {
        if (dd < d1) {
            d2 = d1; i2 = i1;
            if (dd < d0) { d1 = d0; i1 = i0; d0 = dd; i0 = m; }
            else          { d1 = dd; i1 = m; }
        } else { d2 = dd; i2 = m; }
    }
}

// ===================== scratch =====================
__device__ ushortT gA1[(size_t)8 * 8192 * 1024];  // fp16 [H(512) | L(512)]
__device__ ushortT gA2[(size_t)8 * 8192 * 512];   // fp16 [H(256) | L(256)]
__device__ ushortT gW1[256 * 1024];               // fp16 [Wh | Wh]
__device__ ushortT gW2[256 * 512];
__device__ float g_h  [(size_t)8 * 8192 * 256];
__device__ float g_kfT[(size_t)8 * 2048 * 256];
__device__ int   g_idx[8 * 8192 * 3];
__device__ float g_wgt[8 * 8192 * 3];
__device__ float g_E  [8 * 8192];
__device__ float g_En [8 * 8192];
__device__ float g_sumA[8 * 32];
__device__ float g_ctx[8 * 256];
__device__ float g_al1[256], g_be1[256], g_al2[256], g_be2[256];
__device__ float g_c2[32];

// ===================== fused front kernel =====================
// blockIdx.x ranges:
//  [0, 4096)           tr_kf       (m0 x c0 x b : 64 x 8 x 8)
//  [4096, 20480)       tr_unk      (n0 x c0 x b : 256 x 8 x 8)
//  [20480, 22528)      three_nn    (qblk x b : 256 x 8), 8 threads/query
//  [22528, 23040)      expand_w    (512 blocks)
//  [23040, 23296)      prep        (256 blocks)
#define FR_TRKF   4096
#define FR_TRUNK  20480
#define FR_3NN    22528
#define FR_EXPW   23040
#define FR_TOTAL  23296
#define CHPAD8    257

__global__ __launch_bounds__(256) void front_kernel(
    const float* __restrict__ unknown, const float* __restrict__ known,
    const float* __restrict__ uf, const float* __restrict__ kf,
    const float* __restrict__ w1, const float* __restrict__ w2,
    const float* __restrict__ cb1, const float* __restrict__ gg1,
    const float* __restrict__ bb1, const float* __restrict__ mm1,
    const float* __restrict__ vv1,
    const float* __restrict__ cb2, const float* __restrict__ gg2,
    const float* __restrict__ bb2, const float* __restrict__ mm2,
    const float* __restrict__ vv2,
    const float* __restrict__ cw)
{
    __shared__ __align__(16) char sbuf[8 * CHPAD8 * 16];   // 32896 B, reused per branch
    int bx = blockIdx.x;
    int t  = threadIdx.x;

    if (bx < FR_TRKF) {
        // ---- transpose known_feats (B,256,2048) -> g_kfT (B,2048,256) ----
        float (*tile)[33] = (float(*)[33])sbuf;
        int m0 = (bx & 63) * 32, c0 = ((bx >> 6) & 7) * 32, b = bx >> 9;
        int tx = t & 31, ty = t >> 5;
        const float* in = kf + (size_t)b * 256 * MK;
#pragma unroll
        for (int j = 0; j < 32; j += 8)
            tile[ty + j][tx] = in[(size_t)(c0 + ty + j) * MK + m0 + tx];
        __syncthreads();
        float* out = g_kfT + (size_t)b * MK * 256;
#pragma unroll
        for (int j = 0; j < 32; j += 8)
            out[(size_t)(m0 + ty + j) * 256 + c0 + tx] = tile[tx][ty + j];
    } else if (bx < FR_TRUNK) {
        // ---- transpose unknow_feats -> gA1 cols [256,512) H, [768,1024) L ----
        float (*tile)[33] = (float(*)[33])sbuf;
        int idx = bx - FR_TRKF;
        int n0 = (idx & 255) * 32, c0 = ((idx >> 8) & 7) * 32, b = idx >> 11;
        int tx = t & 31, ty = t >> 5;
        const float* in = uf + (size_t)b * 256 * NQ;
#pragma unroll
        for (int j = 0; j < 32; j += 8)
            tile[ty + j][tx] = in[(size_t)(c0 + ty + j) * NQ + n0 + tx];
        __syncthreads();
#pragma unroll
        for (int j = 0; j < 32; j += 8) {
            float v = tile[tx][ty + j];
            ushortT h, l; split_hf(v, h, l);
            size_t row = ((size_t)b * NQ + n0 + ty + j) * 1024;
            gA1[row + 256 + c0 + tx] = h;
            gA1[row + 768 + c0 + tx] = l;
        }
    } else if (bx < FR_3NN) {
        // ---- three_nn: 8 threads/query, 256-pt chunks, conflict-free padding ----
        float4* kp = (float4*)sbuf;     // kp[ck * 257 + j]
        int idx = bx - FR_TRUNK;
        int bz = idx >> 8;
        int q  = (idx & 255) * 32 + (t >> 3);
        int ck = t & 7;

        const float* kb = known + (size_t)bz * MK * 3;
        for (int i = t; i < MK; i += 256) {
            float kx = kb[i * 3 + 0];
            float ky = kb[i * 3 + 1];
            float kz = kb[i * 3 + 2];
            kp[(i >> 8) * CHPAD8 + (i & 255)] = make_float4(kx, ky, kz, kx * kx + ky * ky + kz * kz);
        }
        __syncthreads();

        const float* u = unknown + ((size_t)bz * NQ + q) * 3;
        float ux = u[0], uy = u[1], uz = u[2];
        float x2 = ux * ux + uy * uy + uz * uz;
        float mux = -2.f * ux, muy = -2.f * uy, muz = -2.f * uz;

        float d0 = 1e30f, d1 = 1e30f, d2 = 1e30f;
        int   i0 = 0, i1 = 0, i2 = 0;
        const float4* base = kp + ck * CHPAD8;
        int m0 = ck * 256;
#pragma unroll 4
        for (int j = 0; j < 256; j++) {
            float4 p = base[j];
            float dd = fmaf(mux, p.x, p.w);
            dd = fmaf(muy, p.y, dd);
            dd = fmaf(muz, p.z, dd);
            ins3(d0, i0, d1, i1, d2, i2, dd, m0 + j);
        }

#pragma unroll
        for (int off = 1; off <= 4; off <<= 1) {
            float e0 = __shfl_xor_sync(0xffffffffu, d0, off);
            float e1 = __shfl_xor_sync(0xffffffffu, d1, off);
            float e2 = __shfl_xor_sync(0xffffffffu, d2, off);
            int   j0 = __shfl_xor_sync(0xffffffffu, i0, off);
            int   j1 = __shfl_xor_sync(0xffffffffu, i1, off);
            int   j2 = __shfl_xor_sync(0xffffffffu, i2, off);
            ins3(d0, i0, d1, i1, d2, i2, e0, j0);
            ins3(d0, i0, d1, i1, d2, i2, e1, j1);
            ins3(d0, i0, d1, i1, d2, i2, e2, j2);
        }

        if (ck == 0) {
            float r0 = 1.f / (sqrtf(fmaxf(d0 + x2, 1e-12f)) + 1e-8f);
            float r1 = 1.f / (sqrtf(fmaxf(d1 + x2, 1e-12f)) + 1e-8f);
            float r2 = 1.f / (sqrtf(fmaxf(d2 + x2, 1e-12f)) + 1e-8f);
            float rs = 1.f / (r0 + r1 + r2);
            size_t base2 = ((size_t)bz * NQ + q) * 3;
            g_idx[base2 + 0] = i0; g_idx[base2 + 1] = i1; g_idx[base2 + 2] = i2;
            g_wgt[base2 + 0] = r0 * rs; g_wgt[base2 + 1] = r1 * rs; g_wgt[base2 + 2] = r2 * rs;
        }
    } else if (bx < FR_EXPW) {
        // ---- expand weights to fp16 [Wh | Wh] ----
        int i = (bx - FR_3NN) * 256 + t;
        if (i < 256 * 512) {
            int n = i >> 9, k = i & 511;
            ushortT h = __half_as_ushort(__float2half_rn(w1[i]));
            gW1[n * 1024 + k] = h; gW1[n * 1024 + 512 + k] = h;
        }
        if (i < 256 * 256) {
            int n = i >> 8, k = i & 255;
            ushortT h = __half_as_ushort(__float2half_rn(w2[i]));
            gW2[n * 512 + k] = h; gW2[n * 512 + 256 + k] = h;
        }
    } else {
        // ---- prep: BN fold, codeword norms, zero accumulators ----
        int i = (bx - FR_EXPW) * 256 + t;
        if (i < 256) {
            float s1 = gg1[i] * rsqrtf(vv1[i] + 1e-5f);
            g_al1[i] = s1;
            g_be1[i] = s1 * (cb1[i] - mm1[i]) + bb1[i];
            float s2 = gg2[i] * rsqrtf(vv2[i] + 1e-5f);
            g_al2[i] = s2;
            g_be2[i] = s2 * (cb2[i] - mm2[i]) + bb2[i];
        }
        if (i < 32) {
            float s = 0.f;
            const float* c = cw + i * 256;
            for (int d = 0; d < 256; d++) s += c[d] * c[d];
            g_c2[i] = s;
        }
        if (i < 8 * 32) g_sumA[i] = 0.f;
        if (i < 8 * 8192) g_E[i] = 0.f;
    }
}

// ---------------- interpolate -> gA1 cols [0,256) H, [512,768) L (4-wide) -----------
__global__ __launch_bounds__(256) void interp_kernel()
{
    int bz = blockIdx.y, t = threadIdx.x;
    int n = blockIdx.x * 4 + (t >> 6);
    int d = (t & 63) * 4;
    size_t base = ((size_t)bz * NQ + n) * 3;
    int i0 = g_idx[base], i1 = g_idx[base + 1], i2 = g_idx[base + 2];
    float w0 = g_wgt[base], w1 = g_wgt[base + 1], w2 = g_wgt[base + 2];
    const float* kf = g_kfT + (size_t)bz * MK * 256;
    float4 a = *(const float4*)&kf[(size_t)i0 * 256 + d];
    float4 b = *(const float4*)&kf[(size_t)i1 * 256 + d];
    float4 c = *(const float4*)&kf[(size_t)i2 * 256 + d];
    float v0 = w0 * a.x + w1 * b.x + w2 * c.x;
    float v1 = w0 * a.y + w1 * b.y + w2 * c.y;
    float v2 = w0 * a.z + w1 * b.z + w2 * c.z;
    float v3 = w0 * a.w + w1 * b.w + w2 * c.w;
    ushortT h0, l0, h1, l1, h2, l2, h3, l3;
    split_hf(v0, h0, l0); split_hf(v1, h1, l1);
    split_hf(v2, h2, l2); split_hf(v3, h3, l3);
    size_t row = ((size_t)bz * NQ + n) * 1024;
    uint2 hp = make_uint2((uintT)h0 | ((uintT)h1 << 16), (uintT)h2 | ((uintT)h3 << 16));
    uint2 lp = make_uint2((uintT)l0 | ((uintT)l1 << 16), (uintT)l2 | ((uintT)l3 << 16));
    *(uint2*)&gA1[row + d]       = hp;
    *(uint2*)&gA1[row + 512 + d] = lp;
}

// ===================== HMMA GEMM (fp16 2-term split, 32x64 warp tiles) =====================
template <int L>
__global__ __launch_bounds__(256) void gemm_mma()
{
    constexpr int K   = (L == 1) ? 512 : 256;
    constexpr int KX  = 2 * K;
    constexpr int NCH = KX / 32;
    const ushortT* Ag = (L == 1) ? gA1 : gA2;
    const ushortT* Wg = (L == 1) ? gW1 : gW2;
    const float* alpha = (L == 1) ? g_al1 : g_al2;
    const float* beta  = (L == 1) ? g_be1 : g_be2;

    extern __shared__ __align__(16) ushortT dyn[];
    ushortT* sA = dyn;
    ushortT* sB = dyn + 4 * 4096;
    float* s_al = (float*)(dyn + 8 * 4096);
    float* s_be = s_al + 128;

    int tid = threadIdx.x, wid = tid >> 5, lane = tid & 31;
    int bm = blockIdx.x * 128, bn = blockIdx.y * 128;
    if (tid < 128) { s_al[tid] = alpha[bn + tid]; s_be[tid] = beta[bn + tid]; }

    uint32_t sAb = smem_to_u32(sA);
    uint32_t sBb = smem_to_u32(sB);

    int lr = tid >> 1;
    int ls = (tid & 1) * 2;
    uint32_t off0 = lr * 64 + (((ls)     ^ (lr & 3)) << 4);
    uint32_t off1 = lr * 64 + (((ls + 1) ^ (lr & 3)) << 4);

    const ushortT* Arow = Ag + (size_t)(bm + lr) * KX;
    const ushortT* Wrow = Wg + (size_t)(bn + lr) * KX;

#define LOAD_CHUNK(p) do { \
    int _col = (p) * 32; \
    uint32_t _as = sAb + ((p) & 3) * 8192; \
    uint32_t _ws = sBb + ((p) & 3) * 8192; \
    CP_ASYNC16(_as + off0, Arow + _col + ls * 8); \
    CP_ASYNC16(_as + off1, Arow + _col + ls * 8 + 8); \
    CP_ASYNC16(_ws + off0, Wrow + _col + ls * 8); \
    CP_ASYNC16(_ws + off1, Wrow + _col + ls * 8 + 8); \
    CP_COMMIT(); } while (0)

    LOAD_CHUNK(0);
    LOAD_CHUNK(1);
    LOAD_CHUNK(2);

    float c[2][8][4];
#pragma unroll
    for (int i = 0; i < 2; i++)
#pragma unroll
        for (int j = 0; j < 8; j++)
#pragma unroll
            for (int q = 0; q < 4; q++) c[i][j][q] = 0.f;

    int wm = wid & 3, wn = wid >> 2;

    for (int kc = 0; kc < NCH; kc++) {
        CP_WAIT2();
        __syncthreads();
        int kn = kc + 3;
        if (kn < NCH) LOAD_CHUNK(kn);
        uint32_t aBase = sAb + (kc & 3) * 8192;
        uint32_t bBase = sBb + (kc & 3) * 8192;
#pragma unroll
        for (int kk = 0; kk < 2; kk++) {
            uint32_t afr[2][4], bfr[8][2];
#pragma unroll
            for (int mt = 0; mt < 2; mt++) {
                int r = wm * 32 + mt * 16 + (lane & 15);
                int s = kk * 2 + (lane >> 4);
                ldsm4(afr[mt][0], afr[mt][1], afr[mt][2], afr[mt][3],
                      aBase + r * 64 + ((s ^ (r & 3)) << 4));
            }
#pragma unroll
            for (int np = 0; np < 4; np++) {
                int r = wn * 64 + np * 16 + (lane & 7) + ((lane >> 4) << 3);
                int s = kk * 2 + ((lane >> 3) & 1);
                ldsm4(bfr[2 * np][0], bfr[2 * np][1], bfr[2 * np + 1][0], bfr[2 * np + 1][1],
                      bBase + r * 64 + ((s ^ (r & 3)) << 4));
            }
#pragma unroll
            for (int mt = 0; mt < 2; mt++)
#pragma unroll
                for (int nt = 0; nt < 8; nt++)
                    mma16816(c[mt][nt], afr[mt], bfr[nt]);
        }
    }
#undef LOAD_CHUNK

#pragma unroll
    for (int mt = 0; mt < 2; mt++) {
#pragma unroll
        for (int nt = 0; nt < 8; nt++) {
            int cl = wn * 64 + nt * 8 + (lane & 3) * 2;
            int gcol = bn + cl;
            int rl = wm * 32 + mt * 16 + (lane >> 2);
#pragma unroll
            for (int hh = 0; hh < 2; hh++) {
                int grow = bm + rl + hh * 8;
                float v0 = fmaxf(fmaf(c[mt][nt][hh * 2 + 0], s_al[cl],     s_be[cl]),     0.f);
                float v1 = fmaxf(fmaf(c[mt][nt][hh * 2 + 1], s_al[cl + 1], s_be[cl + 1]), 0.f);
                if (L == 1) {
                    ushortT h0, l0, h1, l1;
                    split_hf(v0, h0, l0); split_hf(v1, h1, l1);
                    *(uintT*)&gA2[(size_t)grow * 512 + gcol]       = (uintT)h0 | ((uintT)h1 << 16);
                    *(uintT*)&gA2[(size_t)grow * 512 + 256 + gcol] = (uintT)l0 | ((uintT)l1 << 16);
                } else {
                    float2 o = make_float2(v0, v1);
                    *(float2*)&g_h[(size_t)grow * 256 + gcol] = o;
                }
            }
        }
    }
}

// ---------------- encoding ----------------
__global__ __launch_bounds__(256) void encoding_kernel(const float* __restrict__ cw,
                                                       const float* __restrict__ scale)
{
    __shared__ float cwT[256][32];
    __shared__ float Ash[64][32];
    __shared__ float c2s[32], scs[32];
    int bz = blockIdx.y;
    int n0 = blockIdx.x * 64;
    int t = threadIdx.x, warp = t >> 5, lane = t & 31;
    for (int i = t; i < 32 * 256; i += 256) cwT[i & 255][i >> 8] = cw[i];
    if (t < 32) { c2s[t] = g_c2[t]; scs[t] = scale[t]; }
    __syncthreads();
    const float* Xb = g_h + ((size_t)bz * NQ + n0) * 256;
    for (int pi = 0; pi < 8; pi++) {
        int p = warp * 8 + pi;
        const float* xp = Xb + (size_t)p * 256;
        float xr[8];
#pragma unroll
        for (int j = 0; j < 8; j++) xr[j] = xp[j * 32 + lane];
        float xn2 = 0.f;
#pragma unroll
        for (int j = 0; j < 8; j++) xn2 = fmaf(xr[j], xr[j], xn2);
#pragma unroll
        for (int o = 16; o > 0; o >>= 1) xn2 += __shfl_xor_sync(0xffffffffu, xn2, o);
        float dotv = 0.f;
#pragma unroll
        for (int j = 0; j < 8; j++) {
            float xj = xr[j];
#pragma unroll
            for (int l2 = 0; l2 < 32; l2++) {
                float x = __shfl_sync(0xffffffffu, xj, l2);
                dotv = fmaf(x, cwT[j * 32 + l2][lane], dotv);
            }
        }
        float sl = scs[lane] * (xn2 - 2.f * dotv + c2s[lane]);
        float mx = sl;
#pragma unroll
        for (int o = 16; o > 0; o >>= 1) mx = fmaxf(mx, __shfl_xor_sync(0xffffffffu, mx, o));
        float e = __expf(sl - mx);
        float se = e;
#pragma unroll
        for (int o = 16; o > 0; o >>= 1) se += __shfl_xor_sync(0xffffffffu, se, o);
        Ash[p][lane] = e / se;
    }
    __syncthreads();
    if (t < 32) {
        float s = 0.f;
        for (int p = 0; p < 64; p++) s += Ash[p][t];
        atomicAdd(&g_sumA[bz * 32 + t], s);
    }
    float acc[32];
#pragma unroll
    for (int k = 0; k < 32; k++) acc[k] = 0.f;
    for (int p = 0; p < 64; p++) {
        float x = Xb[(size_t)p * 256 + t];
#pragma unroll
        for (int k = 0; k < 32; k++) acc[k] = fmaf(Ash[p][k], x, acc[k]);
    }
    float* Eb = g_E + (size_t)bz * 8192;
#pragma unroll
    for (int k = 0; k < 32; k++) atomicAdd(&Eb[k * 256 + t], acc[k]);
}

__global__ __launch_bounds__(256) void enc_fin_kernel(const float* __restrict__ cw)
{
    __shared__ float red[256];
    int bz = blockIdx.x, t = threadIdx.x;
    float ss = 0.f;
    for (int j = t; j < 8192; j += 256) {
        float v = g_E[bz * 8192 + j] - g_sumA[bz * 32 + (j >> 8)] * cw[j];
        v = fmaxf(v, 0.f);
        g_En[bz * 8192 + j] = v;
        ss += v * v;
    }
    red[t] = ss;
    __syncthreads();
    for (int s = 128; s > 0; s >>= 1) {
        if (t < s) red[t] += red[t + s];
        __syncthreads();
    }
    float rinv = 1.f / fmaxf(sqrtf(red[0]), 1e-12f);
    for (int j = t; j < 8192; j += 256) g_En[bz * 8192 + j] *= rinv;
}

__global__ __launch_bounds__(256) void ctx_gemv_kernel(const float* __restrict__ lin_w,
                                                       const float* __restrict__ lin_b)
{
    __shared__ float red[8][256];
    int o = blockIdx.x, t = threadIdx.x;
    float acc[8];
#pragma unroll
    for (int b = 0; b < 8; b++) acc[b] = 0.f;
    const float* wrow = lin_w + (size_t)o * 8192;
    for (int j = t; j < 8192; j += 256) {
        float w = wrow[j];
#pragma unroll
        for (int b = 0; b < 8; b++) acc[b] = fmaf(w, g_En[b * 8192 + j], acc[b]);
    }
#pragma unroll
    for (int b = 0; b < 8; b++) red[b][t] = acc[b];
    __syncthreads();
    for (int s = 128; s > 0; s >>= 1) {
        if (t < s) {
#pragma unroll
            for (int b = 0; b < 8; b++) red[b][t] += red[b][t + s];
        }
        __syncthreads();
    }
    if (t < 8) {
        float z = red[t][0] + lin_b[o];
        g_ctx[t * 256 + o] = 1.f / (1.f + expf(-z));
    }
}

__global__ void final_kernel(float* __restrict__ out)
{
    __shared__ float tile[32][33];
    int bz = blockIdx.z;
    int d0 = blockIdx.x * 32, n0 = blockIdx.y * 32;
    int tx = threadIdx.x, ty = threadIdx.y;
    const float* h = g_h + (size_t)bz * NQ * 256;
#pragma unroll
    for (int j = 0; j < 32; j += 8)
        tile[ty + j][tx] = h[(size_t)(n0 + ty + j) * 256 + d0 + tx];
    __syncthreads();
    float* ob = out + (size_t)bz * 256 * NQ;
#pragma unroll
    for (int j = 0; j < 32; j += 8)
        ob[(size_t)(d0 + ty + j) * NQ + n0 + tx] = tile[tx][ty + j] * g_ctx[bz * 256 + d0 + ty + j];
}

// ===================== launcher =====================
extern "C" void kernel_launch(void* const* d_in, const int* in_sizes, int n_in,
                              void* d_out, int out_size)
{
    (void)in_sizes; (void)n_in; (void)out_size;
    const float* unknown      = (const float*)d_in[0];
    const float* known        = (const float*)d_in[1];
    const float* unknow_feats = (const float*)d_in[2];
    const float* known_feats  = (const float*)d_in[3];
    const float* conv_w1 = (const float*)d_in[4];
    const float* conv_b1 = (const float*)d_in[5];
    const float* bn_g1 = (const float*)d_in[6];
    const float* bn_b1 = (const float*)d_in[7];
    const float* bn_m1 = (const float*)d_in[8];
    const float* bn_v1 = (const float*)d_in[9];
    const float* conv_w2 = (const float*)d_in[10];
    const float* conv_b2 = (const float*)d_in[11];
    const float* bn_g2 = (const float*)d_in[12];
    const float* bn_b2 = (const float*)d_in[13];
    const float* bn_m2 = (const float*)d_in[14];
    const float* bn_v2 = (const float*)d_in[15];
    const float* enc_cw    = (const float*)d_in[16];
    const float* enc_scale = (const float*)d_in[17];
    const float* lin_w     = (const float*)d_in[18];
    const float* lin_b     = (const float*)d_in[19];
    float* out = (float*)d_out;

    const int SMEMSZ = 4 * 16384 + 1024;
    static int attr_done = 0;
    if (!attr_done) {
        cudaFuncSetAttribute(gemm_mma<1>, cudaFuncAttributeMaxDynamicSharedMemorySize, SMEMSZ);
        cudaFuncSetAttribute(gemm_mma<2>, cudaFuncAttributeMaxDynamicSharedMemorySize, SMEMSZ);
        attr_done = 1;
    }

    front_kernel<<<FR_TOTAL, 256>>>(unknown, known, unknow_feats, known_feats,
                                    conv_w1, conv_w2,
                                    conv_b1, bn_g1, bn_b1, bn_m1, bn_v1,
                                    conv_b2, bn_g2, bn_b2, bn_m2, bn_v2, enc_cw);
    interp_kernel<<<dim3(NQ / 4, B_), 256>>>();
    gemm_mma<1><<<dim3(512, 2), 256, SMEMSZ>>>();
    gemm_mma<2><<<dim3(512, 2), 256, SMEMSZ>>>();
    encoding_kernel<<<dim3(NQ / 64, B_), 256>>>(enc_cw, enc_scale);
    enc_fin_kernel<<<B_, 256>>>(enc_cw);
    ctx_gemv_kernel<<<256, 256>>>(lin_w, lin_b);
    final_kernel<<<dim3(8, NQ / 32, B_), dim3(32, 8)>>>(out);
}

// round 12
// speedup vs baseline: 1.4611x; 1.0990x over previous
#include <cuda_runtime.h>
#include <cuda_fp16.h>
#include <math.h>
#include <stdint.h>

#define B_   8
#define NQ   8192
#define MK   2048
typedef unsigned short ushortT;
typedef unsigned int   uintT;

// ===================== helpers =====================
__device__ __forceinline__ uint32_t smem_to_u32(const void* p) {
    uint32_t a;
    asm("{ .reg .u64 t; cvta.to.shared.u64 t, %1; cvt.u32.u64 %0, t; }" : "=r"(a) : "l"(p));
    return a;
}
#define CP_ASYNC16(s, g) \
    asm volatile("cp.async.cg.shared.global [%0], [%1], 16;" :: "r"(s), "l"(g))
#define CP_COMMIT() asm volatile("cp.async.commit_group;")
#define CP_WAIT1()  asm volatile("cp.async.wait_group 1;")

__device__ __forceinline__ void ldsm4(uint32_t& r0, uint32_t& r1, uint32_t& r2, uint32_t& r3,
                                      uint32_t addr) {
    asm volatile("ldmatrix.sync.aligned.m8n8.x4.shared.b16 {%0,%1,%2,%3}, [%4];"
                 : "=r"(r0), "=r"(r1), "=r"(r2), "=r"(r3) : "r"(addr));
}
__device__ __forceinline__ void mma16816(float* d, const uint32_t* a, const uint32_t* b) {
    asm volatile(
        "mma.sync.aligned.m16n8k16.row.col.f32.f16.f16.f32 "
        "{%0,%1,%2,%3}, {%4,%5,%6,%7}, {%8,%9}, {%0,%1,%2,%3};"
        : "+f"(d[0]), "+f"(d[1]), "+f"(d[2]), "+f"(d[3])
        : "r"(a[0]), "r"(a[1]), "r"(a[2]), "r"(a[3]), "r"(b[0]), "r"(b[1]));
}

// fp32 -> fp16 hi + fp16 lo (RNE); h+l carries ~22 mantissa bits
__device__ __forceinline__ void split_hf(float v, ushortT& h, ushortT& l) {
    __half hh = __float2half_rn(v);
    h = __half_as_ushort(hh);
    __half ll = __float2half_rn(v - __half2float(hh));
    l = __half_as_ushort(ll);
}

__device__ __forceinline__ void ins3(float& d0, int& i0, float& d1, int& i1,
                                     float& d2, int& i2, float dd, int m) {
    if (dd < d2) {
        if (dd < d1) {
            d2 = d1; i2 = i1;
            if (dd < d0) { d1 = d0; i1 = i0; d0 = dd; i0 = m; }
            else          { d1 = dd; i1 = m; }
        } else { d2 = dd; i2 = m; }
    }
}

// ===================== scratch =====================
__device__ ushortT gA1[(size_t)8 * 8192 * 1024];  // fp16 [H(512) | L(512)]
__device__ ushortT gA2[(size_t)8 * 8192 * 512];   // fp16 [H(256) | L(256)]
__device__ ushortT gW1[256 * 512];                // fp16 Wh only
__device__ ushortT gW2[256 * 256];
__device__ float g_h  [(size_t)8 * 8192 * 256];
__device__ float g_kfT[(size_t)8 * 2048 * 256];
__device__ int   g_idx[8 * 8192 * 3];
__device__ float g_wgt[8 * 8192 * 3];
__device__ float g_E  [8 * 8192];
__device__ float g_En [8 * 8192];
__device__ float g_sumA[8 * 32];
__device__ float g_ctx[8 * 256];
__device__ float g_al1[256], g_be1[256], g_al2[256], g_be2[256];
__device__ float g_c2[32];

// ===================== fused front kernel =====================
#define FR_TRKF   4096
#define FR_TRUNK  20480
#define FR_3NN    22528
#define FR_EXPW   23040
#define FR_TOTAL  23296
#define CHPAD8    257

__global__ __launch_bounds__(256) void front_kernel(
    const float* __restrict__ unknown, const float* __restrict__ known,
    const float* __restrict__ uf, const float* __restrict__ kf,
    const float* __restrict__ w1, const float* __restrict__ w2,
    const float* __restrict__ cb1, const float* __restrict__ gg1,
    const float* __restrict__ bb1, const float* __restrict__ mm1,
    const float* __restrict__ vv1,
    const float* __restrict__ cb2, const float* __restrict__ gg2,
    const float* __restrict__ bb2, const float* __restrict__ mm2,
    const float* __restrict__ vv2,
    const float* __restrict__ cw)
{
    __shared__ __align__(16) char sbuf[8 * CHPAD8 * 16];
    int bx = blockIdx.x;
    int t  = threadIdx.x;

    if (bx < FR_TRKF) {
        float (*tile)[33] = (float(*)[33])sbuf;
        int m0 = (bx & 63) * 32, c0 = ((bx >> 6) & 7) * 32, b = bx >> 9;
        int tx = t & 31, ty = t >> 5;
        const float* in = kf + (size_t)b * 256 * MK;
#pragma unroll
        for (int j = 0; j < 32; j += 8)
            tile[ty + j][tx] = in[(size_t)(c0 + ty + j) * MK + m0 + tx];
        __syncthreads();
        float* out = g_kfT + (size_t)b * MK * 256;
#pragma unroll
        for (int j = 0; j < 32; j += 8)
            out[(size_t)(m0 + ty + j) * 256 + c0 + tx] = tile[tx][ty + j];
    } else if (bx < FR_TRUNK) {
        float (*tile)[33] = (float(*)[33])sbuf;
        int idx = bx - FR_TRKF;
        int n0 = (idx & 255) * 32, c0 = ((idx >> 8) & 7) * 32, b = idx >> 11;
        int tx = t & 31, ty = t >> 5;
        const float* in = uf + (size_t)b * 256 * NQ;
#pragma unroll
        for (int j = 0; j < 32; j += 8)
            tile[ty + j][tx] = in[(size_t)(c0 + ty + j) * NQ + n0 + tx];
        __syncthreads();
#pragma unroll
        for (int j = 0; j < 32; j += 8) {
            float v = tile[tx][ty + j];
            ushortT h, l; split_hf(v, h, l);
            size_t row = ((size_t)b * NQ + n0 + ty + j) * 1024;
            gA1[row + 256 + c0 + tx] = h;
            gA1[row + 768 + c0 + tx] = l;
        }
    } else if (bx < FR_3NN) {
        float4* kp = (float4*)sbuf;
        int idx = bx - FR_TRUNK;
        int bz = idx >> 8;
        int q  = (idx & 255) * 32 + (t >> 3);
        int ck = t & 7;

        const float* kb = known + (size_t)bz * MK * 3;
        for (int i = t; i < MK; i += 256) {
            float kx = kb[i * 3 + 0];
            float ky = kb[i * 3 + 1];
            float kz = kb[i * 3 + 2];
            kp[(i >> 8) * CHPAD8 + (i & 255)] = make_float4(kx, ky, kz, kx * kx + ky * ky + kz * kz);
        }
        __syncthreads();

        const float* u = unknown + ((size_t)bz * NQ + q) * 3;
        float ux = u[0], uy = u[1], uz = u[2];
        float x2 = ux * ux + uy * uy + uz * uz;
        float mux = -2.f * ux, muy = -2.f * uy, muz = -2.f * uz;

        float d0 = 1e30f, d1 = 1e30f, d2 = 1e30f;
        int   i0 = 0, i1 = 0, i2 = 0;
        const float4* base = kp + ck * CHPAD8;
        int m0 = ck * 256;
#pragma unroll 4
        for (int j = 0; j < 256; j++) {
            float4 p = base[j];
            float dd = fmaf(mux, p.x, p.w);
            dd = fmaf(muy, p.y, dd);
            dd = fmaf(muz, p.z, dd);
            ins3(d0, i0, d1, i1, d2, i2, dd, m0 + j);
        }

#pragma unroll
        for (int off = 1; off <= 4; off <<= 1) {
            float e0 = __shfl_xor_sync(0xffffffffu, d0, off);
            float e1 = __shfl_xor_sync(0xffffffffu, d1, off);
            float e2 = __shfl_xor_sync(0xffffffffu, d2, off);
            int   j0 = __shfl_xor_sync(0xffffffffu, i0, off);
            int   j1 = __shfl_xor_sync(0xffffffffu, i1, off);
            int   j2 = __shfl_xor_sync(0xffffffffu, i2, off);
            ins3(d0, i0, d1, i1, d2, i2, e0, j0);
            ins3(d0, i0, d1, i1, d2, i2, e1, j1);
            ins3(d0, i0, d1, i1, d2, i2, e2, j2);
        }

        if (ck == 0) {
            float r0 = 1.f / (sqrtf(fmaxf(d0 + x2, 1e-12f)) + 1e-8f);
            float r1 = 1.f / (sqrtf(fmaxf(d1 + x2, 1e-12f)) + 1e-8f);
            float r2 = 1.f / (sqrtf(fmaxf(d2 + x2, 1e-12f)) + 1e-8f);
            float rs = 1.f / (r0 + r1 + r2);
            size_t base2 = ((size_t)bz * NQ + q) * 3;
            g_idx[base2 + 0] = i0; g_idx[base2 + 1] = i1; g_idx[base2 + 2] = i2;
            g_wgt[base2 + 0] = r0 * rs; g_wgt[base2 + 1] = r1 * rs; g_wgt[base2 + 2] = r2 * rs;
        }
    } else if (bx < FR_EXPW) {
        int i = (bx - FR_3NN) * 256 + t;
        if (i < 256 * 512) {
            int n = i >> 9, k = i & 511;
            gW1[n * 512 + k] = __half_as_ushort(__float2half_rn(w1[i]));
        }
        if (i < 256 * 256) {
            int n = i >> 8, k = i & 255;
            gW2[n * 256 + k] = __half_as_ushort(__float2half_rn(w2[i]));
        }
    } else {
        int i = (bx - FR_EXPW) * 256 + t;
        if (i < 256) {
            float s1 = gg1[i] * rsqrtf(vv1[i] + 1e-5f);
            g_al1[i] = s1;
            g_be1[i] = s1 * (cb1[i] - mm1[i]) + bb1[i];
            float s2 = gg2[i] * rsqrtf(vv2[i] + 1e-5f);
            g_al2[i] = s2;
            g_be2[i] = s2 * (cb2[i] - mm2[i]) + bb2[i];
        }
        if (i < 32) {
            float s = 0.f;
            const float* c = cw + i * 256;
            for (int d = 0; d < 256; d++) s += c[d] * c[d];
            g_c2[i] = s;
        }
        if (i < 8 * 32) g_sumA[i] = 0.f;
        if (i < 8 * 8192) g_E[i] = 0.f;
    }
}

// ---------------- interpolate -> gA1 cols [0,256) H, [512,768) L (4-wide) -----------
__global__ __launch_bounds__(256) void interp_kernel()
{
    int bz = blockIdx.y, t = threadIdx.x;
    int n = blockIdx.x * 4 + (t >> 6);
    int d = (t & 63) * 4;
    size_t base = ((size_t)bz * NQ + n) * 3;
    int i0 = g_idx[base], i1 = g_idx[base + 1], i2 = g_idx[base + 2];
    float w0 = g_wgt[base], w1 = g_wgt[base + 1], w2 = g_wgt[base + 2];
    const float* kf = g_kfT + (size_t)bz * MK * 256;
    float4 a = *(const float4*)&kf[(size_t)i0 * 256 + d];
    float4 b = *(const float4*)&kf[(size_t)i1 * 256 + d];
    float4 c = *(const float4*)&kf[(size_t)i2 * 256 + d];
    float v0 = w0 * a.x + w1 * b.x + w2 * c.x;
    float v1 = w0 * a.y + w1 * b.y + w2 * c.y;
    float v2 = w0 * a.z + w1 * b.z + w2 * c.z;
    float v3 = w0 * a.w + w1 * b.w + w2 * c.w;
    ushortT h0, l0, h1, l1, h2, l2, h3, l3;
    split_hf(v0, h0, l0); split_hf(v1, h1, l1);
    split_hf(v2, h2, l2); split_hf(v3, h3, l3);
    size_t row = ((size_t)bz * NQ + n) * 1024;
    uint2 hp = make_uint2((uintT)h0 | ((uintT)h1 << 16), (uintT)h2 | ((uintT)h3 << 16));
    uint2 lp = make_uint2((uintT)l0 | ((uintT)l1 << 16), (uintT)l2 | ((uintT)l3 << 16));
    *(uint2*)&gA1[row + d]       = hp;
    *(uint2*)&gA1[row + 512 + d] = lp;
}

// ===================== HMMA GEMM: shared-B fp16 split =====================
// Per K-chunk (32 cols): load A_H, A_L, B once; B fragments reused for H and L MMAs.
// CTA 128x128, 8 warps as 4m x 2n (warp 32x64), 3 stages x 24KB.
template <int L>
__global__ __launch_bounds__(256) void gemm_mma()
{
    constexpr int K   = (L == 1) ? 512 : 256;
    constexpr int NCH = K / 32;          // 16 / 8
    constexpr int KA  = 2 * K;
    const ushortT* Ag = (L == 1) ? gA1 : gA2;
    const ushortT* Wg = (L == 1) ? gW1 : gW2;
    const float* alpha = (L == 1) ? g_al1 : g_al2;
    const float* beta  = (L == 1) ? g_be1 : g_be2;

    extern __shared__ __align__(16) ushortT dyn[];
    ushortT* sAH = dyn;                   // 3 stages x 4096 ushort
    ushortT* sAL = dyn + 3 * 4096;
    ushortT* sB  = dyn + 6 * 4096;
    float* s_al = (float*)(dyn + 9 * 4096);
    float* s_be = s_al + 128;

    int tid = threadIdx.x, wid = tid >> 5, lane = tid & 31;
    int bn = blockIdx.x * 128, bm = blockIdx.y * 128;   // bn fast -> adjacent CTAs share A
    if (tid < 128) { s_al[tid] = alpha[bn + tid]; s_be[tid] = beta[bn + tid]; }

    uint32_t sAHb = smem_to_u32(sAH);
    uint32_t sALb = smem_to_u32(sAL);
    uint32_t sBb  = smem_to_u32(sB);

    int lr = tid >> 1;
    int ls = (tid & 1) * 2;
    uint32_t off0 = lr * 64 + (((ls)     ^ (lr & 3)) << 4);
    uint32_t off1 = lr * 64 + (((ls + 1) ^ (lr & 3)) << 4);

    const ushortT* ArowH = Ag + (size_t)(bm + lr) * KA;        // H block at [0,K)
    const ushortT* ArowL = ArowH + K;                           // L block at [K,2K)
    const ushortT* Wrow  = Wg + (size_t)(bn + lr) * K;

#define LOAD_CHUNK(p, st) do { \
    int _col = (p) * 32; \
    uint32_t _ah = sAHb + (st) * 8192; \
    uint32_t _al = sALb + (st) * 8192; \
    uint32_t _ws = sBb  + (st) * 8192; \
    CP_ASYNC16(_ah + off0, ArowH + _col + ls * 8); \
    CP_ASYNC16(_ah + off1, ArowH + _col + ls * 8 + 8); \
    CP_ASYNC16(_al + off0, ArowL + _col + ls * 8); \
    CP_ASYNC16(_al + off1, ArowL + _col + ls * 8 + 8); \
    CP_ASYNC16(_ws + off0, Wrow + _col + ls * 8); \
    CP_ASYNC16(_ws + off1, Wrow + _col + ls * 8 + 8); \
    CP_COMMIT(); } while (0)

    LOAD_CHUNK(0, 0);
    LOAD_CHUNK(1, 1);

    float c[2][8][4];
#pragma unroll
    for (int i = 0; i < 2; i++)
#pragma unroll
        for (int j = 0; j < 8; j++)
#pragma unroll
            for (int q = 0; q < 4; q++) c[i][j][q] = 0.f;

    int wm = wid & 3, wn = wid >> 2;

    int st = 0;      // stage of current chunk
    int stn = 2;     // stage for next load
    for (int kc = 0; kc < NCH; kc++) {
        CP_WAIT1();
        __syncthreads();
        int kn = kc + 2;
        if (kn < NCH) LOAD_CHUNK(kn, stn);
        uint32_t aHBase = sAHb + st * 8192;
        uint32_t aLBase = sALb + st * 8192;
        uint32_t bBase  = sBb  + st * 8192;
#pragma unroll
        for (int kk = 0; kk < 2; kk++) {
            uint32_t ah[2][4], al[2][4], bf[8][2];
#pragma unroll
            for (int mt = 0; mt < 2; mt++) {
                int r = wm * 32 + mt * 16 + (lane & 15);
                int s = kk * 2 + (lane >> 4);
                uint32_t ro = r * 64 + ((s ^ (r & 3)) << 4);
                ldsm4(ah[mt][0], ah[mt][1], ah[mt][2], ah[mt][3], aHBase + ro);
                ldsm4(al[mt][0], al[mt][1], al[mt][2], al[mt][3], aLBase + ro);
            }
#pragma unroll
            for (int np = 0; np < 4; np++) {
                int r = wn * 64 + np * 16 + (lane & 7) + ((lane >> 4) << 3);
                int s = kk * 2 + ((lane >> 3) & 1);
                ldsm4(bf[2 * np][0], bf[2 * np][1], bf[2 * np + 1][0], bf[2 * np + 1][1],
                      bBase + r * 64 + ((s ^ (r & 3)) << 4));
            }
#pragma unroll
            for (int mt = 0; mt < 2; mt++)
#pragma unroll
                for (int nt = 0; nt < 8; nt++)
                    mma16816(c[mt][nt], ah[mt], bf[nt]);
#pragma unroll
            for (int mt = 0; mt < 2; mt++)
#pragma unroll
                for (int nt = 0; nt < 8; nt++)
                    mma16816(c[mt][nt], al[mt], bf[nt]);
        }
        st  = (st == 2)  ? 0 : st + 1;
        stn = (stn == 2) ? 0 : stn + 1;
    }
#undef LOAD_CHUNK

    // epilogue: BN + ReLU (+ re-split for layer 1)
#pragma unroll
    for (int mt = 0; mt < 2; mt++) {
#pragma unroll
        for (int nt = 0; nt < 8; nt++) {
            int cl = wn * 64 + nt * 8 + (lane & 3) * 2;
            int gcol = bn + cl;
            int rl = wm * 32 + mt * 16 + (lane >> 2);
#pragma unroll
            for (int hh = 0; hh < 2; hh++) {
                int grow = bm + rl + hh * 8;
                float v0 = fmaxf(fmaf(c[mt][nt][hh * 2 + 0], s_al[cl],     s_be[cl]),     0.f);
                float v1 = fmaxf(fmaf(c[mt][nt][hh * 2 + 1], s_al[cl + 1], s_be[cl + 1]), 0.f);
                if (L == 1) {
                    ushortT h0, l0, h1, l1;
                    split_hf(v0, h0, l0); split_hf(v1, h1, l1);
                    *(uintT*)&gA2[(size_t)grow * 512 + gcol]       = (uintT)h0 | ((uintT)h1 << 16);
                    *(uintT*)&gA2[(size_t)grow * 512 + 256 + gcol] = (uintT)l0 | ((uintT)l1 << 16);
                } else {
                    float2 o = make_float2(v0, v1);
                    *(float2*)&g_h[(size_t)grow * 256 + gcol] = o;
                }
            }
        }
    }
}

// ---------------- encoding ----------------
__global__ __launch_bounds__(256) void encoding_kernel(const float* __restrict__ cw,
                                                       const float* __restrict__ scale)
{
    __shared__ float cwT[256][32];
    __shared__ float Ash[64][32];
    __shared__ float c2s[32], scs[32];
    int bz = blockIdx.y;
    int n0 = blockIdx.x * 64;
    int t = threadIdx.x, warp = t >> 5, lane = t & 31;
    for (int i = t; i < 32 * 256; i += 256) cwT[i & 255][i >> 8] = cw[i];
    if (t < 32) { c2s[t] = g_c2[t]; scs[t] = scale[t]; }
    __syncthreads();
    const float* Xb = g_h + ((size_t)bz * NQ + n0) * 256;
    for (int pi = 0; pi < 8; pi++) {
        int p = warp * 8 + pi;
        const float* xp = Xb + (size_t)p * 256;
        float xr[8];
#pragma unroll
        for (int j = 0; j < 8; j++) xr[j] = xp[j * 32 + lane];
        float xn2 = 0.f;
#pragma unroll
        for (int j = 0; j < 8; j++) xn2 = fmaf(xr[j], xr[j], xn2);
#pragma unroll
        for (int o = 16; o > 0; o >>= 1) xn2 += __shfl_xor_sync(0xffffffffu, xn2, o);
        float dotv = 0.f;
#pragma unroll
        for (int j = 0; j < 8; j++) {
            float xj = xr[j];
#pragma unroll
            for (int l2 = 0; l2 < 32; l2++) {
                float x = __shfl_sync(0xffffffffu, xj, l2);
                dotv = fmaf(x, cwT[j * 32 + l2][lane], dotv);
            }
        }
        float sl = scs[lane] * (xn2 - 2.f * dotv + c2s[lane]);
        float mx = sl;
#pragma unroll
        for (int o = 16; o > 0; o >>= 1) mx = fmaxf(mx, __shfl_xor_sync(0xffffffffu, mx, o));
        float e = __expf(sl - mx);
        float se = e;
#pragma unroll
        for (int o = 16; o > 0; o >>= 1) se += __shfl_xor_sync(0xffffffffu, se, o);
        Ash[p][lane] = e / se;
    }
    __syncthreads();
    if (t < 32) {
        float s = 0.f;
        for (int p = 0; p < 64; p++) s += Ash[p][t];
        atomicAdd(&g_sumA[bz * 32 + t], s);
    }
    float acc[32];
#pragma unroll
    for (int k = 0; k < 32; k++) acc[k] = 0.f;
    for (int p = 0; p < 64; p++) {
        float x = Xb[(size_t)p * 256 + t];
#pragma unroll
        for (int k = 0; k < 32; k++) acc[k] = fmaf(Ash[p][k], x, acc[k]);
    }
    float* Eb = g_E + (size_t)bz * 8192;
#pragma unroll
    for (int k = 0; k < 32; k++) atomicAdd(&Eb[k * 256 + t], acc[k]);
}

__global__ __launch_bounds__(256) void enc_fin_kernel(const float* __restrict__ cw)
{
    __shared__ float red[256];
    int bz = blockIdx.x, t = threadIdx.x;
    float ss = 0.f;
    for (int j = t; j < 8192; j += 256) {
        float v = g_E[bz * 8192 + j] - g_sumA[bz * 32 + (j >> 8)] * cw[j];
        v = fmaxf(v, 0.f);
        g_En[bz * 8192 + j] = v;
        ss += v * v;
    }
    red[t] = ss;
    __syncthreads();
    for (int s = 128; s > 0; s >>= 1) {
        if (t < s) red[t] += red[t + s];
        __syncthreads();
    }
    float rinv = 1.f / fmaxf(sqrtf(red[0]), 1e-12f);
    for (int j = t; j < 8192; j += 256) g_En[bz * 8192 + j] *= rinv;
}

__global__ __launch_bounds__(256) void ctx_gemv_kernel(const float* __restrict__ lin_w,
                                                       const float* __restrict__ lin_b)
{
    __shared__ float red[8][256];
    int o = blockIdx.x, t = threadIdx.x;
    float acc[8];
#pragma unroll
    for (int b = 0; b < 8; b++) acc[b] = 0.f;
    const float* wrow = lin_w + (size_t)o * 8192;
    for (int j = t; j < 8192; j += 256) {
        float w = wrow[j];
#pragma unroll
        for (int b = 0; b < 8; b++) acc[b] = fmaf(w, g_En[b * 8192 + j], acc[b]);
    }
#pragma unroll
    for (int b = 0; b < 8; b++) red[b][t] = acc[b];
    __syncthreads();
    for (int s = 128; s > 0; s >>= 1) {
        if (t < s) {
#pragma unroll
            for (int b = 0; b < 8; b++) red[b][t] += red[b][t + s];
        }
        __syncthreads();
    }
    if (t < 8) {
        float z = red[t][0] + lin_b[o];
        g_ctx[t * 256 + o] = 1.f / (1.f + expf(-z));
    }
}

__global__ void final_kernel(float* __restrict__ out)
{
    __shared__ float tile[32][33];
    int bz = blockIdx.z;
    int d0 = blockIdx.x * 32, n0 = blockIdx.y * 32;
    int tx = threadIdx.x, ty = threadIdx.y;
    const float* h = g_h + (size_t)bz * NQ * 256;
#pragma unroll
    for (int j = 0; j < 32; j += 8)
        tile[ty + j][tx] = h[(size_t)(n0 + ty + j) * 256 + d0 + tx];
    __syncthreads();
    float* ob = out + (size_t)bz * 256 * NQ;
#pragma unroll
    for (int j = 0; j < 32; j += 8)
        ob[(size_t)(d0 + ty + j) * NQ + n0 + tx] = tile[tx][ty + j] * g_ctx[bz * 256 + d0 + ty + j];
}

// ===================== launcher =====================
extern "C" void kernel_launch(void* const* d_in, const int* in_sizes, int n_in,
                              void* d_out, int out_size)
{
    (void)in_sizes; (void)n_in; (void)out_size;
    const float* unknown      = (const float*)d_in[0];
    const float* known        = (const float*)d_in[1];
    const float* unknow_feats = (const float*)d_in[2];
    const float* known_feats  = (const float*)d_in[3];
    const float* conv_w1 = (const float*)d_in[4];
    const float* conv_b1 = (const float*)d_in[5];
    const float* bn_g1 = (const float*)d_in[6];
    const float* bn_b1 = (const float*)d_in[7];
    const float* bn_m1 = (const float*)d_in[8];
    const float* bn_v1 = (const float*)d_in[9];
    const float* conv_w2 = (const float*)d_in[10];
    const float* conv_b2 = (const float*)d_in[11];
    const float* bn_g2 = (const float*)d_in[12];
    const float* bn_b2 = (const float*)d_in[13];
    const float* bn_m2 = (const float*)d_in[14];
    const float* bn_v2 = (const float*)d_in[15];
    const float* enc_cw    = (const float*)d_in[16];
    const float* enc_scale = (const float*)d_in[17];
    const float* lin_w     = (const float*)d_in[18];
    const float* lin_b     = (const float*)d_in[19];
    float* out = (float*)d_out;

    const int SMEMSZ = 9 * 8192 + 1024;   // 3 stages x (A_H + A_L + B) + alpha/beta
    static int attr_done = 0;
    if (!attr_done) {
        cudaFuncSetAttribute(gemm_mma<1>, cudaFuncAttributeMaxDynamicSharedMemorySize, SMEMSZ);
        cudaFuncSetAttribute(gemm_mma<2>, cudaFuncAttributeMaxDynamicSharedMemorySize, SMEMSZ);
        attr_done = 1;
    }

    front_kernel<<<FR_TOTAL, 256>>>(unknown, known, unknow_feats, known_feats,
                                    conv_w1, conv_w2,
                                    conv_b1, bn_g1, bn_b1, bn_m1, bn_v1,
                                    conv_b2, bn_g2, bn_b2, bn_m2, bn_v2, enc_cw);
    interp_kernel<<<dim3(NQ / 4, B_), 256>>>();
    gemm_mma<1><<<dim3(2, 512), 256, SMEMSZ>>>();
    gemm_mma<2><<<dim3(2, 512), 256, SMEMSZ>>>();
    encoding_kernel<<<dim3(NQ / 64, B_), 256>>>(enc_cw, enc_scale);
    enc_fin_kernel<<<B_, 256>>>(enc_cw);
    ctx_gemv_kernel<<<256, 256>>>(lin_w, lin_b);
    final_kernel<<<dim3(8, NQ / 32, B_), dim3(32, 8)>>>(out);
}

// round 13
// speedup vs baseline: 1.6250x; 1.1122x over previous
#include <cuda_runtime.h>
#include <cuda_fp16.h>
#include <math.h>
#include <stdint.h>

#define B_   8
#define NQ   8192
#define MK   2048
typedef unsigned short ushortT;
typedef unsigned int   uintT;

// ===================== helpers =====================
__device__ __forceinline__ uint32_t smem_to_u32(const void* p) {
    uint32_t a;
    asm("{ .reg .u64 t; cvta.to.shared.u64 t, %1; cvt.u32.u64 %0, t; }" : "=r"(a) : "l"(p));
    return a;
}
#define CP_ASYNC16(s, g) \
    asm volatile("cp.async.cg.shared.global [%0], [%1], 16;" :: "r"(s), "l"(g))
#define CP_COMMIT() asm volatile("cp.async.commit_group;")
#define CP_WAIT1()  asm volatile("cp.async.wait_group 1;")

__device__ __forceinline__ void ldsm4(uint32_t& r0, uint32_t& r1, uint32_t& r2, uint32_t& r3,
                                      uint32_t addr) {
    asm volatile("ldmatrix.sync.aligned.m8n8.x4.shared.b16 {%0,%1,%2,%3}, [%4];"
                 : "=r"(r0), "=r"(r1), "=r"(r2), "=r"(r3) : "r"(addr));
}
__device__ __forceinline__ void mma16816(float* d, const uint32_t* a, const uint32_t* b) {
    asm volatile(
        "mma.sync.aligned.m16n8k16.row.col.f32.f16.f16.f32 "
        "{%0,%1,%2,%3}, {%4,%5,%6,%7}, {%8,%9}, {%0,%1,%2,%3};"
        : "+f"(d[0]), "+f"(d[1]), "+f"(d[2]), "+f"(d[3])
        : "r"(a[0]), "r"(a[1]), "r"(a[2]), "r"(a[3]), "r"(b[0]), "r"(b[1]));
}

// fp32 -> fp16 hi + fp16 lo (RNE)
__device__ __forceinline__ void split_hf(float v, ushortT& h, ushortT& l) {
    __half hh = __float2half_rn(v);
    h = __half_as_ushort(hh);
    __half ll = __float2half_rn(v - __half2float(hh));
    l = __half_as_ushort(ll);
}

__device__ __forceinline__ void ins3(float& d0, int& i0, float& d1, int& i1,
                                     float& d2, int& i2, float dd, int m) {
    if (dd < d2) {
        if (dd < d1) {
            d2 = d1; i2 = i1;
            if (dd < d0) { d1 = d0; i1 = i0; d0 = dd; i0 = m; }
            else          { d1 = dd; i1 = m; }
        } else { d2 = dd; i2 = m; }
    }
}

// ===================== scratch =====================
__device__ ushortT gA1[(size_t)8 * 8192 * 1024];  // fp16 [H(512) | L(512)]
__device__ ushortT gA2[(size_t)8 * 8192 * 512];   // fp16 [H(256) | L(256)]
__device__ ushortT gW1[256 * 512];                // fp16 Wh only
__device__ ushortT gW2[256 * 256];
__device__ float g_h  [(size_t)8 * 8192 * 256];
__device__ float g_kfT[(size_t)8 * 2048 * 256];
__device__ int   g_idx[8 * 8192 * 3];
__device__ float g_wgt[8 * 8192 * 3];
__device__ float g_E  [8 * 8192];
__device__ float g_En [8 * 8192];
__device__ float g_sumA[8 * 32];
__device__ float g_ctx[8 * 256];
__device__ float g_al1[256], g_be1[256], g_al2[256], g_be2[256];
__device__ float g_c2[32];

// ===================== noop (profile-slot shim) =====================
__global__ void noop_kernel() {}

// ===================== fused front kernel =====================
#define FR_TRKF   4096
#define FR_TRUNK  20480
#define FR_3NN    22528
#define FR_EXPW   23040
#define FR_TOTAL  23296
#define CHPAD8    257

__global__ __launch_bounds__(256) void front_kernel(
    const float* __restrict__ unknown, const float* __restrict__ known,
    const float* __restrict__ uf, const float* __restrict__ kf,
    const float* __restrict__ w1, const float* __restrict__ w2,
    const float* __restrict__ cb1, const float* __restrict__ gg1,
    const float* __restrict__ bb1, const float* __restrict__ mm1,
    const float* __restrict__ vv1,
    const float* __restrict__ cb2, const float* __restrict__ gg2,
    const float* __restrict__ bb2, const float* __restrict__ mm2,
    const float* __restrict__ vv2,
    const float* __restrict__ cw)
{
    __shared__ __align__(16) char sbuf[8 * CHPAD8 * 16];
    int bx = blockIdx.x;
    int t  = threadIdx.x;

    if (bx < FR_TRKF) {
        float (*tile)[33] = (float(*)[33])sbuf;
        int m0 = (bx & 63) * 32, c0 = ((bx >> 6) & 7) * 32, b = bx >> 9;
        int tx = t & 31, ty = t >> 5;
        const float* in = kf + (size_t)b * 256 * MK;
#pragma unroll
        for (int j = 0; j < 32; j += 8)
            tile[ty + j][tx] = in[(size_t)(c0 + ty + j) * MK + m0 + tx];
        __syncthreads();
        float* out = g_kfT + (size_t)b * MK * 256;
#pragma unroll
        for (int j = 0; j < 32; j += 8)
            out[(size_t)(m0 + ty + j) * 256 + c0 + tx] = tile[tx][ty + j];
    } else if (bx < FR_TRUNK) {
        float (*tile)[33] = (float(*)[33])sbuf;
        int idx = bx - FR_TRKF;
        int n0 = (idx & 255) * 32, c0 = ((idx >> 8) & 7) * 32, b = idx >> 11;
        int tx = t & 31, ty = t >> 5;
        const float* in = uf + (size_t)b * 256 * NQ;
#pragma unroll
        for (int j = 0; j < 32; j += 8)
            tile[ty + j][tx] = in[(size_t)(c0 + ty + j) * NQ + n0 + tx];
        __syncthreads();
#pragma unroll
        for (int j = 0; j < 32; j += 8) {
            float v = tile[tx][ty + j];
            ushortT h, l; split_hf(v, h, l);
            size_t row = ((size_t)b * NQ + n0 + ty + j) * 1024;
            gA1[row + 256 + c0 + tx] = h;
            gA1[row + 768 + c0 + tx] = l;
        }
    } else if (bx < FR_3NN) {
        float4* kp = (float4*)sbuf;
        int idx = bx - FR_TRUNK;
        int bz = idx >> 8;
        int q  = (idx & 255) * 32 + (t >> 3);
        int ck = t & 7;

        const float* kb = known + (size_t)bz * MK * 3;
        for (int i = t; i < MK; i += 256) {
            float kx = kb[i * 3 + 0];
            float ky = kb[i * 3 + 1];
            float kz = kb[i * 3 + 2];
            kp[(i >> 8) * CHPAD8 + (i & 255)] = make_float4(kx, ky, kz, kx * kx + ky * ky + kz * kz);
        }
        __syncthreads();

        const float* u = unknown + ((size_t)bz * NQ + q) * 3;
        float ux = u[0], uy = u[1], uz = u[2];
        float x2 = ux * ux + uy * uy + uz * uz;
        float mux = -2.f * ux, muy = -2.f * uy, muz = -2.f * uz;

        float d0 = 1e30f, d1 = 1e30f, d2 = 1e30f;
        int   i0 = 0, i1 = 0, i2 = 0;
        const float4* base = kp + ck * CHPAD8;
        int m0 = ck * 256;
#pragma unroll 4
        for (int j = 0; j < 256; j++) {
            float4 p = base[j];
            float dd = fmaf(mux, p.x, p.w);
            dd = fmaf(muy, p.y, dd);
            dd = fmaf(muz, p.z, dd);
            ins3(d0, i0, d1, i1, d2, i2, dd, m0 + j);
        }

#pragma unroll
        for (int off = 1; off <= 4; off <<= 1) {
            float e0 = __shfl_xor_sync(0xffffffffu, d0, off);
            float e1 = __shfl_xor_sync(0xffffffffu, d1, off);
            float e2 = __shfl_xor_sync(0xffffffffu, d2, off);
            int   j0 = __shfl_xor_sync(0xffffffffu, i0, off);
            int   j1 = __shfl_xor_sync(0xffffffffu, i1, off);
            int   j2 = __shfl_xor_sync(0xffffffffu, i2, off);
            ins3(d0, i0, d1, i1, d2, i2, e0, j0);
            ins3(d0, i0, d1, i1, d2, i2, e1, j1);
            ins3(d0, i0, d1, i1, d2, i2, e2, j2);
        }

        if (ck == 0) {
            float r0 = 1.f / (sqrtf(fmaxf(d0 + x2, 1e-12f)) + 1e-8f);
            float r1 = 1.f / (sqrtf(fmaxf(d1 + x2, 1e-12f)) + 1e-8f);
            float r2 = 1.f / (sqrtf(fmaxf(d2 + x2, 1e-12f)) + 1e-8f);
            float rs = 1.f / (r0 + r1 + r2);
            size_t base2 = ((size_t)bz * NQ + q) * 3;
            g_idx[base2 + 0] = i0; g_idx[base2 + 1] = i1; g_idx[base2 + 2] = i2;
            g_wgt[base2 + 0] = r0 * rs; g_wgt[base2 + 1] = r1 * rs; g_wgt[base2 + 2] = r2 * rs;
        }
    } else if (bx < FR_EXPW) {
        int i = (bx - FR_3NN) * 256 + t;
        if (i < 256 * 512) {
            int n = i >> 9, k = i & 511;
            gW1[n * 512 + k] = __half_as_ushort(__float2half_rn(w1[i]));
        }
        if (i < 256 * 256) {
            int n = i >> 8, k = i & 255;
            gW2[n * 256 + k] = __half_as_ushort(__float2half_rn(w2[i]));
        }
    } else {
        int i = (bx - FR_EXPW) * 256 + t;
        if (i < 256) {
            float s1 = gg1[i] * rsqrtf(vv1[i] + 1e-5f);
            g_al1[i] = s1;
            g_be1[i] = s1 * (cb1[i] - mm1[i]) + bb1[i];
            float s2 = gg2[i] * rsqrtf(vv2[i] + 1e-5f);
            g_al2[i] = s2;
            g_be2[i] = s2 * (cb2[i] - mm2[i]) + bb2[i];
        }
        if (i < 32) {
            float s = 0.f;
            const float* c = cw + i * 256;
            for (int d = 0; d < 256; d++) s += c[d] * c[d];
            g_c2[i] = s;
        }
        if (i < 8 * 32) g_sumA[i] = 0.f;
        if (i < 8 * 8192) g_E[i] = 0.f;
    }
}

// ---------------- interpolate: 8 floats/thread (MLP=6) ----------------
__global__ __launch_bounds__(256) void interp_kernel()
{
    int bz = blockIdx.y, t = threadIdx.x;
    int n = blockIdx.x * 8 + (t >> 5);
    int d = (t & 31) * 8;
    size_t base = ((size_t)bz * NQ + n) * 3;
    int i0 = g_idx[base], i1 = g_idx[base + 1], i2 = g_idx[base + 2];
    float w0 = g_wgt[base], w1 = g_wgt[base + 1], w2 = g_wgt[base + 2];
    const float* kf = g_kfT + (size_t)bz * MK * 256;
    const float* r0 = &kf[(size_t)i0 * 256 + d];
    const float* r1 = &kf[(size_t)i1 * 256 + d];
    const float* r2 = &kf[(size_t)i2 * 256 + d];
    float4 a0 = *(const float4*)r0,       a1 = *(const float4*)(r0 + 4);
    float4 b0 = *(const float4*)r1,       b1 = *(const float4*)(r1 + 4);
    float4 c0 = *(const float4*)r2,       c1 = *(const float4*)(r2 + 4);
    float v[8];
    v[0] = w0 * a0.x + w1 * b0.x + w2 * c0.x;
    v[1] = w0 * a0.y + w1 * b0.y + w2 * c0.y;
    v[2] = w0 * a0.z + w1 * b0.z + w2 * c0.z;
    v[3] = w0 * a0.w + w1 * b0.w + w2 * c0.w;
    v[4] = w0 * a1.x + w1 * b1.x + w2 * c1.x;
    v[5] = w0 * a1.y + w1 * b1.y + w2 * c1.y;
    v[6] = w0 * a1.z + w1 * b1.z + w2 * c1.z;
    v[7] = w0 * a1.w + w1 * b1.w + w2 * c1.w;
    uintT hp[4], lp[4];
#pragma unroll
    for (int j = 0; j < 4; j++) {
        ushortT h0, l0, h1, l1;
        split_hf(v[2 * j], h0, l0);
        split_hf(v[2 * j + 1], h1, l1);
        hp[j] = (uintT)h0 | ((uintT)h1 << 16);
        lp[j] = (uintT)l0 | ((uintT)l1 << 16);
    }
    size_t row = ((size_t)bz * NQ + n) * 1024;
    *(uint4*)&gA1[row + d]       = *(uint4*)hp;
    *(uint4*)&gA1[row + 512 + d] = *(uint4*)lp;
}

// ===================== HMMA GEMM: shared-B fp16 split (unchanged from R12) ============
template <int L>
__global__ __launch_bounds__(256) void gemm_mma()
{
    constexpr int K   = (L == 1) ? 512 : 256;
    constexpr int NCH = K / 32;
    constexpr int KA  = 2 * K;
    const ushortT* Ag = (L == 1) ? gA1 : gA2;
    const ushortT* Wg = (L == 1) ? gW1 : gW2;
    const float* alpha = (L == 1) ? g_al1 : g_al2;
    const float* beta  = (L == 1) ? g_be1 : g_be2;

    extern __shared__ __align__(16) ushortT dyn[];
    ushortT* sAH = dyn;
    ushortT* sAL = dyn + 3 * 4096;
    ushortT* sB  = dyn + 6 * 4096;
    float* s_al = (float*)(dyn + 9 * 4096);
    float* s_be = s_al + 128;

    int tid = threadIdx.x, wid = tid >> 5, lane = tid & 31;
    int bn = blockIdx.x * 128, bm = blockIdx.y * 128;
    if (tid < 128) { s_al[tid] = alpha[bn + tid]; s_be[tid] = beta[bn + tid]; }

    uint32_t sAHb = smem_to_u32(sAH);
    uint32_t sALb = smem_to_u32(sAL);
    uint32_t sBb  = smem_to_u32(sB);

    int lr = tid >> 1;
    int ls = (tid & 1) * 2;
    uint32_t off0 = lr * 64 + (((ls)     ^ (lr & 3)) << 4);
    uint32_t off1 = lr * 64 + (((ls + 1) ^ (lr & 3)) << 4);

    const ushortT* ArowH = Ag + (size_t)(bm + lr) * KA;
    const ushortT* ArowL = ArowH + K;
    const ushortT* Wrow  = Wg + (size_t)(bn + lr) * K;

#define LOAD_CHUNK(p, st) do { \
    int _col = (p) * 32; \
    uint32_t _ah = sAHb + (st) * 8192; \
    uint32_t _al = sALb + (st) * 8192; \
    uint32_t _ws = sBb  + (st) * 8192; \
    CP_ASYNC16(_ah + off0, ArowH + _col + ls * 8); \
    CP_ASYNC16(_ah + off1, ArowH + _col + ls * 8 + 8); \
    CP_ASYNC16(_al + off0, ArowL + _col + ls * 8); \
    CP_ASYNC16(_al + off1, ArowL + _col + ls * 8 + 8); \
    CP_ASYNC16(_ws + off0, Wrow + _col + ls * 8); \
    CP_ASYNC16(_ws + off1, Wrow + _col + ls * 8 + 8); \
    CP_COMMIT(); } while (0)

    LOAD_CHUNK(0, 0);
    LOAD_CHUNK(1, 1);

    float c[2][8][4];
#pragma unroll
    for (int i = 0; i < 2; i++)
#pragma unroll
        for (int j = 0; j < 8; j++)
#pragma unroll
            for (int q = 0; q < 4; q++) c[i][j][q] = 0.f;

    int wm = wid & 3, wn = wid >> 2;

    int st = 0, stn = 2;
    for (int kc = 0; kc < NCH; kc++) {
        CP_WAIT1();
        __syncthreads();
        int kn = kc + 2;
        if (kn < NCH) LOAD_CHUNK(kn, stn);
        uint32_t aHBase = sAHb + st * 8192;
        uint32_t aLBase = sALb + st * 8192;
        uint32_t bBase  = sBb  + st * 8192;
#pragma unroll
        for (int kk = 0; kk < 2; kk++) {
            uint32_t ah[2][4], al[2][4], bf[8][2];
#pragma unroll
            for (int mt = 0; mt < 2; mt++) {
                int r = wm * 32 + mt * 16 + (lane & 15);
                int s = kk * 2 + (lane >> 4);
                uint32_t ro = r * 64 + ((s ^ (r & 3)) << 4);
                ldsm4(ah[mt][0], ah[mt][1], ah[mt][2], ah[mt][3], aHBase + ro);
                ldsm4(al[mt][0], al[mt][1], al[mt][2], al[mt][3], aLBase + ro);
            }
#pragma unroll
            for (int np = 0; np < 4; np++) {
                int r = wn * 64 + np * 16 + (lane & 7) + ((lane >> 4) << 3);
                int s = kk * 2 + ((lane >> 3) & 1);
                ldsm4(bf[2 * np][0], bf[2 * np][1], bf[2 * np + 1][0], bf[2 * np + 1][1],
                      bBase + r * 64 + ((s ^ (r & 3)) << 4));
            }
#pragma unroll
            for (int mt = 0; mt < 2; mt++)
#pragma unroll
                for (int nt = 0; nt < 8; nt++)
                    mma16816(c[mt][nt], ah[mt], bf[nt]);
#pragma unroll
            for (int mt = 0; mt < 2; mt++)
#pragma unroll
                for (int nt = 0; nt < 8; nt++)
                    mma16816(c[mt][nt], al[mt], bf[nt]);
        }
        st  = (st == 2)  ? 0 : st + 1;
        stn = (stn == 2) ? 0 : stn + 1;
    }
#undef LOAD_CHUNK

#pragma unroll
    for (int mt = 0; mt < 2; mt++) {
#pragma unroll
        for (int nt = 0; nt < 8; nt++) {
            int cl = wn * 64 + nt * 8 + (lane & 3) * 2;
            int gcol = bn + cl;
            int rl = wm * 32 + mt * 16 + (lane >> 2);
#pragma unroll
            for (int hh = 0; hh < 2; hh++) {
                int grow = bm + rl + hh * 8;
                float v0 = fmaxf(fmaf(c[mt][nt][hh * 2 + 0], s_al[cl],     s_be[cl]),     0.f);
                float v1 = fmaxf(fmaf(c[mt][nt][hh * 2 + 1], s_al[cl + 1], s_be[cl + 1]), 0.f);
                if (L == 1) {
                    ushortT h0, l0, h1, l1;
                    split_hf(v0, h0, l0); split_hf(v1, h1, l1);
                    *(uintT*)&gA2[(size_t)grow * 512 + gcol]       = (uintT)h0 | ((uintT)h1 << 16);
                    *(uintT*)&gA2[(size_t)grow * 512 + 256 + gcol] = (uintT)l0 | ((uintT)l1 << 16);
                } else {
                    float2 o = make_float2(v0, v1);
                    *(float2*)&g_h[(size_t)grow * 256 + gcol] = o;
                }
            }
        }
    }
}

// ===================== encoding: register-tiled dots + fused softmax + aggregation ====
#define XSTR  260
#define CWSTR 36
#define ASTR  36
#define ENC_SMEM ((64 * XSTR + 256 * CWSTR + 64 * ASTR + 64) * 4)

__global__ __launch_bounds__(256) void encoding_kernel(const float* __restrict__ cw,
                                                       const float* __restrict__ scale)
{
    extern __shared__ float es[];
    float* sX  = es;                        // [64][260]
    float* cwT = es + 64 * XSTR;            // [256][36]
    float* sA  = cwT + 256 * CWSTR;         // [64][36]
    float* sXn = sA + 64 * ASTR;            // [64]

    int bz = blockIdx.y, n0 = blockIdx.x * 64, t = threadIdx.x;
    const float* Xb = g_h + ((size_t)bz * NQ + n0) * 256;

    for (int i = t; i < 64 * 64; i += 256) {
        int p = i >> 6, d4 = i & 63;
        *(float4*)&sX[p * XSTR + d4 * 4] = *(const float4*)&Xb[(size_t)p * 256 + d4 * 4];
    }
    for (int i = t; i < 32 * 256; i += 256) {
        int k = i >> 8, d = i & 255;
        cwT[d * CWSTR + k] = cw[i];
    }
    __syncthreads();

    // dots: thread = (pg [32] x kg [8]); 2 points x 4 codewords per thread
    {
        int pg = t >> 3, kg = t & 7;
        const float* xr0 = sX + (2 * pg) * XSTR;
        const float* xr1 = xr0 + XSTR;
        const float* cwr = cwT + kg * 4;
        float a0[4] = {0.f, 0.f, 0.f, 0.f}, a1[4] = {0.f, 0.f, 0.f, 0.f};
        float xn0 = 0.f, xn1 = 0.f;
#pragma unroll 4
        for (int d = 0; d < 256; d += 4) {
            float4 x0 = *(const float4*)&xr0[d];
            float4 x1 = *(const float4*)&xr1[d];
            xn0 = fmaf(x0.x, x0.x, xn0); xn0 = fmaf(x0.y, x0.y, xn0);
            xn0 = fmaf(x0.z, x0.z, xn0); xn0 = fmaf(x0.w, x0.w, xn0);
            xn1 = fmaf(x1.x, x1.x, xn1); xn1 = fmaf(x1.y, x1.y, xn1);
            xn1 = fmaf(x1.z, x1.z, xn1); xn1 = fmaf(x1.w, x1.w, xn1);
            float xv0[4] = {x0.x, x0.y, x0.z, x0.w};
            float xv1[4] = {x1.x, x1.y, x1.z, x1.w};
#pragma unroll
            for (int dd = 0; dd < 4; dd++) {
                float4 c4 = *(const float4*)&cwr[(d + dd) * CWSTR];
                a0[0] = fmaf(xv0[dd], c4.x, a0[0]);
                a0[1] = fmaf(xv0[dd], c4.y, a0[1]);
                a0[2] = fmaf(xv0[dd], c4.z, a0[2]);
                a0[3] = fmaf(xv0[dd], c4.w, a0[3]);
                a1[0] = fmaf(xv1[dd], c4.x, a1[0]);
                a1[1] = fmaf(xv1[dd], c4.y, a1[1]);
                a1[2] = fmaf(xv1[dd], c4.z, a1[2]);
                a1[3] = fmaf(xv1[dd], c4.w, a1[3]);
            }
        }
        int p0 = 2 * pg, ks = kg * 4;
#pragma unroll
        for (int j = 0; j < 4; j++) {
            sA[p0 * ASTR + ks + j]       = a0[j];
            sA[(p0 + 1) * ASTR + ks + j] = a1[j];
        }
        if (kg == 0) { sXn[p0] = xn0; sXn[p0 + 1] = xn1; }
    }
    __syncthreads();

    // softmax: warp per 8 points, lane = codeword
    {
        int warp = t >> 5, lane = t & 31;
        float sc = scale[lane], c2v = g_c2[lane];
        for (int pi = 0; pi < 8; pi++) {
            int p = warp * 8 + pi;
            float sl = sc * (sXn[p] - 2.f * sA[p * ASTR + lane] + c2v);
            float mx = sl;
#pragma unroll
            for (int o = 16; o > 0; o >>= 1) mx = fmaxf(mx, __shfl_xor_sync(0xffffffffu, mx, o));
            float e = __expf(sl - mx);
            float se = e;
#pragma unroll
            for (int o = 16; o > 0; o >>= 1) se += __shfl_xor_sync(0xffffffffu, se, o);
            sA[p * ASTR + lane] = e / se;
        }
    }
    __syncthreads();
    if (t < 32) {
        float s = 0.f;
        for (int p = 0; p < 64; p++) s += sA[p * ASTR + t];
        atomicAdd(&g_sumA[bz * 32 + t], s);
    }

    // aggregation: d = t, acc over 64 points
    float acc[32];
#pragma unroll
    for (int k = 0; k < 32; k++) acc[k] = 0.f;
    for (int p = 0; p < 64; p++) {
        float x = sX[p * XSTR + t];
#pragma unroll
        for (int kq = 0; kq < 8; kq++) {
            float4 a4 = *(const float4*)&sA[p * ASTR + kq * 4];
            acc[kq * 4 + 0] = fmaf(a4.x, x, acc[kq * 4 + 0]);
            acc[kq * 4 + 1] = fmaf(a4.y, x, acc[kq * 4 + 1]);
            acc[kq * 4 + 2] = fmaf(a4.z, x, acc[kq * 4 + 2]);
            acc[kq * 4 + 3] = fmaf(a4.w, x, acc[kq * 4 + 3]);
        }
    }
    float* Eb = g_E + (size_t)bz * 8192;
#pragma unroll
    for (int k = 0; k < 32; k++) atomicAdd(&Eb[k * 256 + t], acc[k]);
}

__global__ __launch_bounds__(256) void enc_fin_kernel(const float* __restrict__ cw)
{
    __shared__ float red[256];
    int bz = blockIdx.x, t = threadIdx.x;
    float ss = 0.f;
    for (int j = t; j < 8192; j += 256) {
        float v = g_E[bz * 8192 + j] - g_sumA[bz * 32 + (j >> 8)] * cw[j];
        v = fmaxf(v, 0.f);
        g_En[bz * 8192 + j] = v;
        ss += v * v;
    }
    red[t] = ss;
    __syncthreads();
    for (int s = 128; s > 0; s >>= 1) {
        if (t < s) red[t] += red[t + s];
        __syncthreads();
    }
    float rinv = 1.f / fmaxf(sqrtf(red[0]), 1e-12f);
    for (int j = t; j < 8192; j += 256) g_En[bz * 8192 + j] *= rinv;
}

__global__ __launch_bounds__(256) void ctx_gemv_kernel(const float* __restrict__ lin_w,
                                                       const float* __restrict__ lin_b)
{
    __shared__ float red[8][256];
    int o = blockIdx.x, t = threadIdx.x;
    float acc[8];
#pragma unroll
    for (int b = 0; b < 8; b++) acc[b] = 0.f;
    const float* wrow = lin_w + (size_t)o * 8192;
    for (int j = t; j < 8192; j += 256) {
        float w = wrow[j];
#pragma unroll
        for (int b = 0; b < 8; b++) acc[b] = fmaf(w, g_En[b * 8192 + j], acc[b]);
    }
#pragma unroll
    for (int b = 0; b < 8; b++) red[b][t] = acc[b];
    __syncthreads();
    for (int s = 128; s > 0; s >>= 1) {
        if (t < s) {
#pragma unroll
            for (int b = 0; b < 8; b++) red[b][t] += red[b][t + s];
        }
        __syncthreads();
    }
    if (t < 8) {
        float z = red[t][0] + lin_b[o];
        g_ctx[t * 256 + o] = 1.f / (1.f + expf(-z));
    }
}

__global__ void final_kernel(float* __restrict__ out)
{
    __shared__ float tile[32][33];
    int bz = blockIdx.z;
    int d0 = blockIdx.x * 32, n0 = blockIdx.y * 32;
    int tx = threadIdx.x, ty = threadIdx.y;
    const float* h = g_h + (size_t)bz * NQ * 256;
#pragma unroll
    for (int j = 0; j < 32; j += 8)
        tile[ty + j][tx] = h[(size_t)(n0 + ty + j) * 256 + d0 + tx];
    __syncthreads();
    float* ob = out + (size_t)bz * 256 * NQ;
#pragma unroll
    for (int j = 0; j < 32; j += 8)
        ob[(size_t)(d0 + ty + j) * NQ + n0 + tx] = tile[tx][ty + j] * g_ctx[bz * 256 + d0 + ty + j];
}

// ===================== launcher =====================
extern "C" void kernel_launch(void* const* d_in, const int* in_sizes, int n_in,
                              void* d_out, int out_size)
{
    (void)in_sizes; (void)n_in; (void)out_size;
    const float* unknown      = (const float*)d_in[0];
    const float* known        = (const float*)d_in[1];
    const float* unknow_feats = (const float*)d_in[2];
    const float* known_feats  = (const float*)d_in[3];
    const float* conv_w1 = (const float*)d_in[4];
    const float* conv_b1 = (const float*)d_in[5];
    const float* bn_g1 = (const float*)d_in[6];
    const float* bn_b1 = (const float*)d_in[7];
    const float* bn_m1 = (const float*)d_in[8];
    const float* bn_v1 = (const float*)d_in[9];
    const float* conv_w2 = (const float*)d_in[10];
    const float* conv_b2 = (const float*)d_in[11];
    const float* bn_g2 = (const float*)d_in[12];
    const float* bn_b2 = (const float*)d_in[13];
    const float* bn_m2 = (const float*)d_in[14];
    const float* bn_v2 = (const float*)d_in[15];
    const float* enc_cw    = (const float*)d_in[16];
    const float* enc_scale = (const float*)d_in[17];
    const float* lin_w     = (const float*)d_in[18];
    const float* lin_b     = (const float*)d_in[19];
    float* out = (float*)d_out;

    const int SMEMSZ = 9 * 8192 + 1024;
    static int attr_done = 0;
    if (!attr_done) {
        cudaFuncSetAttribute(gemm_mma<1>, cudaFuncAttributeMaxDynamicSharedMemorySize, SMEMSZ);
        cudaFuncSetAttribute(gemm_mma<2>, cudaFuncAttributeMaxDynamicSharedMemorySize, SMEMSZ);
        cudaFuncSetAttribute(encoding_kernel, cudaFuncAttributeMaxDynamicSharedMemorySize, ENC_SMEM);
        attr_done = 1;
    }

    noop_kernel<<<1, 32>>>();
    front_kernel<<<FR_TOTAL, 256>>>(unknown, known, unknow_feats, known_feats,
                                    conv_w1, conv_w2,
                                    conv_b1, bn_g1, bn_b1, bn_m1, bn_v1,
                                    conv_b2, bn_g2, bn_b2, bn_m2, bn_v2, enc_cw);
    interp_kernel<<<dim3(NQ / 8, B_), 256>>>();
    gemm_mma<1><<<dim3(2, 512), 256, SMEMSZ>>>();
    gemm_mma<2><<<dim3(2, 512), 256, SMEMSZ>>>();
    encoding_kernel<<<dim3(NQ / 64, B_), 256, ENC_SMEM>>>(enc_cw, enc_scale);
    enc_fin_kernel<<<B_, 256>>>(enc_cw);
    ctx_gemv_kernel<<<256, 256>>>(lin_w, lin_b);
    final_kernel<<<dim3(8, NQ / 32, B_), dim3(32, 8)>>>(out);
}

// round 14
// speedup vs baseline: 1.6664x; 1.0255x over previous
#include <cuda_runtime.h>
#include <cuda_fp16.h>
#include <math.h>
#include <stdint.h>

#define B_   8
#define NQ   8192
#define MK   2048
typedef unsigned short ushortT;
typedef unsigned int   uintT;

// ===================== helpers =====================
__device__ __forceinline__ uint32_t smem_to_u32(const void* p) {
    uint32_t a;
    asm("{ .reg .u64 t; cvta.to.shared.u64 t, %1; cvt.u32.u64 %0, t; }" : "=r"(a) : "l"(p));
    return a;
}
#define CP_ASYNC16(s, g) \
    asm volatile("cp.async.cg.shared.global [%0], [%1], 16;" :: "r"(s), "l"(g))
#define CP_COMMIT() asm volatile("cp.async.commit_group;")
#define CP_WAIT1()  asm volatile("cp.async.wait_group 1;")

__device__ __forceinline__ void ldsm4(uint32_t& r0, uint32_t& r1, uint32_t& r2, uint32_t& r3,
                                      uint32_t addr) {
    asm volatile("ldmatrix.sync.aligned.m8n8.x4.shared.b16 {%0,%1,%2,%3}, [%4];"
                 : "=r"(r0), "=r"(r1), "=r"(r2), "=r"(r3) : "r"(addr));
}
__device__ __forceinline__ void mma16816(float* d, const uint32_t* a, const uint32_t* b) {
    asm volatile(
        "mma.sync.aligned.m16n8k16.row.col.f32.f16.f16.f32 "
        "{%0,%1,%2,%3}, {%4,%5,%6,%7}, {%8,%9}, {%0,%1,%2,%3};"
        : "+f"(d[0]), "+f"(d[1]), "+f"(d[2]), "+f"(d[3])
        : "r"(a[0]), "r"(a[1]), "r"(a[2]), "r"(a[3]), "r"(b[0]), "r"(b[1]));
}

// fp32 -> fp16 hi + fp16 lo (RNE)
__device__ __forceinline__ void split_hf(float v, ushortT& h, ushortT& l) {
    __half hh = __float2half_rn(v);
    h = __half_as_ushort(hh);
    __half ll = __float2half_rn(v - __half2float(hh));
    l = __half_as_ushort(ll);
}

__device__ __forceinline__ void ins3(float& d0, int& i0, float& d1, int& i1,
                                     float& d2, int& i2, float dd, int m) {
    if (dd < d2) {
        if (dd < d1) {
            d2 = d1; i2 = i1;
            if (dd < d0) { d1 = d0; i1 = i0; d0 = dd; i0 = m; }
            else          { d1 = dd; i1 = m; }
        } else { d2 = dd; i2 = m; }
    }
}

// ===================== scratch =====================
__device__ ushortT gA1[(size_t)8 * 8192 * 1024];  // fp16 [H(512) | L(512)]
__device__ ushortT gA2[(size_t)8 * 8192 * 512];   // fp16 [H(256) | L(256)]
__device__ ushortT gW1[256 * 512];                // fp16 Wh only
__device__ ushortT gW2[256 * 256];
__device__ float g_h  [(size_t)8 * 8192 * 256];
__device__ float g_kfT[(size_t)8 * 2048 * 256];
__device__ int   g_idx[8 * 8192 * 3];
__device__ float g_wgt[8 * 8192 * 3];
__device__ float g_E  [8 * 8192];
__device__ float g_En [8 * 8192];
__device__ float g_sumA[8 * 32];
__device__ float g_ctx[8 * 256];
__device__ float g_al1[256], g_be1[256], g_al2[256], g_be2[256];
__device__ float g_c2[32];

// ===================== noop (profile-slot shim) =====================
__global__ void noop_kernel() {}

// ===================== fused front kernel =====================
#define FR_TRKF   4096
#define FR_TRUNK  20480
#define FR_3NN    22528
#define FR_EXPW   23040
#define FR_TOTAL  23296
#define CHPAD8    257

__global__ __launch_bounds__(256) void front_kernel(
    const float* __restrict__ unknown, const float* __restrict__ known,
    const float* __restrict__ uf, const float* __restrict__ kf,
    const float* __restrict__ w1, const float* __restrict__ w2,
    const float* __restrict__ cb1, const float* __restrict__ gg1,
    const float* __restrict__ bb1, const float* __restrict__ mm1,
    const float* __restrict__ vv1,
    const float* __restrict__ cb2, const float* __restrict__ gg2,
    const float* __restrict__ bb2, const float* __restrict__ mm2,
    const float* __restrict__ vv2,
    const float* __restrict__ cw)
{
    __shared__ __align__(16) char sbuf[8 * CHPAD8 * 16];
    int bx = blockIdx.x;
    int t  = threadIdx.x;

    if (bx < FR_TRKF) {
        // ---- transpose known_feats (B,256,2048) -> g_kfT (B,2048,256), float4 ----
        float (*tile)[33] = (float(*)[33])sbuf;
        int m0 = (bx & 63) * 32, c0 = ((bx >> 6) & 7) * 32, b = bx >> 9;
        int cr = t >> 3, q4 = (t & 7) * 4;
        const float* in = kf + (size_t)b * 256 * MK;
        float4 v = *(const float4*)&in[(size_t)(c0 + cr) * MK + m0 + q4];
        tile[cr][q4 + 0] = v.x; tile[cr][q4 + 1] = v.y;
        tile[cr][q4 + 2] = v.z; tile[cr][q4 + 3] = v.w;
        __syncthreads();
        float* out = g_kfT + (size_t)b * MK * 256;
        float4 w = make_float4(tile[q4 + 0][cr], tile[q4 + 1][cr],
                               tile[q4 + 2][cr], tile[q4 + 3][cr]);
        *(float4*)&out[(size_t)(m0 + cr) * 256 + c0 + q4] = w;
    } else if (bx < FR_TRUNK) {
        // ---- transpose unknow_feats -> gA1 cols [256,512) H, [768,1024) L, float4 ----
        float (*tile)[33] = (float(*)[33])sbuf;
        int idx = bx - FR_TRKF;
        int n0 = (idx & 255) * 32, c0 = ((idx >> 8) & 7) * 32, b = idx >> 11;
        int cr = t >> 3, q4 = (t & 7) * 4;
        const float* in = uf + (size_t)b * 256 * NQ;
        float4 v = *(const float4*)&in[(size_t)(c0 + cr) * NQ + n0 + q4];
        tile[cr][q4 + 0] = v.x; tile[cr][q4 + 1] = v.y;
        tile[cr][q4 + 2] = v.z; tile[cr][q4 + 3] = v.w;
        __syncthreads();
        ushortT h0, l0, h1, l1, h2, l2, h3, l3;
        split_hf(tile[q4 + 0][cr], h0, l0);
        split_hf(tile[q4 + 1][cr], h1, l1);
        split_hf(tile[q4 + 2][cr], h2, l2);
        split_hf(tile[q4 + 3][cr], h3, l3);
        uint2 hp = make_uint2((uintT)h0 | ((uintT)h1 << 16), (uintT)h2 | ((uintT)h3 << 16));
        uint2 lp = make_uint2((uintT)l0 | ((uintT)l1 << 16), (uintT)l2 | ((uintT)l3 << 16));
        size_t row = ((size_t)b * NQ + n0 + cr) * 1024;
        *(uint2*)&gA1[row + 256 + c0 + q4] = hp;
        *(uint2*)&gA1[row + 768 + c0 + q4] = lp;
    } else if (bx < FR_3NN) {
        float4* kp = (float4*)sbuf;
        int idx = bx - FR_TRUNK;
        int bz = idx >> 8;
        int q  = (idx & 255) * 32 + (t >> 3);
        int ck = t & 7;

        const float* kb = known + (size_t)bz * MK * 3;
        for (int i = t; i < MK; i += 256) {
            float kx = kb[i * 3 + 0];
            float ky = kb[i * 3 + 1];
            float kz = kb[i * 3 + 2];
            kp[(i >> 8) * CHPAD8 + (i & 255)] = make_float4(kx, ky, kz, kx * kx + ky * ky + kz * kz);
        }
        __syncthreads();

        const float* u = unknown + ((size_t)bz * NQ + q) * 3;
        float ux = u[0], uy = u[1], uz = u[2];
        float x2 = ux * ux + uy * uy + uz * uz;
        float mux = -2.f * ux, muy = -2.f * uy, muz = -2.f * uz;

        float d0 = 1e30f, d1 = 1e30f, d2 = 1e30f;
        int   i0 = 0, i1 = 0, i2 = 0;
        const float4* base = kp + ck * CHPAD8;
        int m0 = ck * 256;
#pragma unroll 4
        for (int j = 0; j < 256; j++) {
            float4 p = base[j];
            float dd = fmaf(mux, p.x, p.w);
            dd = fmaf(muy, p.y, dd);
            dd = fmaf(muz, p.z, dd);
            ins3(d0, i0, d1, i1, d2, i2, dd, m0 + j);
        }

#pragma unroll
        for (int off = 1; off <= 4; off <<= 1) {
            float e0 = __shfl_xor_sync(0xffffffffu, d0, off);
            float e1 = __shfl_xor_sync(0xffffffffu, d1, off);
            float e2 = __shfl_xor_sync(0xffffffffu, d2, off);
            int   j0 = __shfl_xor_sync(0xffffffffu, i0, off);
            int   j1 = __shfl_xor_sync(0xffffffffu, i1, off);
            int   j2 = __shfl_xor_sync(0xffffffffu, i2, off);
            ins3(d0, i0, d1, i1, d2, i2, e0, j0);
            ins3(d0, i0, d1, i1, d2, i2, e1, j1);
            ins3(d0, i0, d1, i1, d2, i2, e2, j2);
        }

        if (ck == 0) {
            float r0 = 1.f / (sqrtf(fmaxf(d0 + x2, 1e-12f)) + 1e-8f);
            float r1 = 1.f / (sqrtf(fmaxf(d1 + x2, 1e-12f)) + 1e-8f);
            float r2 = 1.f / (sqrtf(fmaxf(d2 + x2, 1e-12f)) + 1e-8f);
            float rs = 1.f / (r0 + r1 + r2);
            size_t base2 = ((size_t)bz * NQ + q) * 3;
            g_idx[base2 + 0] = i0; g_idx[base2 + 1] = i1; g_idx[base2 + 2] = i2;
            g_wgt[base2 + 0] = r0 * rs; g_wgt[base2 + 1] = r1 * rs; g_wgt[base2 + 2] = r2 * rs;
        }
    } else if (bx < FR_EXPW) {
        int i = (bx - FR_3NN) * 256 + t;
        if (i < 256 * 512) {
            int n = i >> 9, k = i & 511;
            gW1[n * 512 + k] = __half_as_ushort(__float2half_rn(w1[i]));
        }
        if (i < 256 * 256) {
            int n = i >> 8, k = i & 255;
            gW2[n * 256 + k] = __half_as_ushort(__float2half_rn(w2[i]));
        }
    } else {
        int i = (bx - FR_EXPW) * 256 + t;
        if (i < 256) {
            float s1 = gg1[i] * rsqrtf(vv1[i] + 1e-5f);
            g_al1[i] = s1;
            g_be1[i] = s1 * (cb1[i] - mm1[i]) + bb1[i];
            float s2 = gg2[i] * rsqrtf(vv2[i] + 1e-5f);
            g_al2[i] = s2;
            g_be2[i] = s2 * (cb2[i] - mm2[i]) + bb2[i];
        }
        if (i < 32) {
            float s = 0.f;
            const float* c = cw + i * 256;
            for (int d = 0; d < 256; d++) s += c[d] * c[d];
            g_c2[i] = s;
        }
        if (i < 8 * 32) g_sumA[i] = 0.f;
        if (i < 8 * 8192) g_E[i] = 0.f;
    }
}

// ---------------- interpolate: 8 floats/thread (MLP=6) ----------------
__global__ __launch_bounds__(256) void interp_kernel()
{
    int bz = blockIdx.y, t = threadIdx.x;
    int n = blockIdx.x * 8 + (t >> 5);
    int d = (t & 31) * 8;
    size_t base = ((size_t)bz * NQ + n) * 3;
    int i0 = g_idx[base], i1 = g_idx[base + 1], i2 = g_idx[base + 2];
    float w0 = g_wgt[base], w1 = g_wgt[base + 1], w2 = g_wgt[base + 2];
    const float* kf = g_kfT + (size_t)bz * MK * 256;
    const float* r0 = &kf[(size_t)i0 * 256 + d];
    const float* r1 = &kf[(size_t)i1 * 256 + d];
    const float* r2 = &kf[(size_t)i2 * 256 + d];
    float4 a0 = *(const float4*)r0,       a1 = *(const float4*)(r0 + 4);
    float4 b0 = *(const float4*)r1,       b1 = *(const float4*)(r1 + 4);
    float4 c0 = *(const float4*)r2,       c1 = *(const float4*)(r2 + 4);
    float v[8];
    v[0] = w0 * a0.x + w1 * b0.x + w2 * c0.x;
    v[1] = w0 * a0.y + w1 * b0.y + w2 * c0.y;
    v[2] = w0 * a0.z + w1 * b0.z + w2 * c0.z;
    v[3] = w0 * a0.w + w1 * b0.w + w2 * c0.w;
    v[4] = w0 * a1.x + w1 * b1.x + w2 * c1.x;
    v[5] = w0 * a1.y + w1 * b1.y + w2 * c1.y;
    v[6] = w0 * a1.z + w1 * b1.z + w2 * c1.z;
    v[7] = w0 * a1.w + w1 * b1.w + w2 * c1.w;
    uintT hp[4], lp[4];
#pragma unroll
    for (int j = 0; j < 4; j++) {
        ushortT h0, l0, h1, l1;
        split_hf(v[2 * j], h0, l0);
        split_hf(v[2 * j + 1], h1, l1);
        hp[j] = (uintT)h0 | ((uintT)h1 << 16);
        lp[j] = (uintT)l0 | ((uintT)l1 << 16);
    }
    size_t row = ((size_t)bz * NQ + n) * 1024;
    *(uint4*)&gA1[row + d]       = *(uint4*)hp;
    *(uint4*)&gA1[row + 512 + d] = *(uint4*)lp;
}

// ===================== HMMA GEMM: shared-B fp16 split =====================
template <int L>
__global__ __launch_bounds__(256) void gemm_mma()
{
    constexpr int K   = (L == 1) ? 512 : 256;
    constexpr int NCH = K / 32;
    constexpr int KA  = 2 * K;
    const ushortT* Ag = (L == 1) ? gA1 : gA2;
    const ushortT* Wg = (L == 1) ? gW1 : gW2;
    const float* alpha = (L == 1) ? g_al1 : g_al2;
    const float* beta  = (L == 1) ? g_be1 : g_be2;

    extern __shared__ __align__(16) ushortT dyn[];
    ushortT* sAH = dyn;
    ushortT* sAL = dyn + 3 * 4096;
    ushortT* sB  = dyn + 6 * 4096;
    float* s_al = (float*)(dyn + 9 * 4096);
    float* s_be = s_al + 128;

    int tid = threadIdx.x, wid = tid >> 5, lane = tid & 31;
    int bn = blockIdx.x * 128, bm = blockIdx.y * 128;
    if (tid < 128) { s_al[tid] = alpha[bn + tid]; s_be[tid] = beta[bn + tid]; }

    uint32_t sAHb = smem_to_u32(sAH);
    uint32_t sALb = smem_to_u32(sAL);
    uint32_t sBb  = smem_to_u32(sB);

    int lr = tid >> 1;
    int ls = (tid & 1) * 2;
    uint32_t off0 = lr * 64 + (((ls)     ^ (lr & 3)) << 4);
    uint32_t off1 = lr * 64 + (((ls + 1) ^ (lr & 3)) << 4);

    const ushortT* ArowH = Ag + (size_t)(bm + lr) * KA;
    const ushortT* ArowL = ArowH + K;
    const ushortT* Wrow  = Wg + (size_t)(bn + lr) * K;

#define LOAD_CHUNK(p, st) do { \
    int _col = (p) * 32; \
    uint32_t _ah = sAHb + (st) * 8192; \
    uint32_t _al = sALb + (st) * 8192; \
    uint32_t _ws = sBb  + (st) * 8192; \
    CP_ASYNC16(_ah + off0, ArowH + _col + ls * 8); \
    CP_ASYNC16(_ah + off1, ArowH + _col + ls * 8 + 8); \
    CP_ASYNC16(_al + off0, ArowL + _col + ls * 8); \
    CP_ASYNC16(_al + off1, ArowL + _col + ls * 8 + 8); \
    CP_ASYNC16(_ws + off0, Wrow + _col + ls * 8); \
    CP_ASYNC16(_ws + off1, Wrow + _col + ls * 8 + 8); \
    CP_COMMIT(); } while (0)

    LOAD_CHUNK(0, 0);
    LOAD_CHUNK(1, 1);

    float c[2][8][4];
#pragma unroll
    for (int i = 0; i < 2; i++)
#pragma unroll
        for (int j = 0; j < 8; j++)
#pragma unroll
            for (int q = 0; q < 4; q++) c[i][j][q] = 0.f;

    int wm = wid & 3, wn = wid >> 2;

    int st = 0, stn = 2;
    for (int kc = 0; kc < NCH; kc++) {
        CP_WAIT1();
        __syncthreads();
        int kn = kc + 2;
        if (kn < NCH) LOAD_CHUNK(kn, stn);
        uint32_t aHBase = sAHb + st * 8192;
        uint32_t aLBase = sALb + st * 8192;
        uint32_t bBase  = sBb  + st * 8192;
#pragma unroll
        for (int kk = 0; kk < 2; kk++) {
            uint32_t ah[2][4], al[2][4], bf[8][2];
#pragma unroll
            for (int mt = 0; mt < 2; mt++) {
                int r = wm * 32 + mt * 16 + (lane & 15);
                int s = kk * 2 + (lane >> 4);
                uint32_t ro = r * 64 + ((s ^ (r & 3)) << 4);
                ldsm4(ah[mt][0], ah[mt][1], ah[mt][2], ah[mt][3], aHBase + ro);
                ldsm4(al[mt][0], al[mt][1], al[mt][2], al[mt][3], aLBase + ro);
            }
#pragma unroll
            for (int np = 0; np < 4; np++) {
                int r = wn * 64 + np * 16 + (lane & 7) + ((lane >> 4) << 3);
                int s = kk * 2 + ((lane >> 3) & 1);
                ldsm4(bf[2 * np][0], bf[2 * np][1], bf[2 * np + 1][0], bf[2 * np + 1][1],
                      bBase + r * 64 + ((s ^ (r & 3)) << 4));
            }
#pragma unroll
            for (int mt = 0; mt < 2; mt++)
#pragma unroll
                for (int nt = 0; nt < 8; nt++)
                    mma16816(c[mt][nt], ah[mt], bf[nt]);
#pragma unroll
            for (int mt = 0; mt < 2; mt++)
#pragma unroll
                for (int nt = 0; nt < 8; nt++)
                    mma16816(c[mt][nt], al[mt], bf[nt]);
        }
        st  = (st == 2)  ? 0 : st + 1;
        stn = (stn == 2) ? 0 : stn + 1;
    }
#undef LOAD_CHUNK

#pragma unroll
    for (int mt = 0; mt < 2; mt++) {
#pragma unroll
        for (int nt = 0; nt < 8; nt++) {
            int cl = wn * 64 + nt * 8 + (lane & 3) * 2;
            int gcol = bn + cl;
            int rl = wm * 32 + mt * 16 + (lane >> 2);
#pragma unroll
            for (int hh = 0; hh < 2; hh++) {
                int grow = bm + rl + hh * 8;
                float v0 = fmaxf(fmaf(c[mt][nt][hh * 2 + 0], s_al[cl],     s_be[cl]),     0.f);
                float v1 = fmaxf(fmaf(c[mt][nt][hh * 2 + 1], s_al[cl + 1], s_be[cl + 1]), 0.f);
                if (L == 1) {
                    ushortT h0, l0, h1, l1;
                    split_hf(v0, h0, l0); split_hf(v1, h1, l1);
                    *(uintT*)&gA2[(size_t)grow * 512 + gcol]       = (uintT)h0 | ((uintT)h1 << 16);
                    *(uintT*)&gA2[(size_t)grow * 512 + 256 + gcol] = (uintT)l0 | ((uintT)l1 << 16);
                } else {
                    float2 o = make_float2(v0, v1);
                    *(float2*)&g_h[(size_t)grow * 256 + gcol] = o;
                }
            }
        }
    }
}

// ===================== encoding: register-tiled dots + fused softmax + aggregation ====
#define XSTR  260
#define CWSTR 36
#define ASTR  36
#define ENC_SMEM ((64 * XSTR + 256 * CWSTR + 64 * ASTR + 64) * 4)

__global__ __launch_bounds__(256) void encoding_kernel(const float* __restrict__ cw,
                                                       const float* __restrict__ scale)
{
    extern __shared__ float es[];
    float* sX  = es;
    float* cwT = es + 64 * XSTR;
    float* sA  = cwT + 256 * CWSTR;
    float* sXn = sA + 64 * ASTR;

    int bz = blockIdx.y, n0 = blockIdx.x * 64, t = threadIdx.x;
    const float* Xb = g_h + ((size_t)bz * NQ + n0) * 256;

    for (int i = t; i < 64 * 64; i += 256) {
        int p = i >> 6, d4 = i & 63;
        *(float4*)&sX[p * XSTR + d4 * 4] = *(const float4*)&Xb[(size_t)p * 256 + d4 * 4];
    }
    for (int i = t; i < 32 * 256; i += 256) {
        int k = i >> 8, d = i & 255;
        cwT[d * CWSTR + k] = cw[i];
    }
    __syncthreads();

    {
        int pg = t >> 3, kg = t & 7;
        const float* xr0 = sX + (2 * pg) * XSTR;
        const float* xr1 = xr0 + XSTR;
        const float* cwr = cwT + kg * 4;
        float a0[4] = {0.f, 0.f, 0.f, 0.f}, a1[4] = {0.f, 0.f, 0.f, 0.f};
        float xn0 = 0.f, xn1 = 0.f;
#pragma unroll 4
        for (int d = 0; d < 256; d += 4) {
            float4 x0 = *(const float4*)&xr0[d];
            float4 x1 = *(const float4*)&xr1[d];
            xn0 = fmaf(x0.x, x0.x, xn0); xn0 = fmaf(x0.y, x0.y, xn0);
            xn0 = fmaf(x0.z, x0.z, xn0); xn0 = fmaf(x0.w, x0.w, xn0);
            xn1 = fmaf(x1.x, x1.x, xn1); xn1 = fmaf(x1.y, x1.y, xn1);
            xn1 = fmaf(x1.z, x1.z, xn1); xn1 = fmaf(x1.w, x1.w, xn1);
            float xv0[4] = {x0.x, x0.y, x0.z, x0.w};
            float xv1[4] = {x1.x, x1.y, x1.z, x1.w};
#pragma unroll
            for (int dd = 0; dd < 4; dd++) {
                float4 c4 = *(const float4*)&cwr[(d + dd) * CWSTR];
                a0[0] = fmaf(xv0[dd], c4.x, a0[0]);
                a0[1] = fmaf(xv0[dd], c4.y, a0[1]);
                a0[2] = fmaf(xv0[dd], c4.z, a0[2]);
                a0[3] = fmaf(xv0[dd], c4.w, a0[3]);
                a1[0] = fmaf(xv1[dd], c4.x, a1[0]);
                a1[1] = fmaf(xv1[dd], c4.y, a1[1]);
                a1[2] = fmaf(xv1[dd], c4.z, a1[2]);
                a1[3] = fmaf(xv1[dd], c4.w, a1[3]);
            }
        }
        int p0 = 2 * pg, ks = kg * 4;
#pragma unroll
        for (int j = 0; j < 4; j++) {
            sA[p0 * ASTR + ks + j]       = a0[j];
            sA[(p0 + 1) * ASTR + ks + j] = a1[j];
        }
        if (kg == 0) { sXn[p0] = xn0; sXn[p0 + 1] = xn1; }
    }
    __syncthreads();

    {
        int warp = t >> 5, lane = t & 31;
        float sc = scale[lane], c2v = g_c2[lane];
        for (int pi = 0; pi < 8; pi++) {
            int p = warp * 8 + pi;
            float sl = sc * (sXn[p] - 2.f * sA[p * ASTR + lane] + c2v);
            float mx = sl;
#pragma unroll
            for (int o = 16; o > 0; o >>= 1) mx = fmaxf(mx, __shfl_xor_sync(0xffffffffu, mx, o));
            float e = __expf(sl - mx);
            float se = e;
#pragma unroll
            for (int o = 16; o > 0; o >>= 1) se += __shfl_xor_sync(0xffffffffu, se, o);
            sA[p * ASTR + lane] = e / se;
        }
    }
    __syncthreads();
    if (t < 32) {
        float s = 0.f;
        for (int p = 0; p < 64; p++) s += sA[p * ASTR + t];
        atomicAdd(&g_sumA[bz * 32 + t], s);
    }

    float acc[32];
#pragma unroll
    for (int k = 0; k < 32; k++) acc[k] = 0.f;
    for (int p = 0; p < 64; p++) {
        float x = sX[p * XSTR + t];
#pragma unroll
        for (int kq = 0; kq < 8; kq++) {
            float4 a4 = *(const float4*)&sA[p * ASTR + kq * 4];
            acc[kq * 4 + 0] = fmaf(a4.x, x, acc[kq * 4 + 0]);
            acc[kq * 4 + 1] = fmaf(a4.y, x, acc[kq * 4 + 1]);
            acc[kq * 4 + 2] = fmaf(a4.z, x, acc[kq * 4 + 2]);
            acc[kq * 4 + 3] = fmaf(a4.w, x, acc[kq * 4 + 3]);
        }
    }
    float* Eb = g_E + (size_t)bz * 8192;
#pragma unroll
    for (int k = 0; k < 32; k++) atomicAdd(&Eb[k * 256 + t], acc[k]);
}

__global__ __launch_bounds__(256) void enc_fin_kernel(const float* __restrict__ cw)
{
    __shared__ float red[256];
    int bz = blockIdx.x, t = threadIdx.x;
    float ss = 0.f;
    for (int j = t; j < 8192; j += 256) {
        float v = g_E[bz * 8192 + j] - g_sumA[bz * 32 + (j >> 8)] * cw[j];
        v = fmaxf(v, 0.f);
        g_En[bz * 8192 + j] = v;
        ss += v * v;
    }
    red[t] = ss;
    __syncthreads();
    for (int s = 128; s > 0; s >>= 1) {
        if (t < s) red[t] += red[t + s];
        __syncthreads();
    }
    float rinv = 1.f / fmaxf(sqrtf(red[0]), 1e-12f);
    for (int j = t; j < 8192; j += 256) g_En[bz * 8192 + j] *= rinv;
}

__global__ __launch_bounds__(256) void ctx_gemv_kernel(const float* __restrict__ lin_w,
                                                       const float* __restrict__ lin_b)
{
    __shared__ float red[8][256];
    int o = blockIdx.x, t = threadIdx.x;
    float acc[8];
#pragma unroll
    for (int b = 0; b < 8; b++) acc[b] = 0.f;
    const float* wrow = lin_w + (size_t)o * 8192;
    for (int j = t; j < 8192; j += 256) {
        float w = wrow[j];
#pragma unroll
        for (int b = 0; b < 8; b++) acc[b] = fmaf(w, g_En[b * 8192 + j], acc[b]);
    }
#pragma unroll
    for (int b = 0; b < 8; b++) red[b][t] = acc[b];
    __syncthreads();
    for (int s = 128; s > 0; s >>= 1) {
        if (t < s) {
#pragma unroll
            for (int b = 0; b < 8; b++) red[b][t] += red[b][t + s];
        }
        __syncthreads();
    }
    if (t < 8) {
        float z = red[t][0] + lin_b[o];
        g_ctx[t * 256 + o] = 1.f / (1.f + expf(-z));
    }
}

// ---------------- final: float4 tiled transpose + ctx scale ----------------
__global__ __launch_bounds__(256) void final_kernel(float* __restrict__ out)
{
    __shared__ float tile[32][33];
    int bz = blockIdx.z;
    int d0 = blockIdx.x * 32, n0 = blockIdx.y * 32;
    int t = threadIdx.x;
    int nr = t >> 3, q4 = (t & 7) * 4;
    const float* h = g_h + (size_t)bz * NQ * 256;
    float4 v = *(const float4*)&h[(size_t)(n0 + nr) * 256 + d0 + q4];
    tile[q4 + 0][nr] = v.x; tile[q4 + 1][nr] = v.y;
    tile[q4 + 2][nr] = v.z; tile[q4 + 3][nr] = v.w;
    __syncthreads();
    int dr = nr;   // row in d
    float cx = g_ctx[bz * 256 + d0 + dr];
    float4 w = make_float4(tile[dr][q4 + 0] * cx, tile[dr][q4 + 1] * cx,
                           tile[dr][q4 + 2] * cx, tile[dr][q4 + 3] * cx);
    float* ob = out + (size_t)bz * 256 * NQ;
    *(float4*)&ob[(size_t)(d0 + dr) * NQ + n0 + q4] = w;
}

// ===================== launcher =====================
extern "C" void kernel_launch(void* const* d_in, const int* in_sizes, int n_in,
                              void* d_out, int out_size)
{
    (void)in_sizes; (void)n_in; (void)out_size;
    const float* unknown      = (const float*)d_in[0];
    const float* known        = (const float*)d_in[1];
    const float* unknow_feats = (const float*)d_in[2];
    const float* known_feats  = (const float*)d_in[3];
    const float* conv_w1 = (const float*)d_in[4];
    const float* conv_b1 = (const float*)d_in[5];
    const float* bn_g1 = (const float*)d_in[6];
    const float* bn_b1 = (const float*)d_in[7];
    const float* bn_m1 = (const float*)d_in[8];
    const float* bn_v1 = (const float*)d_in[9];
    const float* conv_w2 = (const float*)d_in[10];
    const float* conv_b2 = (const float*)d_in[11];
    const float* bn_g2 = (const float*)d_in[12];
    const float* bn_b2 = (const float*)d_in[13];
    const float* bn_m2 = (const float*)d_in[14];
    const float* bn_v2 = (const float*)d_in[15];
    const float* enc_cw    = (const float*)d_in[16];
    const float* enc_scale = (const float*)d_in[17];
    const float* lin_w     = (const float*)d_in[18];
    const float* lin_b     = (const float*)d_in[19];
    float* out = (float*)d_out;

    const int SMEMSZ = 9 * 8192 + 1024;
    static int attr_done = 0;
    if (!attr_done) {
        cudaFuncSetAttribute(gemm_mma<1>, cudaFuncAttributeMaxDynamicSharedMemorySize, SMEMSZ);
        cudaFuncSetAttribute(gemm_mma<2>, cudaFuncAttributeMaxDynamicSharedMemorySize, SMEMSZ);
        cudaFuncSetAttribute(encoding_kernel, cudaFuncAttributeMaxDynamicSharedMemorySize, ENC_SMEM);
        attr_done = 1;
    }

    noop_kernel<<<1, 32>>>();
    noop_kernel<<<1, 32>>>();
    noop_kernel<<<1, 32>>>();
    front_kernel<<<FR_TOTAL, 256>>>(unknown, known, unknow_feats, known_feats,
                                    conv_w1, conv_w2,
                                    conv_b1, bn_g1, bn_b1, bn_m1, bn_v1,
                                    conv_b2, bn_g2, bn_b2, bn_m2, bn_v2, enc_cw);
    interp_kernel<<<dim3(NQ / 8, B_), 256>>>();
    gemm_mma<1><<<dim3(2, 512), 256, SMEMSZ>>>();
    gemm_mma<2><<<dim3(2, 512), 256, SMEMSZ>>>();
    encoding_kernel<<<dim3(NQ / 64, B_), 256, ENC_SMEM>>>(enc_cw, enc_scale);
    enc_fin_kernel<<<B_, 256>>>(enc_cw);
    ctx_gemv_kernel<<<256, 256>>>(lin_w, lin_b);
    final_kernel<<<dim3(8, NQ / 32, B_), 256>>>(out);
}

// round 15
// speedup vs baseline: 1.6738x; 1.0045x over previous
#include <cuda_runtime.h>
#include <cuda_fp16.h>
#include <math.h>
#include <stdint.h>

#define B_   8
#define NQ   8192
#define MK   2048
typedef unsigned short ushortT;
typedef unsigned int   uintT;

// ===================== helpers =====================
__device__ __forceinline__ uint32_t smem_to_u32(const void* p) {
    uint32_t a;
    asm("{ .reg .u64 t; cvta.to.shared.u64 t, %1; cvt.u32.u64 %0, t; }" : "=r"(a) : "l"(p));
    return a;
}
#define CP_ASYNC16(s, g) \
    asm volatile("cp.async.cg.shared.global [%0], [%1], 16;" :: "r"(s), "l"(g))
#define CP_COMMIT() asm volatile("cp.async.commit_group;")
#define CP_WAIT1()  asm volatile("cp.async.wait_group 1;")

__device__ __forceinline__ void ldsm4(uint32_t& r0, uint32_t& r1, uint32_t& r2, uint32_t& r3,
                                      uint32_t addr) {
    asm volatile("ldmatrix.sync.aligned.m8n8.x4.shared.b16 {%0,%1,%2,%3}, [%4];"
                 : "=r"(r0), "=r"(r1), "=r"(r2), "=r"(r3) : "r"(addr));
}
__device__ __forceinline__ void mma16816(float* d, const uint32_t* a, const uint32_t* b) {
    asm volatile(
        "mma.sync.aligned.m16n8k16.row.col.f32.f16.f16.f32 "
        "{%0,%1,%2,%3}, {%4,%5,%6,%7}, {%8,%9}, {%0,%1,%2,%3};"
        : "+f"(d[0]), "+f"(d[1]), "+f"(d[2]), "+f"(d[3])
        : "r"(a[0]), "r"(a[1]), "r"(a[2]), "r"(a[3]), "r"(b[0]), "r"(b[1]));
}

// packed: 2 fp32 -> (h0,h1) packed + (l0,l1) packed, RNE (identical values to scalar path)
__device__ __forceinline__ void split2(float v0, float v1, uintT& hp, uintT& lp) {
    __half2 h2 = __floats2half2_rn(v0, v1);
    hp = *(uintT*)&h2;
    float l0 = v0 - __low2float(h2);
    float l1 = v1 - __high2float(h2);
    __half2 l2 = __floats2half2_rn(l0, l1);
    lp = *(uintT*)&l2;
}

__device__ __forceinline__ void ins3(float& d0, int& i0, float& d1, int& i1,
                                     float& d2, int& i2, float dd, int m) {
    if (dd < d2) {
        if (dd < d1) {
            d2 = d1; i2 = i1;
            if (dd < d0) { d1 = d0; i1 = i0; d0 = dd; i0 = m; }
            else          { d1 = dd; i1 = m; }
        } else { d2 = dd; i2 = m; }
    }
}

// ===================== scratch =====================
__device__ ushortT gA1[(size_t)8 * 8192 * 1024];  // fp16 [H(512) | L(512)]
__device__ ushortT gA2[(size_t)8 * 8192 * 512];   // fp16 [H(256) | L(256)]
__device__ ushortT gW1[256 * 512];                // fp16 Wh only
__device__ ushortT gW2[256 * 256];
__device__ float g_h  [(size_t)8 * 8192 * 256];
__device__ float g_kfT[(size_t)8 * 2048 * 256];
__device__ int   g_idx[8 * 8192 * 3];
__device__ float g_wgt[8 * 8192 * 3];
__device__ float g_E  [8 * 8192];
__device__ float g_En [8 * 8192];
__device__ float g_sumA[8 * 32];
__device__ float g_ctx[8 * 256];
__device__ float g_al1[256], g_be1[256], g_al2[256], g_be2[256];
__device__ float g_c2[32];

// ===================== noop (profile-slot shim) =====================
__global__ void noop_kernel() {}

// ===================== fused front kernel =====================
#define FR_TRKF   4096
#define FR_TRUNK  20480
#define FR_3NN    22528
#define FR_EXPW   23040
#define FR_TOTAL  23296
#define CHPAD8    257

__global__ __launch_bounds__(256) void front_kernel(
    const float* __restrict__ unknown, const float* __restrict__ known,
    const float* __restrict__ uf, const float* __restrict__ kf,
    const float* __restrict__ w1, const float* __restrict__ w2,
    const float* __restrict__ cb1, const float* __restrict__ gg1,
    const float* __restrict__ bb1, const float* __restrict__ mm1,
    const float* __restrict__ vv1,
    const float* __restrict__ cb2, const float* __restrict__ gg2,
    const float* __restrict__ bb2, const float* __restrict__ mm2,
    const float* __restrict__ vv2,
    const float* __restrict__ cw)
{
    __shared__ __align__(16) char sbuf[8 * CHPAD8 * 16];
    int bx = blockIdx.x;
    int t  = threadIdx.x;

    if (bx < FR_TRKF) {
        float (*tile)[33] = (float(*)[33])sbuf;
        int m0 = (bx & 63) * 32, c0 = ((bx >> 6) & 7) * 32, b = bx >> 9;
        int cr = t >> 3, q4 = (t & 7) * 4;
        const float* in = kf + (size_t)b * 256 * MK;
        float4 v = *(const float4*)&in[(size_t)(c0 + cr) * MK + m0 + q4];
        tile[cr][q4 + 0] = v.x; tile[cr][q4 + 1] = v.y;
        tile[cr][q4 + 2] = v.z; tile[cr][q4 + 3] = v.w;
        __syncthreads();
        float* out = g_kfT + (size_t)b * MK * 256;
        float4 w = make_float4(tile[q4 + 0][cr], tile[q4 + 1][cr],
                               tile[q4 + 2][cr], tile[q4 + 3][cr]);
        *(float4*)&out[(size_t)(m0 + cr) * 256 + c0 + q4] = w;
    } else if (bx < FR_TRUNK) {
        float (*tile)[33] = (float(*)[33])sbuf;
        int idx = bx - FR_TRKF;
        int n0 = (idx & 255) * 32, c0 = ((idx >> 8) & 7) * 32, b = idx >> 11;
        int cr = t >> 3, q4 = (t & 7) * 4;
        const float* in = uf + (size_t)b * 256 * NQ;
        float4 v = *(const float4*)&in[(size_t)(c0 + cr) * NQ + n0 + q4];
        tile[cr][q4 + 0] = v.x; tile[cr][q4 + 1] = v.y;
        tile[cr][q4 + 2] = v.z; tile[cr][q4 + 3] = v.w;
        __syncthreads();
        uint2 hp, lp;
        split2(tile[q4 + 0][cr], tile[q4 + 1][cr], hp.x, lp.x);
        split2(tile[q4 + 2][cr], tile[q4 + 3][cr], hp.y, lp.y);
        size_t row = ((size_t)b * NQ + n0 + cr) * 1024;
        *(uint2*)&gA1[row + 256 + c0 + q4] = hp;
        *(uint2*)&gA1[row + 768 + c0 + q4] = lp;
    } else if (bx < FR_3NN) {
        float4* kp = (float4*)sbuf;
        int idx = bx - FR_TRUNK;
        int bz = idx >> 8;
        int q  = (idx & 255) * 32 + (t >> 3);
        int ck = t & 7;

        const float* kb = known + (size_t)bz * MK * 3;
        for (int i = t; i < MK; i += 256) {
            float kx = kb[i * 3 + 0];
            float ky = kb[i * 3 + 1];
            float kz = kb[i * 3 + 2];
            kp[(i >> 8) * CHPAD8 + (i & 255)] = make_float4(kx, ky, kz, kx * kx + ky * ky + kz * kz);
        }
        __syncthreads();

        const float* u = unknown + ((size_t)bz * NQ + q) * 3;
        float ux = u[0], uy = u[1], uz = u[2];
        float x2 = ux * ux + uy * uy + uz * uz;
        float mux = -2.f * ux, muy = -2.f * uy, muz = -2.f * uz;

        float d0 = 1e30f, d1 = 1e30f, d2 = 1e30f;
        int   i0 = 0, i1 = 0, i2 = 0;
        const float4* base = kp + ck * CHPAD8;
        int m0 = ck * 256;
#pragma unroll 4
        for (int j = 0; j < 256; j++) {
            float4 p = base[j];
            float dd = fmaf(mux, p.x, p.w);
            dd = fmaf(muy, p.y, dd);
            dd = fmaf(muz, p.z, dd);
            ins3(d0, i0, d1, i1, d2, i2, dd, m0 + j);
        }

#pragma unroll
        for (int off = 1; off <= 4; off <<= 1) {
            float e0 = __shfl_xor_sync(0xffffffffu, d0, off);
            float e1 = __shfl_xor_sync(0xffffffffu, d1, off);
            float e2 = __shfl_xor_sync(0xffffffffu, d2, off);
            int   j0 = __shfl_xor_sync(0xffffffffu, i0, off);
            int   j1 = __shfl_xor_sync(0xffffffffu, i1, off);
            int   j2 = __shfl_xor_sync(0xffffffffu, i2, off);
            ins3(d0, i0, d1, i1, d2, i2, e0, j0);
            ins3(d0, i0, d1, i1, d2, i2, e1, j1);
            ins3(d0, i0, d1, i1, d2, i2, e2, j2);
        }

        if (ck == 0) {
            float r0 = 1.f / (sqrtf(fmaxf(d0 + x2, 1e-12f)) + 1e-8f);
            float r1 = 1.f / (sqrtf(fmaxf(d1 + x2, 1e-12f)) + 1e-8f);
            float r2 = 1.f / (sqrtf(fmaxf(d2 + x2, 1e-12f)) + 1e-8f);
            float rs = 1.f / (r0 + r1 + r2);
            size_t base2 = ((size_t)bz * NQ + q) * 3;
            g_idx[base2 + 0] = i0; g_idx[base2 + 1] = i1; g_idx[base2 + 2] = i2;
            g_wgt[base2 + 0] = r0 * rs; g_wgt[base2 + 1] = r1 * rs; g_wgt[base2 + 2] = r2 * rs;
        }
    } else if (bx < FR_EXPW) {
        int i = (bx - FR_3NN) * 256 + t;
        if (i < 256 * 512) {
            int n = i >> 9, k = i & 511;
            gW1[n * 512 + k] = __half_as_ushort(__float2half_rn(w1[i]));
        }
        if (i < 256 * 256) {
            int n = i >> 8, k = i & 255;
            gW2[n * 256 + k] = __half_as_ushort(__float2half_rn(w2[i]));
        }
    } else {
        int i = (bx - FR_EXPW) * 256 + t;
        if (i < 256) {
            float s1 = gg1[i] * rsqrtf(vv1[i] + 1e-5f);
            g_al1[i] = s1;
            g_be1[i] = s1 * (cb1[i] - mm1[i]) + bb1[i];
            float s2 = gg2[i] * rsqrtf(vv2[i] + 1e-5f);
            g_al2[i] = s2;
            g_be2[i] = s2 * (cb2[i] - mm2[i]) + bb2[i];
        }
        if (i < 32) {
            float s = 0.f;
            const float* c = cw + i * 256;
            for (int d = 0; d < 256; d++) s += c[d] * c[d];
            g_c2[i] = s;
        }
        if (i < 8 * 32) g_sumA[i] = 0.f;
        if (i < 8 * 8192) g_E[i] = 0.f;
    }
}

// ---------------- interpolate: 8 floats/thread, packed converts ----------------
__global__ __launch_bounds__(256) void interp_kernel()
{
    int bz = blockIdx.y, t = threadIdx.x;
    int n = blockIdx.x * 8 + (t >> 5);
    int d = (t & 31) * 8;
    size_t base = ((size_t)bz * NQ + n) * 3;
    int i0 = g_idx[base], i1 = g_idx[base + 1], i2 = g_idx[base + 2];
    float w0 = g_wgt[base], w1 = g_wgt[base + 1], w2 = g_wgt[base + 2];
    const float* kf = g_kfT + (size_t)bz * MK * 256;
    const float* r0 = &kf[(size_t)i0 * 256 + d];
    const float* r1 = &kf[(size_t)i1 * 256 + d];
    const float* r2 = &kf[(size_t)i2 * 256 + d];
    float4 a0 = *(const float4*)r0,       a1 = *(const float4*)(r0 + 4);
    float4 b0 = *(const float4*)r1,       b1 = *(const float4*)(r1 + 4);
    float4 c0 = *(const float4*)r2,       c1 = *(const float4*)(r2 + 4);
    float v[8];
    v[0] = w0 * a0.x + w1 * b0.x + w2 * c0.x;
    v[1] = w0 * a0.y + w1 * b0.y + w2 * c0.y;
    v[2] = w0 * a0.z + w1 * b0.z + w2 * c0.z;
    v[3] = w0 * a0.w + w1 * b0.w + w2 * c0.w;
    v[4] = w0 * a1.x + w1 * b1.x + w2 * c1.x;
    v[5] = w0 * a1.y + w1 * b1.y + w2 * c1.y;
    v[6] = w0 * a1.z + w1 * b1.z + w2 * c1.z;
    v[7] = w0 * a1.w + w1 * b1.w + w2 * c1.w;
    uintT hp[4], lp[4];
#pragma unroll
    for (int j = 0; j < 4; j++)
        split2(v[2 * j], v[2 * j + 1], hp[j], lp[j]);
    size_t row = ((size_t)bz * NQ + n) * 1024;
    *(uint4*)&gA1[row + d]       = *(uint4*)hp;
    *(uint4*)&gA1[row + 512 + d] = *(uint4*)lp;
}

// ===================== HMMA GEMM: shared-B fp16 split =====================
template <int L>
__global__ __launch_bounds__(256) void gemm_mma()
{
    constexpr int K   = (L == 1) ? 512 : 256;
    constexpr int NCH = K / 32;
    constexpr int KA  = 2 * K;
    const ushortT* Ag = (L == 1) ? gA1 : gA2;
    const ushortT* Wg = (L == 1) ? gW1 : gW2;
    const float* alpha = (L == 1) ? g_al1 : g_al2;
    const float* beta  = (L == 1) ? g_be1 : g_be2;

    extern __shared__ __align__(16) ushortT dyn[];
    ushortT* sAH = dyn;
    ushortT* sAL = dyn + 3 * 4096;
    ushortT* sB  = dyn + 6 * 4096;
    float* s_al = (float*)(dyn + 9 * 4096);
    float* s_be = s_al + 128;

    int tid = threadIdx.x, wid = tid >> 5, lane = tid & 31;
    int bn = blockIdx.x * 128, bm = blockIdx.y * 128;
    if (tid < 128) { s_al[tid] = alpha[bn + tid]; s_be[tid] = beta[bn + tid]; }

    uint32_t sAHb = smem_to_u32(sAH);
    uint32_t sALb = smem_to_u32(sAL);
    uint32_t sBb  = smem_to_u32(sB);

    int lr = tid >> 1;
    int ls = (tid & 1) * 2;
    uint32_t off0 = lr * 64 + (((ls)     ^ (lr & 3)) << 4);
    uint32_t off1 = lr * 64 + (((ls + 1) ^ (lr & 3)) << 4);

    const ushortT* ArowH = Ag + (size_t)(bm + lr) * KA;
    const ushortT* ArowL = ArowH + K;
    const ushortT* Wrow  = Wg + (size_t)(bn + lr) * K;

#define LOAD_CHUNK(p, st) do { \
    int _col = (p) * 32; \
    uint32_t _ah = sAHb + (st) * 8192; \
    uint32_t _al = sALb + (st) * 8192; \
    uint32_t _ws = sBb  + (st) * 8192; \
    CP_ASYNC16(_ah + off0, ArowH + _col + ls * 8); \
    CP_ASYNC16(_ah + off1, ArowH + _col + ls * 8 + 8); \
    CP_ASYNC16(_al + off0, ArowL + _col + ls * 8); \
    CP_ASYNC16(_al + off1, ArowL + _col + ls * 8 + 8); \
    CP_ASYNC16(_ws + off0, Wrow + _col + ls * 8); \
    CP_ASYNC16(_ws + off1, Wrow + _col + ls * 8 + 8); \
    CP_COMMIT(); } while (0)

    LOAD_CHUNK(0, 0);
    LOAD_CHUNK(1, 1);

    float c[2][8][4];
#pragma unroll
    for (int i = 0; i < 2; i++)
#pragma unroll
        for (int j = 0; j < 8; j++)
#pragma unroll
            for (int q = 0; q < 4; q++) c[i][j][q] = 0.f;

    int wm = wid & 3, wn = wid >> 2;

    int st = 0, stn = 2;
    for (int kc = 0; kc < NCH; kc++) {
        CP_WAIT1();
        __syncthreads();
        int kn = kc + 2;
        if (kn < NCH) LOAD_CHUNK(kn, stn);
        uint32_t aHBase = sAHb + st * 8192;
        uint32_t aLBase = sALb + st * 8192;
        uint32_t bBase  = sBb  + st * 8192;
#pragma unroll
        for (int kk = 0; kk < 2; kk++) {
            uint32_t ah[2][4], al[2][4], bf[8][2];
#pragma unroll
            for (int mt = 0; mt < 2; mt++) {
                int r = wm * 32 + mt * 16 + (lane & 15);
                int s = kk * 2 + (lane >> 4);
                uint32_t ro = r * 64 + ((s ^ (r & 3)) << 4);
                ldsm4(ah[mt][0], ah[mt][1], ah[mt][2], ah[mt][3], aHBase + ro);
                ldsm4(al[mt][0], al[mt][1], al[mt][2], al[mt][3], aLBase + ro);
            }
#pragma unroll
            for (int np = 0; np < 4; np++) {
                int r = wn * 64 + np * 16 + (lane & 7) + ((lane >> 4) << 3);
                int s = kk * 2 + ((lane >> 3) & 1);
                ldsm4(bf[2 * np][0], bf[2 * np][1], bf[2 * np + 1][0], bf[2 * np + 1][1],
                      bBase + r * 64 + ((s ^ (r & 3)) << 4));
            }
#pragma unroll
            for (int mt = 0; mt < 2; mt++)
#pragma unroll
                for (int nt = 0; nt < 8; nt++)
                    mma16816(c[mt][nt], ah[mt], bf[nt]);
#pragma unroll
            for (int mt = 0; mt < 2; mt++)
#pragma unroll
                for (int nt = 0; nt < 8; nt++)
                    mma16816(c[mt][nt], al[mt], bf[nt]);
        }
        st  = (st == 2)  ? 0 : st + 1;
        stn = (stn == 2) ? 0 : stn + 1;
    }
#undef LOAD_CHUNK

#pragma unroll
    for (int mt = 0; mt < 2; mt++) {
#pragma unroll
        for (int nt = 0; nt < 8; nt++) {
            int cl = wn * 64 + nt * 8 + (lane & 3) * 2;
            int gcol = bn + cl;
            int rl = wm * 32 + mt * 16 + (lane >> 2);
#pragma unroll
            for (int hh = 0; hh < 2; hh++) {
                int grow = bm + rl + hh * 8;
                float v0 = fmaxf(fmaf(c[mt][nt][hh * 2 + 0], s_al[cl],     s_be[cl]),     0.f);
                float v1 = fmaxf(fmaf(c[mt][nt][hh * 2 + 1], s_al[cl + 1], s_be[cl + 1]), 0.f);
                if (L == 1) {
                    uintT hp, lp;
                    split2(v0, v1, hp, lp);
                    *(uintT*)&gA2[(size_t)grow * 512 + gcol]       = hp;
                    *(uintT*)&gA2[(size_t)grow * 512 + 256 + gcol] = lp;
                } else {
                    float2 o = make_float2(v0, v1);
                    *(float2*)&g_h[(size_t)grow * 256 + gcol] = o;
                }
            }
        }
    }
}

// ===================== encoding =====================
#define XSTR  260
#define CWSTR 36
#define ASTR  36
#define ENC_SMEM ((64 * XSTR + 256 * CWSTR + 64 * ASTR + 64) * 4)

__global__ __launch_bounds__(256) void encoding_kernel(const float* __restrict__ cw,
                                                       const float* __restrict__ scale)
{
    extern __shared__ float es[];
    float* sX  = es;
    float* cwT = es + 64 * XSTR;
    float* sA  = cwT + 256 * CWSTR;
    float* sXn = sA + 64 * ASTR;

    int bz = blockIdx.y, n0 = blockIdx.x * 64, t = threadIdx.x;
    const float* Xb = g_h + ((size_t)bz * NQ + n0) * 256;

    for (int i = t; i < 64 * 64; i += 256) {
        int p = i >> 6, d4 = i & 63;
        *(float4*)&sX[p * XSTR + d4 * 4] = *(const float4*)&Xb[(size_t)p * 256 + d4 * 4];
    }
    for (int i = t; i < 32 * 256; i += 256) {
        int k = i >> 8, d = i & 255;
        cwT[d * CWSTR + k] = cw[i];
    }
    __syncthreads();

    {
        int pg = t >> 3, kg = t & 7;
        const float* xr0 = sX + (2 * pg) * XSTR;
        const float* xr1 = xr0 + XSTR;
        const float* cwr = cwT + kg * 4;
        float a0[4] = {0.f, 0.f, 0.f, 0.f}, a1[4] = {0.f, 0.f, 0.f, 0.f};
        float xn0 = 0.f, xn1 = 0.f;
#pragma unroll 4
        for (int d = 0; d < 256; d += 4) {
            float4 x0 = *(const float4*)&xr0[d];
            float4 x1 = *(const float4*)&xr1[d];
            xn0 = fmaf(x0.x, x0.x, xn0); xn0 = fmaf(x0.y, x0.y, xn0);
            xn0 = fmaf(x0.z, x0.z, xn0); xn0 = fmaf(x0.w, x0.w, xn0);
            xn1 = fmaf(x1.x, x1.x, xn1); xn1 = fmaf(x1.y, x1.y, xn1);
            xn1 = fmaf(x1.z, x1.z, xn1); xn1 = fmaf(x1.w, x1.w, xn1);
            float xv0[4] = {x0.x, x0.y, x0.z, x0.w};
            float xv1[4] = {x1.x, x1.y, x1.z, x1.w};
#pragma unroll
            for (int dd = 0; dd < 4; dd++) {
                float4 c4 = *(const float4*)&cwr[(d + dd) * CWSTR];
                a0[0] = fmaf(xv0[dd], c4.x, a0[0]);
                a0[1] = fmaf(xv0[dd], c4.y, a0[1]);
                a0[2] = fmaf(xv0[dd], c4.z, a0[2]);
                a0[3] = fmaf(xv0[dd], c4.w, a0[3]);
                a1[0] = fmaf(xv1[dd], c4.x, a1[0]);
                a1[1] = fmaf(xv1[dd], c4.y, a1[1]);
                a1[2] = fmaf(xv1[dd], c4.z, a1[2]);
                a1[3] = fmaf(xv1[dd], c4.w, a1[3]);
            }
        }
        int p0 = 2 * pg, ks = kg * 4;
#pragma unroll
        for (int j = 0; j < 4; j++) {
            sA[p0 * ASTR + ks + j]       = a0[j];
            sA[(p0 + 1) * ASTR + ks + j] = a1[j];
        }
        if (kg == 0) { sXn[p0] = xn0; sXn[p0 + 1] = xn1; }
    }
    __syncthreads();

    {
        int warp = t >> 5, lane = t & 31;
        float sc = scale[lane], c2v = g_c2[lane];
        for (int pi = 0; pi < 8; pi++) {
            int p = warp * 8 + pi;
            float sl = sc * (sXn[p] - 2.f * sA[p * ASTR + lane] + c2v);
            float mx = sl;
#pragma unroll
            for (int o = 16; o > 0; o >>= 1) mx = fmaxf(mx, __shfl_xor_sync(0xffffffffu, mx, o));
            float e = __expf(sl - mx);
            float se = e;
#pragma unroll
            for (int o = 16; o > 0; o >>= 1) se += __shfl_xor_sync(0xffffffffu, se, o);
            sA[p * ASTR + lane] = e / se;
        }
    }
    __syncthreads();
    if (t < 32) {
        float s = 0.f;
        for (int p = 0; p < 64; p++) s += sA[p * ASTR + t];
        atomicAdd(&g_sumA[bz * 32 + t], s);
    }

    float acc[32];
#pragma unroll
    for (int k = 0; k < 32; k++) acc[k] = 0.f;
    for (int p = 0; p < 64; p++) {
        float x = sX[p * XSTR + t];
#pragma unroll
        for (int kq = 0; kq < 8; kq++) {
            float4 a4 = *(const float4*)&sA[p * ASTR + kq * 4];
            acc[kq * 4 + 0] = fmaf(a4.x, x, acc[kq * 4 + 0]);
            acc[kq * 4 + 1] = fmaf(a4.y, x, acc[kq * 4 + 1]);
            acc[kq * 4 + 2] = fmaf(a4.z, x, acc[kq * 4 + 2]);
            acc[kq * 4 + 3] = fmaf(a4.w, x, acc[kq * 4 + 3]);
        }
    }
    float* Eb = g_E + (size_t)bz * 8192;
#pragma unroll
    for (int k = 0; k < 32; k++) atomicAdd(&Eb[k * 256 + t], acc[k]);
}

__global__ __launch_bounds__(256) void enc_fin_kernel(const float* __restrict__ cw)
{
    __shared__ float red[256];
    int bz = blockIdx.x, t = threadIdx.x;
    float ss = 0.f;
    for (int j = t; j < 8192; j += 256) {
        float v = g_E[bz * 8192 + j] - g_sumA[bz * 32 + (j >> 8)] * cw[j];
        v = fmaxf(v, 0.f);
        g_En[bz * 8192 + j] = v;
        ss += v * v;
    }
    red[t] = ss;
    __syncthreads();
    for (int s = 128; s > 0; s >>= 1) {
        if (t < s) red[t] += red[t + s];
        __syncthreads();
    }
    float rinv = 1.f / fmaxf(sqrtf(red[0]), 1e-12f);
    for (int j = t; j < 8192; j += 256) g_En[bz * 8192 + j] *= rinv;
}

__global__ __launch_bounds__(256) void ctx_gemv_kernel(const float* __restrict__ lin_w,
                                                       const float* __restrict__ lin_b)
{
    __shared__ float red[8][256];
    int o = blockIdx.x, t = threadIdx.x;
    float acc[8];
#pragma unroll
    for (int b = 0; b < 8; b++) acc[b] = 0.f;
    const float* wrow = lin_w + (size_t)o * 8192;
    for (int j = t; j < 8192; j += 256) {
        float w = wrow[j];
#pragma unroll
        for (int b = 0; b < 8; b++) acc[b] = fmaf(w, g_En[b * 8192 + j], acc[b]);
    }
#pragma unroll
    for (int b = 0; b < 8; b++) red[b][t] = acc[b];
    __syncthreads();
    for (int s = 128; s > 0; s >>= 1) {
        if (t < s) {
#pragma unroll
            for (int b = 0; b < 8; b++) red[b][t] += red[b][t + s];
        }
        __syncthreads();
    }
    if (t < 8) {
        float z = red[t][0] + lin_b[o];
        g_ctx[t * 256 + o] = 1.f / (1.f + expf(-z));
    }
}

// ---------------- final: float4 tiled transpose + ctx scale ----------------
__global__ __launch_bounds__(256) void final_kernel(float* __restrict__ out)
{
    __shared__ float tile[32][33];
    int bz = blockIdx.z;
    int d0 = blockIdx.x * 32, n0 = blockIdx.y * 32;
    int t = threadIdx.x;
    int nr = t >> 3, q4 = (t & 7) * 4;
    const float* h = g_h + (size_t)bz * NQ * 256;
    float4 v = *(const float4*)&h[(size_t)(n0 + nr) * 256 + d0 + q4];
    tile[q4 + 0][nr] = v.x; tile[q4 + 1][nr] = v.y;
    tile[q4 + 2][nr] = v.z; tile[q4 + 3][nr] = v.w;
    __syncthreads();
    int dr = nr;
    float cx = g_ctx[bz * 256 + d0 + dr];
    float4 w = make_float4(tile[dr][q4 + 0] * cx, tile[dr][q4 + 1] * cx,
                           tile[dr][q4 + 2] * cx, tile[dr][q4 + 3] * cx);
    float* ob = out + (size_t)bz * 256 * NQ;
    *(float4*)&ob[(size_t)(d0 + dr) * NQ + n0 + q4] = w;
}

// ===================== launcher =====================
extern "C" void kernel_launch(void* const* d_in, const int* in_sizes, int n_in,
                              void* d_out, int out_size)
{
    (void)in_sizes; (void)n_in; (void)out_size;
    const float* unknown      = (const float*)d_in[0];
    const float* known        = (const float*)d_in[1];
    const float* unknow_feats = (const float*)d_in[2];
    const float* known_feats  = (const float*)d_in[3];
    const float* conv_w1 = (const float*)d_in[4];
    const float* conv_b1 = (const float*)d_in[5];
    const float* bn_g1 = (const float*)d_in[6];
    const float* bn_b1 = (const float*)d_in[7];
    const float* bn_m1 = (const float*)d_in[8];
    const float* bn_v1 = (const float*)d_in[9];
    const float* conv_w2 = (const float*)d_in[10];
    const float* conv_b2 = (const float*)d_in[11];
    const float* bn_g2 = (const float*)d_in[12];
    const float* bn_b2 = (const float*)d_in[13];
    const float* bn_m2 = (const float*)d_in[14];
    const float* bn_v2 = (const float*)d_in[15];
    const float* enc_cw    = (const float*)d_in[16];
    const float* enc_scale = (const float*)d_in[17];
    const float* lin_w     = (const float*)d_in[18];
    const float* lin_b     = (const float*)d_in[19];
    float* out = (float*)d_out;

    const int SMEMSZ = 9 * 8192 + 1024;
    static int attr_done = 0;
    if (!attr_done) {
        cudaFuncSetAttribute(gemm_mma<1>, cudaFuncAttributeMaxDynamicSharedMemorySize, SMEMSZ);
        cudaFuncSetAttribute(gemm_mma<2>, cudaFuncAttributeMaxDynamicSharedMemorySize, SMEMSZ);
        cudaFuncSetAttribute(encoding_kernel, cudaFuncAttributeMaxDynamicSharedMemorySize, ENC_SMEM);
        attr_done = 1;
    }

    noop_kernel<<<1, 32>>>();
    noop_kernel<<<1, 32>>>();
    front_kernel<<<FR_TOTAL, 256>>>(unknown, known, unknow_feats, known_feats,
                                    conv_w1, conv_w2,
                                    conv_b1, bn_g1, bn_b1, bn_m1, bn_v1,
                                    conv_b2, bn_g2, bn_b2, bn_m2, bn_v2, enc_cw);
    interp_kernel<<<dim3(NQ / 8, B_), 256>>>();
    gemm_mma<1><<<dim3(2, 512), 256, SMEMSZ>>>();
    gemm_mma<2><<<dim3(2, 512), 256, SMEMSZ>>>();
    encoding_kernel<<<dim3(NQ / 64, B_), 256, ENC_SMEM>>>(enc_cw, enc_scale);
    enc_fin_kernel<<<B_, 256>>>(enc_cw);
    ctx_gemv_kernel<<<256, 256>>>(lin_w, lin_b);
    final_kernel<<<dim3(8, NQ / 32, B_), 256>>>(out);
}

// round 16
// speedup vs baseline: 1.6763x; 1.0014x over previous
#include <cuda_runtime.h>
#include <cuda_fp16.h>
#include <math.h>
#include <stdint.h>

#define B_   8
#define NQ   8192
#define MK   2048
typedef unsigned short ushortT;
typedef unsigned int   uintT;

// ===================== helpers =====================
__device__ __forceinline__ uint32_t smem_to_u32(const void* p) {
    uint32_t a;
    asm("{ .reg .u64 t; cvta.to.shared.u64 t, %1; cvt.u32.u64 %0, t; }" : "=r"(a) : "l"(p));
    return a;
}
#define CP_ASYNC16(s, g) \
    asm volatile("cp.async.cg.shared.global [%0], [%1], 16;" :: "r"(s), "l"(g))
#define CP_COMMIT() asm volatile("cp.async.commit_group;")
#define CP_WAIT1()  asm volatile("cp.async.wait_group 1;")

__device__ __forceinline__ void ldsm4(uint32_t& r0, uint32_t& r1, uint32_t& r2, uint32_t& r3,
                                      uint32_t addr) {
    asm volatile("ldmatrix.sync.aligned.m8n8.x4.shared.b16 {%0,%1,%2,%3}, [%4];"
                 : "=r"(r0), "=r"(r1), "=r"(r2), "=r"(r3) : "r"(addr));
}
__device__ __forceinline__ void mma16816(float* d, const uint32_t* a, const uint32_t* b) {
    asm volatile(
        "mma.sync.aligned.m16n8k16.row.col.f32.f16.f16.f32 "
        "{%0,%1,%2,%3}, {%4,%5,%6,%7}, {%8,%9}, {%0,%1,%2,%3};"
        : "+f"(d[0]), "+f"(d[1]), "+f"(d[2]), "+f"(d[3])
        : "r"(a[0]), "r"(a[1]), "r"(a[2]), "r"(a[3]), "r"(b[0]), "r"(b[1]));
}

// packed: 2 fp32 -> (h0,h1) packed + (l0,l1) packed, RNE
__device__ __forceinline__ void split2(float v0, float v1, uintT& hp, uintT& lp) {
    __half2 h2 = __floats2half2_rn(v0, v1);
    hp = *(uintT*)&h2;
    float l0 = v0 - __low2float(h2);
    float l1 = v1 - __high2float(h2);
    __half2 l2 = __floats2half2_rn(l0, l1);
    lp = *(uintT*)&l2;
}

__device__ __forceinline__ void ins3(float& d0, int& i0, float& d1, int& i1,
                                     float& d2, int& i2, float dd, int m) {
    if (dd < d2) {
        if (dd < d1) {
            d2 = d1; i2 = i1;
            if (dd < d0) { d1 = d0; i1 = i0; d0 = dd; i0 = m; }
            else          { d1 = dd; i1 = m; }
        } else { d2 = dd; i2 = m; }
    }
}

// ===================== scratch =====================
__device__ ushortT gA1[(size_t)8 * 8192 * 1024];  // fp16 [H(512) | L(512)]
__device__ ushortT gA2[(size_t)8 * 8192 * 512];   // fp16 [H(256) | L(256)]
__device__ ushortT gW1[256 * 512];                // fp16 Wh only
__device__ ushortT gW2[256 * 256];
__device__ float g_h  [(size_t)8 * 8192 * 256];
__device__ float g_kfT[(size_t)8 * 2048 * 256];
__device__ int   g_idx[8 * 8192 * 3];
__device__ float g_wgt[8 * 8192 * 3];
__device__ float g_E  [8 * 8192];
__device__ float g_En [8 * 8192];
__device__ float g_sumA[8 * 32];
__device__ float g_ctx[8 * 256];
__device__ float g_al1[256], g_be1[256], g_al2[256], g_be2[256];
__device__ float g_c2[32];

// ===================== fused front kernel (three_nn FIRST: long-pole blocks start early)
#define FR_3NN    2048
#define FR_TRKF   6144
#define FR_TRUNK  22528
#define FR_EXPW   23040
#define FR_TOTAL  23296
#define CHPAD8    257

__global__ __launch_bounds__(256) void front_kernel(
    const float* __restrict__ unknown, const float* __restrict__ known,
    const float* __restrict__ uf, const float* __restrict__ kf,
    const float* __restrict__ w1, const float* __restrict__ w2,
    const float* __restrict__ cb1, const float* __restrict__ gg1,
    const float* __restrict__ bb1, const float* __restrict__ mm1,
    const float* __restrict__ vv1,
    const float* __restrict__ cb2, const float* __restrict__ gg2,
    const float* __restrict__ bb2, const float* __restrict__ mm2,
    const float* __restrict__ vv2,
    const float* __restrict__ cw)
{
    __shared__ __align__(16) char sbuf[8 * CHPAD8 * 16];
    int bx = blockIdx.x;
    int t  = threadIdx.x;

    if (bx < FR_3NN) {
        // ---- three_nn: 8 threads/query, 256-pt padded chunks ----
        float4* kp = (float4*)sbuf;
        int bz = bx >> 8;
        int q  = (bx & 255) * 32 + (t >> 3);
        int ck = t & 7;

        const float* kb = known + (size_t)bz * MK * 3;
        for (int i = t; i < MK; i += 256) {
            float kx = kb[i * 3 + 0];
            float ky = kb[i * 3 + 1];
            float kz = kb[i * 3 + 2];
            kp[(i >> 8) * CHPAD8 + (i & 255)] = make_float4(kx, ky, kz, kx * kx + ky * ky + kz * kz);
        }
        __syncthreads();

        const float* u = unknown + ((size_t)bz * NQ + q) * 3;
        float ux = u[0], uy = u[1], uz = u[2];
        float x2 = ux * ux + uy * uy + uz * uz;
        float mux = -2.f * ux, muy = -2.f * uy, muz = -2.f * uz;

        float d0 = 1e30f, d1 = 1e30f, d2 = 1e30f;
        int   i0 = 0, i1 = 0, i2 = 0;
        const float4* base = kp + ck * CHPAD8;
        int m0 = ck * 256;
#pragma unroll 4
        for (int j = 0; j < 256; j++) {
            float4 p = base[j];
            float dd = fmaf(mux, p.x, p.w);
            dd = fmaf(muy, p.y, dd);
            dd = fmaf(muz, p.z, dd);
            ins3(d0, i0, d1, i1, d2, i2, dd, m0 + j);
        }

#pragma unroll
        for (int off = 1; off <= 4; off <<= 1) {
            float e0 = __shfl_xor_sync(0xffffffffu, d0, off);
            float e1 = __shfl_xor_sync(0xffffffffu, d1, off);
            float e2 = __shfl_xor_sync(0xffffffffu, d2, off);
            int   j0 = __shfl_xor_sync(0xffffffffu, i0, off);
            int   j1 = __shfl_xor_sync(0xffffffffu, i1, off);
            int   j2 = __shfl_xor_sync(0xffffffffu, i2, off);
            ins3(d0, i0, d1, i1, d2, i2, e0, j0);
            ins3(d0, i0, d1, i1, d2, i2, e1, j1);
            ins3(d0, i0, d1, i1, d2, i2, e2, j2);
        }

        if (ck == 0) {
            float r0 = 1.f / (sqrtf(fmaxf(d0 + x2, 1e-12f)) + 1e-8f);
            float r1 = 1.f / (sqrtf(fmaxf(d1 + x2, 1e-12f)) + 1e-8f);
            float r2 = 1.f / (sqrtf(fmaxf(d2 + x2, 1e-12f)) + 1e-8f);
            float rs = 1.f / (r0 + r1 + r2);
            size_t base2 = ((size_t)bz * NQ + q) * 3;
            g_idx[base2 + 0] = i0; g_idx[base2 + 1] = i1; g_idx[base2 + 2] = i2;
            g_wgt[base2 + 0] = r0 * rs; g_wgt[base2 + 1] = r1 * rs; g_wgt[base2 + 2] = r2 * rs;
        }
    } else if (bx < FR_TRKF) {
        // ---- transpose known_feats (B,256,2048) -> g_kfT, float4 ----
        float (*tile)[33] = (float(*)[33])sbuf;
        int idx = bx - FR_3NN;
        int m0 = (idx & 63) * 32, c0 = ((idx >> 6) & 7) * 32, b = idx >> 9;
        int cr = t >> 3, q4 = (t & 7) * 4;
        const float* in = kf + (size_t)b * 256 * MK;
        float4 v = *(const float4*)&in[(size_t)(c0 + cr) * MK + m0 + q4];
        tile[cr][q4 + 0] = v.x; tile[cr][q4 + 1] = v.y;
        tile[cr][q4 + 2] = v.z; tile[cr][q4 + 3] = v.w;
        __syncthreads();
        float* out = g_kfT + (size_t)b * MK * 256;
        float4 w = make_float4(tile[q4 + 0][cr], tile[q4 + 1][cr],
                               tile[q4 + 2][cr], tile[q4 + 3][cr]);
        *(float4*)&out[(size_t)(m0 + cr) * 256 + c0 + q4] = w;
    } else if (bx < FR_TRUNK) {
        // ---- transpose unknow_feats -> gA1 H/L, float4 + packed split ----
        float (*tile)[33] = (float(*)[33])sbuf;
        int idx = bx - FR_TRKF;
        int n0 = (idx & 255) * 32, c0 = ((idx >> 8) & 7) * 32, b = idx >> 11;
        int cr = t >> 3, q4 = (t & 7) * 4;
        const float* in = uf + (size_t)b * 256 * NQ;
        float4 v = *(const float4*)&in[(size_t)(c0 + cr) * NQ + n0 + q4];
        tile[cr][q4 + 0] = v.x; tile[cr][q4 + 1] = v.y;
        tile[cr][q4 + 2] = v.z; tile[cr][q4 + 3] = v.w;
        __syncthreads();
        uint2 hp, lp;
        split2(tile[q4 + 0][cr], tile[q4 + 1][cr], hp.x, lp.x);
        split2(tile[q4 + 2][cr], tile[q4 + 3][cr], hp.y, lp.y);
        size_t row = ((size_t)b * NQ + n0 + cr) * 1024;
        *(uint2*)&gA1[row + 256 + c0 + q4] = hp;
        *(uint2*)&gA1[row + 768 + c0 + q4] = lp;
    } else if (bx < FR_EXPW) {
        int i = (bx - FR_TRUNK) * 256 + t;
        if (i < 256 * 512) {
            int n = i >> 9, k = i & 511;
            gW1[n * 512 + k] = __half_as_ushort(__float2half_rn(w1[i]));
        }
        if (i < 256 * 256) {
            int n = i >> 8, k = i & 255;
            gW2[n * 256 + k] = __half_as_ushort(__float2half_rn(w2[i]));
        }
    } else {
        int i = (bx - FR_EXPW) * 256 + t;
        if (i < 256) {
            float s1 = gg1[i] * rsqrtf(vv1[i] + 1e-5f);
            g_al1[i] = s1;
            g_be1[i] = s1 * (cb1[i] - mm1[i]) + bb1[i];
            float s2 = gg2[i] * rsqrtf(vv2[i] + 1e-5f);
            g_al2[i] = s2;
            g_be2[i] = s2 * (cb2[i] - mm2[i]) + bb2[i];
        }
        if (i < 32) {
            float s = 0.f;
            const float* c = cw + i * 256;
            for (int d = 0; d < 256; d++) s += c[d] * c[d];
            g_c2[i] = s;
        }
        if (i < 8 * 32) g_sumA[i] = 0.f;
        if (i < 8 * 8192) g_E[i] = 0.f;
    }
}

// ---------------- interpolate: 8 floats/thread, packed converts ----------------
__global__ __launch_bounds__(256) void interp_kernel()
{
    int bz = blockIdx.y, t = threadIdx.x;
    int n = blockIdx.x * 8 + (t >> 5);
    int d = (t & 31) * 8;
    size_t base = ((size_t)bz * NQ + n) * 3;
    int i0 = g_idx[base], i1 = g_idx[base + 1], i2 = g_idx[base + 2];
    float w0 = g_wgt[base], w1 = g_wgt[base + 1], w2 = g_wgt[base + 2];
    const float* kf = g_kfT + (size_t)bz * MK * 256;
    const float* r0 = &kf[(size_t)i0 * 256 + d];
    const float* r1 = &kf[(size_t)i1 * 256 + d];
    const float* r2 = &kf[(size_t)i2 * 256 + d];
    float4 a0 = *(const float4*)r0,       a1 = *(const float4*)(r0 + 4);
    float4 b0 = *(const float4*)r1,       b1 = *(const float4*)(r1 + 4);
    float4 c0 = *(const float4*)r2,       c1 = *(const float4*)(r2 + 4);
    float v[8];
    v[0] = w0 * a0.x + w1 * b0.x + w2 * c0.x;
    v[1] = w0 * a0.y + w1 * b0.y + w2 * c0.y;
    v[2] = w0 * a0.z + w1 * b0.z + w2 * c0.z;
    v[3] = w0 * a0.w + w1 * b0.w + w2 * c0.w;
    v[4] = w0 * a1.x + w1 * b1.x + w2 * c1.x;
    v[5] = w0 * a1.y + w1 * b1.y + w2 * c1.y;
    v[6] = w0 * a1.z + w1 * b1.z + w2 * c1.z;
    v[7] = w0 * a1.w + w1 * b1.w + w2 * c1.w;
    uintT hp[4], lp[4];
#pragma unroll
    for (int j = 0; j < 4; j++)
        split2(v[2 * j], v[2 * j + 1], hp[j], lp[j]);
    size_t row = ((size_t)bz * NQ + n) * 1024;
    *(uint4*)&gA1[row + d]       = *(uint4*)hp;
    *(uint4*)&gA1[row + 512 + d] = *(uint4*)lp;
}

// ===================== HMMA GEMM: shared-B fp16 split =====================
template <int L>
__global__ __launch_bounds__(256) void gemm_mma()
{
    constexpr int K   = (L == 1) ? 512 : 256;
    constexpr int NCH = K / 32;
    constexpr int KA  = 2 * K;
    const ushortT* Ag = (L == 1) ? gA1 : gA2;
    const ushortT* Wg = (L == 1) ? gW1 : gW2;
    const float* alpha = (L == 1) ? g_al1 : g_al2;
    const float* beta  = (L == 1) ? g_be1 : g_be2;

    extern __shared__ __align__(16) ushortT dyn[];
    ushortT* sAH = dyn;
    ushortT* sAL = dyn + 3 * 4096;
    ushortT* sB  = dyn + 6 * 4096;
    float* s_al = (float*)(dyn + 9 * 4096);
    float* s_be = s_al + 128;

    int tid = threadIdx.x, wid = tid >> 5, lane = tid & 31;
    int bn = blockIdx.x * 128, bm = blockIdx.y * 128;
    if (tid < 128) { s_al[tid] = alpha[bn + tid]; s_be[tid] = beta[bn + tid]; }

    uint32_t sAHb = smem_to_u32(sAH);
    uint32_t sALb = smem_to_u32(sAL);
    uint32_t sBb  = smem_to_u32(sB);

    int lr = tid >> 1;
    int ls = (tid & 1) * 2;
    uint32_t off0 = lr * 64 + (((ls)     ^ (lr & 3)) << 4);
    uint32_t off1 = lr * 64 + (((ls + 1) ^ (lr & 3)) << 4);

    const ushortT* ArowH = Ag + (size_t)(bm + lr) * KA;
    const ushortT* ArowL = ArowH + K;
    const ushortT* Wrow  = Wg + (size_t)(bn + lr) * K;

#define LOAD_CHUNK(p, st) do { \
    int _col = (p) * 32; \
    uint32_t _ah = sAHb + (st) * 8192; \
    uint32_t _al = sALb + (st) * 8192; \
    uint32_t _ws = sBb  + (st) * 8192; \
    CP_ASYNC16(_ah + off0, ArowH + _col + ls * 8); \
    CP_ASYNC16(_ah + off1, ArowH + _col + ls * 8 + 8); \
    CP_ASYNC16(_al + off0, ArowL + _col + ls * 8); \
    CP_ASYNC16(_al + off1, ArowL + _col + ls * 8 + 8); \
    CP_ASYNC16(_ws + off0, Wrow + _col + ls * 8); \
    CP_ASYNC16(_ws + off1, Wrow + _col + ls * 8 + 8); \
    CP_COMMIT(); } while (0)

    LOAD_CHUNK(0, 0);
    LOAD_CHUNK(1, 1);

    float c[2][8][4];
#pragma unroll
    for (int i = 0; i < 2; i++)
#pragma unroll
        for (int j = 0; j < 8; j++)
#pragma unroll
            for (int q = 0; q < 4; q++) c[i][j][q] = 0.f;

    int wm = wid & 3, wn = wid >> 2;

    int st = 0, stn = 2;
    for (int kc = 0; kc < NCH; kc++) {
        CP_WAIT1();
        __syncthreads();
        int kn = kc + 2;
        if (kn < NCH) LOAD_CHUNK(kn, stn);
        uint32_t aHBase = sAHb + st * 8192;
        uint32_t aLBase = sALb + st * 8192;
        uint32_t bBase  = sBb  + st * 8192;
#pragma unroll
        for (int kk = 0; kk < 2; kk++) {
            uint32_t ah[2][4], al[2][4], bf[8][2];
#pragma unroll
            for (int mt = 0; mt < 2; mt++) {
                int r = wm * 32 + mt * 16 + (lane & 15);
                int s = kk * 2 + (lane >> 4);
                uint32_t ro = r * 64 + ((s ^ (r & 3)) << 4);
                ldsm4(ah[mt][0], ah[mt][1], ah[mt][2], ah[mt][3], aHBase + ro);
                ldsm4(al[mt][0], al[mt][1], al[mt][2], al[mt][3], aLBase + ro);
            }
#pragma unroll
            for (int np = 0; np < 4; np++) {
                int r = wn * 64 + np * 16 + (lane & 7) + ((lane >> 4) << 3);
                int s = kk * 2 + ((lane >> 3) & 1);
                ldsm4(bf[2 * np][0], bf[2 * np][1], bf[2 * np + 1][0], bf[2 * np + 1][1],
                      bBase + r * 64 + ((s ^ (r & 3)) << 4));
            }
#pragma unroll
            for (int mt = 0; mt < 2; mt++)
#pragma unroll
                for (int nt = 0; nt < 8; nt++)
                    mma16816(c[mt][nt], ah[mt], bf[nt]);
#pragma unroll
            for (int mt = 0; mt < 2; mt++)
#pragma unroll
                for (int nt = 0; nt < 8; nt++)
                    mma16816(c[mt][nt], al[mt], bf[nt]);
        }
        st  = (st == 2)  ? 0 : st + 1;
        stn = (stn == 2) ? 0 : stn + 1;
    }
#undef LOAD_CHUNK

#pragma unroll
    for (int mt = 0; mt < 2; mt++) {
#pragma unroll
        for (int nt = 0; nt < 8; nt++) {
            int cl = wn * 64 + nt * 8 + (lane & 3) * 2;
            int gcol = bn + cl;
            int rl = wm * 32 + mt * 16 + (lane >> 2);
#pragma unroll
            for (int hh = 0; hh < 2; hh++) {
                int grow = bm + rl + hh * 8;
                float v0 = fmaxf(fmaf(c[mt][nt][hh * 2 + 0], s_al[cl],     s_be[cl]),     0.f);
                float v1 = fmaxf(fmaf(c[mt][nt][hh * 2 + 1], s_al[cl + 1], s_be[cl + 1]), 0.f);
                if (L == 1) {
                    uintT hp, lp;
                    split2(v0, v1, hp, lp);
                    *(uintT*)&gA2[(size_t)grow * 512 + gcol]       = hp;
                    *(uintT*)&gA2[(size_t)grow * 512 + 256 + gcol] = lp;
                } else {
                    float2 o = make_float2(v0, v1);
                    *(float2*)&g_h[(size_t)grow * 256 + gcol] = o;
                }
            }
        }
    }
}

// ===================== encoding =====================
#define XSTR  260
#define CWSTR 36
#define ASTR  36
#define ENC_SMEM ((64 * XSTR + 256 * CWSTR + 64 * ASTR + 64) * 4)

__global__ __launch_bounds__(256) void encoding_kernel(const float* __restrict__ cw,
                                                       const float* __restrict__ scale)
{
    extern __shared__ float es[];
    float* sX  = es;
    float* cwT = es + 64 * XSTR;
    float* sA  = cwT + 256 * CWSTR;
    float* sXn = sA + 64 * ASTR;

    int bz = blockIdx.y, n0 = blockIdx.x * 64, t = threadIdx.x;
    const float* Xb = g_h + ((size_t)bz * NQ + n0) * 256;

    for (int i = t; i < 64 * 64; i += 256) {
        int p = i >> 6, d4 = i & 63;
        *(float4*)&sX[p * XSTR + d4 * 4] = *(const float4*)&Xb[(size_t)p * 256 + d4 * 4];
    }
    for (int i = t; i < 32 * 256; i += 256) {
        int k = i >> 8, d = i & 255;
        cwT[d * CWSTR + k] = cw[i];
    }
    __syncthreads();

    {
        int pg = t >> 3, kg = t & 7;
        const float* xr0 = sX + (2 * pg) * XSTR;
        const float* xr1 = xr0 + XSTR;
        const float* cwr = cwT + kg * 4;
        float a0[4] = {0.f, 0.f, 0.f, 0.f}, a1[4] = {0.f, 0.f, 0.f, 0.f};
        float xn0 = 0.f, xn1 = 0.f;
#pragma unroll 4
        for (int d = 0; d < 256; d += 4) {
            float4 x0 = *(const float4*)&xr0[d];
            float4 x1 = *(const float4*)&xr1[d];
            xn0 = fmaf(x0.x, x0.x, xn0); xn0 = fmaf(x0.y, x0.y, xn0);
            xn0 = fmaf(x0.z, x0.z, xn0); xn0 = fmaf(x0.w, x0.w, xn0);
            xn1 = fmaf(x1.x, x1.x, xn1); xn1 = fmaf(x1.y, x1.y, xn1);
            xn1 = fmaf(x1.z, x1.z, xn1); xn1 = fmaf(x1.w, x1.w, xn1);
            float xv0[4] = {x0.x, x0.y, x0.z, x0.w};
            float xv1[4] = {x1.x, x1.y, x1.z, x1.w};
#pragma unroll
            for (int dd = 0; dd < 4; dd++) {
                float4 c4 = *(const float4*)&cwr[(d + dd) * CWSTR];
                a0[0] = fmaf(xv0[dd], c4.x, a0[0]);
                a0[1] = fmaf(xv0[dd], c4.y, a0[1]);
                a0[2] = fmaf(xv0[dd], c4.z, a0[2]);
                a0[3] = fmaf(xv0[dd], c4.w, a0[3]);
                a1[0] = fmaf(xv1[dd], c4.x, a1[0]);
                a1[1] = fmaf(xv1[dd], c4.y, a1[1]);
                a1[2] = fmaf(xv1[dd], c4.z, a1[2]);
                a1[3] = fmaf(xv1[dd], c4.w, a1[3]);
            }
        }
        int p0 = 2 * pg, ks = kg * 4;
#pragma unroll
        for (int j = 0; j < 4; j++) {
            sA[p0 * ASTR + ks + j]       = a0[j];
            sA[(p0 + 1) * ASTR + ks + j] = a1[j];
        }
        if (kg == 0) { sXn[p0] = xn0; sXn[p0 + 1] = xn1; }
    }
    __syncthreads();

    {
        int warp = t >> 5, lane = t & 31;
        float sc = scale[lane], c2v = g_c2[lane];
        for (int pi = 0; pi < 8; pi++) {
            int p = warp * 8 + pi;
            float sl = sc * (sXn[p] - 2.f * sA[p * ASTR + lane] + c2v);
            float mx = sl;
#pragma unroll
            for (int o = 16; o > 0; o >>= 1) mx = fmaxf(mx, __shfl_xor_sync(0xffffffffu, mx, o));
            float e = __expf(sl - mx);
            float se = e;
#pragma unroll
            for (int o = 16; o > 0; o >>= 1) se += __shfl_xor_sync(0xffffffffu, se, o);
            sA[p * ASTR + lane] = e / se;
        }
    }
    __syncthreads();
    if (t < 32) {
        float s = 0.f;
        for (int p = 0; p < 64; p++) s += sA[p * ASTR + t];
        atomicAdd(&g_sumA[bz * 32 + t], s);
    }

    float acc[32];
#pragma unroll
    for (int k = 0; k < 32; k++) acc[k] = 0.f;
    for (int p = 0; p < 64; p++) {
        float x = sX[p * XSTR + t];
#pragma unroll
        for (int kq = 0; kq < 8; kq++) {
            float4 a4 = *(const float4*)&sA[p * ASTR + kq * 4];
            acc[kq * 4 + 0] = fmaf(a4.x, x, acc[kq * 4 + 0]);
            acc[kq * 4 + 1] = fmaf(a4.y, x, acc[kq * 4 + 1]);
            acc[kq * 4 + 2] = fmaf(a4.z, x, acc[kq * 4 + 2]);
            acc[kq * 4 + 3] = fmaf(a4.w, x, acc[kq * 4 + 3]);
        }
    }
    float* Eb = g_E + (size_t)bz * 8192;
#pragma unroll
    for (int k = 0; k < 32; k++) atomicAdd(&Eb[k * 256 + t], acc[k]);
}

__global__ __launch_bounds__(256) void enc_fin_kernel(const float* __restrict__ cw)
{
    __shared__ float red[256];
    int bz = blockIdx.x, t = threadIdx.x;
    float ss = 0.f;
    for (int j = t; j < 8192; j += 256) {
        float v = g_E[bz * 8192 + j] - g_sumA[bz * 32 + (j >> 8)] * cw[j];
        v = fmaxf(v, 0.f);
        g_En[bz * 8192 + j] = v;
        ss += v * v;
    }
    red[t] = ss;
    __syncthreads();
    for (int s = 128; s > 0; s >>= 1) {
        if (t < s) red[t] += red[t + s];
        __syncthreads();
    }
    float rinv = 1.f / fmaxf(sqrtf(red[0]), 1e-12f);
    for (int j = t; j < 8192; j += 256) g_En[bz * 8192 + j] *= rinv;
}

__global__ __launch_bounds__(256) void ctx_gemv_kernel(const float* __restrict__ lin_w,
                                                       const float* __restrict__ lin_b)
{
    __shared__ float red[8][256];
    int o = blockIdx.x, t = threadIdx.x;
    float acc[8];
#pragma unroll
    for (int b = 0; b < 8; b++) acc[b] = 0.f;
    const float* wrow = lin_w + (size_t)o * 8192;
    for (int j = t; j < 8192; j += 256) {
        float w = wrow[j];
#pragma unroll
        for (int b = 0; b < 8; b++) acc[b] = fmaf(w, g_En[b * 8192 + j], acc[b]);
    }
#pragma unroll
    for (int b = 0; b < 8; b++) red[b][t] = acc[b];
    __syncthreads();
    for (int s = 128; s > 0; s >>= 1) {
        if (t < s) {
#pragma unroll
            for (int b = 0; b < 8; b++) red[b][t] += red[b][t + s];
        }
        __syncthreads();
    }
    if (t < 8) {
        float z = red[t][0] + lin_b[o];
        g_ctx[t * 256 + o] = 1.f / (1.f + expf(-z));
    }
}

// ---------------- final: float4 tiled transpose + ctx scale ----------------
__global__ __launch_bounds__(256) void final_kernel(float* __restrict__ out)
{
    __shared__ float tile[32][33];
    int bz = blockIdx.z;
    int d0 = blockIdx.x * 32, n0 = blockIdx.y * 32;
    int t = threadIdx.x;
    int nr = t >> 3, q4 = (t & 7) * 4;
    const float* h = g_h + (size_t)bz * NQ * 256;
    float4 v = *(const float4*)&h[(size_t)(n0 + nr) * 256 + d0 + q4];
    tile[q4 + 0][nr] = v.x; tile[q4 + 1][nr] = v.y;
    tile[q4 + 2][nr] = v.z; tile[q4 + 3][nr] = v.w;
    __syncthreads();
    int dr = nr;
    float cx = g_ctx[bz * 256 + d0 + dr];
    float4 w = make_float4(tile[dr][q4 + 0] * cx, tile[dr][q4 + 1] * cx,
                           tile[dr][q4 + 2] * cx, tile[dr][q4 + 3] * cx);
    float* ob = out + (size_t)bz * 256 * NQ;
    *(float4*)&ob[(size_t)(d0 + dr) * NQ + n0 + q4] = w;
}

// ===================== launcher =====================
extern "C" void kernel_launch(void* const* d_in, const int* in_sizes, int n_in,
                              void* d_out, int out_size)
{
    (void)in_sizes; (void)n_in; (void)out_size;
    const float* unknown      = (const float*)d_in[0];
    const float* known        = (const float*)d_in[1];
    const float* unknow_feats = (const float*)d_in[2];
    const float* known_feats  = (const float*)d_in[3];
    const float* conv_w1 = (const float*)d_in[4];
    const float* conv_b1 = (const float*)d_in[5];
    const float* bn_g1 = (const float*)d_in[6];
    const float* bn_b1 = (const float*)d_in[7];
    const float* bn_m1 = (const float*)d_in[8];
    const float* bn_v1 = (const float*)d_in[9];
    const float* conv_w2 = (const float*)d_in[10];
    const float* conv_b2 = (const float*)d_in[11];
    const float* bn_g2 = (const float*)d_in[12];
    const float* bn_b2 = (const float*)d_in[13];
    const float* bn_m2 = (const float*)d_in[14];
    const float* bn_v2 = (const float*)d_in[15];
    const float* enc_cw    = (const float*)d_in[16];
    const float* enc_scale = (const float*)d_in[17];
    const float* lin_w     = (const float*)d_in[18];
    const float* lin_b     = (const float*)d_in[19];
    float* out = (float*)d_out;

    const int SMEMSZ = 9 * 8192 + 1024;
    static int attr_done = 0;
    if (!attr_done) {
        cudaFuncSetAttribute(gemm_mma<1>, cudaFuncAttributeMaxDynamicSharedMemorySize, SMEMSZ);
        cudaFuncSetAttribute(gemm_mma<2>, cudaFuncAttributeMaxDynamicSharedMemorySize, SMEMSZ);
        cudaFuncSetAttribute(encoding_kernel, cudaFuncAttributeMaxDynamicSharedMemorySize, ENC_SMEM);
        attr_done = 1;
    }

    front_kernel<<<FR_TOTAL, 256>>>(unknown, known, unknow_feats, known_feats,
                                    conv_w1, conv_w2,
                                    conv_b1, bn_g1, bn_b1, bn_m1, bn_v1,
                                    conv_b2, bn_g2, bn_b2, bn_m2, bn_v2, enc_cw);
    interp_kernel<<<dim3(NQ / 8, B_), 256>>>();
    gemm_mma<1><<<dim3(2, 512), 256, SMEMSZ>>>();
    gemm_mma<2><<<dim3(2, 512), 256, SMEMSZ>>>();
    encoding_kernel<<<dim3(NQ / 64, B_), 256, ENC_SMEM>>>(enc_cw, enc_scale);
    enc_fin_kernel<<<B_, 256>>>(enc_cw);
    ctx_gemv_kernel<<<256, 256>>>(lin_w, lin_b);
    final_kernel<<<dim3(8, NQ / 32, B_), 256>>>(out);
}

// round 17
// speedup vs baseline: 1.9432x; 1.1593x over previous
#include <cuda_runtime.h>
#include <cuda_fp16.h>
#include <math.h>
#include <stdint.h>

#define B_   8
#define NQ   8192
#define MK   2048
typedef unsigned short ushortT;
typedef unsigned int   uintT;

// ===================== helpers =====================
__device__ __forceinline__ uint32_t smem_to_u32(const void* p) {
    uint32_t a;
    asm("{ .reg .u64 t; cvta.to.shared.u64 t, %1; cvt.u32.u64 %0, t; }" : "=r"(a) : "l"(p));
    return a;
}
#define CP_ASYNC16(s, g) \
    asm volatile("cp.async.cg.shared.global [%0], [%1], 16;" :: "r"(s), "l"(g))
#define CP_COMMIT() asm volatile("cp.async.commit_group;")
#define CP_WAIT1()  asm volatile("cp.async.wait_group 1;")

__device__ __forceinline__ void ldsm4(uint32_t& r0, uint32_t& r1, uint32_t& r2, uint32_t& r3,
                                      uint32_t addr) {
    asm volatile("ldmatrix.sync.aligned.m8n8.x4.shared.b16 {%0,%1,%2,%3}, [%4];"
                 : "=r"(r0), "=r"(r1), "=r"(r2), "=r"(r3) : "r"(addr));
}
__device__ __forceinline__ void mma16816(float* d, const uint32_t* a, const uint32_t* b) {
    asm volatile(
        "mma.sync.aligned.m16n8k16.row.col.f32.f16.f16.f32 "
        "{%0,%1,%2,%3}, {%4,%5,%6,%7}, {%8,%9}, {%0,%1,%2,%3};"
        : "+f"(d[0]), "+f"(d[1]), "+f"(d[2]), "+f"(d[3])
        : "r"(a[0]), "r"(a[1]), "r"(a[2]), "r"(a[3]), "r"(b[0]), "r"(b[1]));
}

// pack 2 fp32 -> fp16x2 (RNE)
__device__ __forceinline__ uintT pack2(float a, float b) {
    __half2 h2 = __floats2half2_rn(a, b);
    return *(uintT*)&h2;
}

__device__ __forceinline__ void ins3(float& d0, int& i0, float& d1, int& i1,
                                     float& d2, int& i2, float dd, int m) {
    if (dd < d2) {
        if (dd < d1) {
            d2 = d1; i2 = i1;
            if (dd < d0) { d1 = d0; i1 = i0; d0 = dd; i0 = m; }
            else          { d1 = dd; i1 = m; }
        } else { d2 = dd; i2 = m; }
    }
}

// ===================== scratch =====================
__device__ ushortT gA1[(size_t)8 * 8192 * 512];   // fp16 activations (H only)
__device__ ushortT gA2[(size_t)8 * 8192 * 256];
__device__ ushortT gW1[256 * 512];                // fp16 weights
__device__ ushortT gW2[256 * 256];
__device__ float g_h  [(size_t)8 * 8192 * 256];
__device__ float g_kfT[(size_t)8 * 2048 * 256];
__device__ int   g_idx[8 * 8192 * 3];
__device__ float g_wgt[8 * 8192 * 3];
__device__ float g_E  [8 * 8192];
__device__ float g_En [8 * 8192];
__device__ float g_sumA[8 * 32];
__device__ float g_ctx[8 * 256];
__device__ float g_al1[256], g_be1[256], g_al2[256], g_be2[256];
__device__ float g_c2[32];

// ===================== fused front kernel =====================
#define FR_3NN    2048
#define FR_TRKF   6144
#define FR_TRUNK  22528
#define FR_EXPW   23040
#define FR_TOTAL  23296
#define CHPAD8    257

__global__ __launch_bounds__(256) void front_kernel(
    const float* __restrict__ unknown, const float* __restrict__ known,
    const float* __restrict__ uf, const float* __restrict__ kf,
    const float* __restrict__ w1, const float* __restrict__ w2,
    const float* __restrict__ cb1, const float* __restrict__ gg1,
    const float* __restrict__ bb1, const float* __restrict__ mm1,
    const float* __restrict__ vv1,
    const float* __restrict__ cb2, const float* __restrict__ gg2,
    const float* __restrict__ bb2, const float* __restrict__ mm2,
    const float* __restrict__ vv2,
    const float* __restrict__ cw)
{
    __shared__ __align__(16) char sbuf[8 * CHPAD8 * 16];
    int bx = blockIdx.x;
    int t  = threadIdx.x;

    if (bx < FR_3NN) {
        float4* kp = (float4*)sbuf;
        int bz = bx >> 8;
        int q  = (bx & 255) * 32 + (t >> 3);
        int ck = t & 7;

        const float* kb = known + (size_t)bz * MK * 3;
        for (int i = t; i < MK; i += 256) {
            float kx = kb[i * 3 + 0];
            float ky = kb[i * 3 + 1];
            float kz = kb[i * 3 + 2];
            kp[(i >> 8) * CHPAD8 + (i & 255)] = make_float4(kx, ky, kz, kx * kx + ky * ky + kz * kz);
        }
        __syncthreads();

        const float* u = unknown + ((size_t)bz * NQ + q) * 3;
        float ux = u[0], uy = u[1], uz = u[2];
        float x2 = ux * ux + uy * uy + uz * uz;
        float mux = -2.f * ux, muy = -2.f * uy, muz = -2.f * uz;

        float d0 = 1e30f, d1 = 1e30f, d2 = 1e30f;
        int   i0 = 0, i1 = 0, i2 = 0;
        const float4* base = kp + ck * CHPAD8;
        int m0 = ck * 256;
#pragma unroll 4
        for (int j = 0; j < 256; j++) {
            float4 p = base[j];
            float dd = fmaf(mux, p.x, p.w);
            dd = fmaf(muy, p.y, dd);
            dd = fmaf(muz, p.z, dd);
            ins3(d0, i0, d1, i1, d2, i2, dd, m0 + j);
        }

#pragma unroll
        for (int off = 1; off <= 4; off <<= 1) {
            float e0 = __shfl_xor_sync(0xffffffffu, d0, off);
            float e1 = __shfl_xor_sync(0xffffffffu, d1, off);
            float e2 = __shfl_xor_sync(0xffffffffu, d2, off);
            int   j0 = __shfl_xor_sync(0xffffffffu, i0, off);
            int   j1 = __shfl_xor_sync(0xffffffffu, i1, off);
            int   j2 = __shfl_xor_sync(0xffffffffu, i2, off);
            ins3(d0, i0, d1, i1, d2, i2, e0, j0);
            ins3(d0, i0, d1, i1, d2, i2, e1, j1);
            ins3(d0, i0, d1, i1, d2, i2, e2, j2);
        }

        if (ck == 0) {
            float r0 = 1.f / (sqrtf(fmaxf(d0 + x2, 1e-12f)) + 1e-8f);
            float r1 = 1.f / (sqrtf(fmaxf(d1 + x2, 1e-12f)) + 1e-8f);
            float r2 = 1.f / (sqrtf(fmaxf(d2 + x2, 1e-12f)) + 1e-8f);
            float rs = 1.f / (r0 + r1 + r2);
            size_t base2 = ((size_t)bz * NQ + q) * 3;
            g_idx[base2 + 0] = i0; g_idx[base2 + 1] = i1; g_idx[base2 + 2] = i2;
            g_wgt[base2 + 0] = r0 * rs; g_wgt[base2 + 1] = r1 * rs; g_wgt[base2 + 2] = r2 * rs;
        }
    } else if (bx < FR_TRKF) {
        float (*tile)[33] = (float(*)[33])sbuf;
        int idx = bx - FR_3NN;
        int m0 = (idx & 63) * 32, c0 = ((idx >> 6) & 7) * 32, b = idx >> 9;
        int cr = t >> 3, q4 = (t & 7) * 4;
        const float* in = kf + (size_t)b * 256 * MK;
        float4 v = *(const float4*)&in[(size_t)(c0 + cr) * MK + m0 + q4];
        tile[cr][q4 + 0] = v.x; tile[cr][q4 + 1] = v.y;
        tile[cr][q4 + 2] = v.z; tile[cr][q4 + 3] = v.w;
        __syncthreads();
        float* out = g_kfT + (size_t)b * MK * 256;
        float4 w = make_float4(tile[q4 + 0][cr], tile[q4 + 1][cr],
                               tile[q4 + 2][cr], tile[q4 + 3][cr]);
        *(float4*)&out[(size_t)(m0 + cr) * 256 + c0 + q4] = w;
    } else if (bx < FR_TRUNK) {
        float (*tile)[33] = (float(*)[33])sbuf;
        int idx = bx - FR_TRKF;
        int n0 = (idx & 255) * 32, c0 = ((idx >> 8) & 7) * 32, b = idx >> 11;
        int cr = t >> 3, q4 = (t & 7) * 4;
        const float* in = uf + (size_t)b * 256 * NQ;
        float4 v = *(const float4*)&in[(size_t)(c0 + cr) * NQ + n0 + q4];
        tile[cr][q4 + 0] = v.x; tile[cr][q4 + 1] = v.y;
        tile[cr][q4 + 2] = v.z; tile[cr][q4 + 3] = v.w;
        __syncthreads();
        uint2 hp = make_uint2(pack2(tile[q4 + 0][cr], tile[q4 + 1][cr]),
                              pack2(tile[q4 + 2][cr], tile[q4 + 3][cr]));
        size_t row = ((size_t)b * NQ + n0 + cr) * 512;
        *(uint2*)&gA1[row + 256 + c0 + q4] = hp;
    } else if (bx < FR_EXPW) {
        int i = (bx - FR_TRUNK) * 256 + t;
        if (i < 256 * 512) {
            int n = i >> 9, k = i & 511;
            gW1[n * 512 + k] = __half_as_ushort(__float2half_rn(w1[i]));
        }
        if (i < 256 * 256) {
            int n = i >> 8, k = i & 255;
            gW2[n * 256 + k] = __half_as_ushort(__float2half_rn(w2[i]));
        }
    } else {
        int i = (bx - FR_EXPW) * 256 + t;
        if (i < 256) {
            float s1 = gg1[i] * rsqrtf(vv1[i] + 1e-5f);
            g_al1[i] = s1;
            g_be1[i] = s1 * (cb1[i] - mm1[i]) + bb1[i];
            float s2 = gg2[i] * rsqrtf(vv2[i] + 1e-5f);
            g_al2[i] = s2;
            g_be2[i] = s2 * (cb2[i] - mm2[i]) + bb2[i];
        }
        if (i < 32) {
            float s = 0.f;
            const float* c = cw + i * 256;
            for (int d = 0; d < 256; d++) s += c[d] * c[d];
            g_c2[i] = s;
        }
        if (i < 8 * 32) g_sumA[i] = 0.f;
        if (i < 8 * 8192) g_E[i] = 0.f;
    }
}

// ---------------- interpolate: 8 floats/thread, fp16 H only ----------------
__global__ __launch_bounds__(256) void interp_kernel()
{
    int bz = blockIdx.y, t = threadIdx.x;
    int n = blockIdx.x * 8 + (t >> 5);
    int d = (t & 31) * 8;
    size_t base = ((size_t)bz * NQ + n) * 3;
    int i0 = g_idx[base], i1 = g_idx[base + 1], i2 = g_idx[base + 2];
    float w0 = g_wgt[base], w1 = g_wgt[base + 1], w2 = g_wgt[base + 2];
    const float* kf = g_kfT + (size_t)bz * MK * 256;
    const float* r0 = &kf[(size_t)i0 * 256 + d];
    const float* r1 = &kf[(size_t)i1 * 256 + d];
    const float* r2 = &kf[(size_t)i2 * 256 + d];
    float4 a0 = *(const float4*)r0,       a1 = *(const float4*)(r0 + 4);
    float4 b0 = *(const float4*)r1,       b1 = *(const float4*)(r1 + 4);
    float4 c0 = *(const float4*)r2,       c1 = *(const float4*)(r2 + 4);
    float v[8];
    v[0] = w0 * a0.x + w1 * b0.x + w2 * c0.x;
    v[1] = w0 * a0.y + w1 * b0.y + w2 * c0.y;
    v[2] = w0 * a0.z + w1 * b0.z + w2 * c0.z;
    v[3] = w0 * a0.w + w1 * b0.w + w2 * c0.w;
    v[4] = w0 * a1.x + w1 * b1.x + w2 * c1.x;
    v[5] = w0 * a1.y + w1 * b1.y + w2 * c1.y;
    v[6] = w0 * a1.z + w1 * b1.z + w2 * c1.z;
    v[7] = w0 * a1.w + w1 * b1.w + w2 * c1.w;
    uintT hp[4];
#pragma unroll
    for (int j = 0; j < 4; j++)
        hp[j] = pack2(v[2 * j], v[2 * j + 1]);
    size_t row = ((size_t)bz * NQ + n) * 512;
    *(uint4*)&gA1[row + d] = *(uint4*)hp;
}

// ===================== HMMA GEMM: plain fp16, 32x64 warp tiles =====================
// CTA 128x128xK, 8 warps (4m x 2n), 3-stage cp.async (A 8KB + B 8KB per stage).
template <int L>
__global__ __launch_bounds__(256) void gemm_mma()
{
    constexpr int K   = (L == 1) ? 512 : 256;
    constexpr int NCH = K / 32;          // 16 / 8
    const ushortT* Ag = (L == 1) ? gA1 : gA2;
    const ushortT* Wg = (L == 1) ? gW1 : gW2;
    const float* alpha = (L == 1) ? g_al1 : g_al2;
    const float* beta  = (L == 1) ? g_be1 : g_be2;

    extern __shared__ __align__(16) ushortT dyn[];
    ushortT* sA = dyn;                   // 3 stages x 4096 ushort
    ushortT* sB = dyn + 3 * 4096;
    float* s_al = (float*)(dyn + 6 * 4096);
    float* s_be = s_al + 128;

    int tid = threadIdx.x, wid = tid >> 5, lane = tid & 31;
    int bn = blockIdx.x * 128, bm = blockIdx.y * 128;
    if (tid < 128) { s_al[tid] = alpha[bn + tid]; s_be[tid] = beta[bn + tid]; }

    uint32_t sAb = smem_to_u32(sA);
    uint32_t sBb = smem_to_u32(sB);

    int lr = tid >> 1;
    int ls = (tid & 1) * 2;
    uint32_t off0 = lr * 64 + (((ls)     ^ (lr & 3)) << 4);
    uint32_t off1 = lr * 64 + (((ls + 1) ^ (lr & 3)) << 4);

    const ushortT* Arow = Ag + (size_t)(bm + lr) * K;
    const ushortT* Wrow = Wg + (size_t)(bn + lr) * K;

#define LOAD_CHUNK(p, st) do { \
    int _col = (p) * 32; \
    uint32_t _as = sAb + (st) * 8192; \
    uint32_t _ws = sBb + (st) * 8192; \
    CP_ASYNC16(_as + off0, Arow + _col + ls * 8); \
    CP_ASYNC16(_as + off1, Arow + _col + ls * 8 + 8); \
    CP_ASYNC16(_ws + off0, Wrow + _col + ls * 8); \
    CP_ASYNC16(_ws + off1, Wrow + _col + ls * 8 + 8); \
    CP_COMMIT(); } while (0)

    LOAD_CHUNK(0, 0);
    LOAD_CHUNK(1, 1);

    float c[2][8][4];
#pragma unroll
    for (int i = 0; i < 2; i++)
#pragma unroll
        for (int j = 0; j < 8; j++)
#pragma unroll
            for (int q = 0; q < 4; q++) c[i][j][q] = 0.f;

    int wm = wid & 3, wn = wid >> 2;

    int st = 0, stn = 2;
    for (int kc = 0; kc < NCH; kc++) {
        CP_WAIT1();
        __syncthreads();
        int kn = kc + 2;
        if (kn < NCH) LOAD_CHUNK(kn, stn);
        uint32_t aBase = sAb + st * 8192;
        uint32_t bBase = sBb + st * 8192;
#pragma unroll
        for (int kk = 0; kk < 2; kk++) {
            uint32_t af[2][4], bf[8][2];
#pragma unroll
            for (int mt = 0; mt < 2; mt++) {
                int r = wm * 32 + mt * 16 + (lane & 15);
                int s = kk * 2 + (lane >> 4);
                ldsm4(af[mt][0], af[mt][1], af[mt][2], af[mt][3],
                      aBase + r * 64 + ((s ^ (r & 3)) << 4));
            }
#pragma unroll
            for (int np = 0; np < 4; np++) {
                int r = wn * 64 + np * 16 + (lane & 7) + ((lane >> 4) << 3);
                int s = kk * 2 + ((lane >> 3) & 1);
                ldsm4(bf[2 * np][0], bf[2 * np][1], bf[2 * np + 1][0], bf[2 * np + 1][1],
                      bBase + r * 64 + ((s ^ (r & 3)) << 4));
            }
#pragma unroll
            for (int mt = 0; mt < 2; mt++)
#pragma unroll
                for (int nt = 0; nt < 8; nt++)
                    mma16816(c[mt][nt], af[mt], bf[nt]);
        }
        st  = (st == 2)  ? 0 : st + 1;
        stn = (stn == 2) ? 0 : stn + 1;
    }
#undef LOAD_CHUNK

    // epilogue: BN + ReLU (+ fp16 pack for layer 1)
#pragma unroll
    for (int mt = 0; mt < 2; mt++) {
#pragma unroll
        for (int nt = 0; nt < 8; nt++) {
            int cl = wn * 64 + nt * 8 + (lane & 3) * 2;
            int gcol = bn + cl;
            int rl = wm * 32 + mt * 16 + (lane >> 2);
#pragma unroll
            for (int hh = 0; hh < 2; hh++) {
                int grow = bm + rl + hh * 8;
                float v0 = fmaxf(fmaf(c[mt][nt][hh * 2 + 0], s_al[cl],     s_be[cl]),     0.f);
                float v1 = fmaxf(fmaf(c[mt][nt][hh * 2 + 1], s_al[cl + 1], s_be[cl + 1]), 0.f);
                if (L == 1) {
                    *(uintT*)&gA2[(size_t)grow * 256 + gcol] = pack2(v0, v1);
                } else {
                    float2 o = make_float2(v0, v1);
                    *(float2*)&g_h[(size_t)grow * 256 + gcol] = o;
                }
            }
        }
    }
}

// ===================== encoding =====================
#define XSTR  260
#define CWSTR 36
#define ASTR  36
#define ENC_SMEM ((64 * XSTR + 256 * CWSTR + 64 * ASTR + 64) * 4)

__global__ __launch_bounds__(256) void encoding_kernel(const float* __restrict__ cw,
                                                       const float* __restrict__ scale)
{
    extern __shared__ float es[];
    float* sX  = es;
    float* cwT = es + 64 * XSTR;
    float* sA  = cwT + 256 * CWSTR;
    float* sXn = sA + 64 * ASTR;

    int bz = blockIdx.y, n0 = blockIdx.x * 64, t = threadIdx.x;
    const float* Xb = g_h + ((size_t)bz * NQ + n0) * 256;

    for (int i = t; i < 64 * 64; i += 256) {
        int p = i >> 6, d4 = i & 63;
        *(float4*)&sX[p * XSTR + d4 * 4] = *(const float4*)&Xb[(size_t)p * 256 + d4 * 4];
    }
    for (int i = t; i < 32 * 256; i += 256) {
        int k = i >> 8, d = i & 255;
        cwT[d * CWSTR + k] = cw[i];
    }
    __syncthreads();

    {
        int pg = t >> 3, kg = t & 7;
        const float* xr0 = sX + (2 * pg) * XSTR;
        const float* xr1 = xr0 + XSTR;
        const float* cwr = cwT + kg * 4;
        float a0[4] = {0.f, 0.f, 0.f, 0.f}, a1[4] = {0.f, 0.f, 0.f, 0.f};
        float xn0 = 0.f, xn1 = 0.f;
#pragma unroll 4
        for (int d = 0; d < 256; d += 4) {
            float4 x0 = *(const float4*)&xr0[d];
            float4 x1 = *(const float4*)&xr1[d];
            xn0 = fmaf(x0.x, x0.x, xn0); xn0 = fmaf(x0.y, x0.y, xn0);
            xn0 = fmaf(x0.z, x0.z, xn0); xn0 = fmaf(x0.w, x0.w, xn0);
            xn1 = fmaf(x1.x, x1.x, xn1); xn1 = fmaf(x1.y, x1.y, xn1);
            xn1 = fmaf(x1.z, x1.z, xn1); xn1 = fmaf(x1.w, x1.w, xn1);
            float xv0[4] = {x0.x, x0.y, x0.z, x0.w};
            float xv1[4] = {x1.x, x1.y, x1.z, x1.w};
#pragma unroll
            for (int dd = 0; dd < 4; dd++) {
                float4 c4 = *(const float4*)&cwr[(d + dd) * CWSTR];
                a0[0] = fmaf(xv0[dd], c4.x, a0[0]);
                a0[1] = fmaf(xv0[dd], c4.y, a0[1]);
                a0[2] = fmaf(xv0[dd], c4.z, a0[2]);
                a0[3] = fmaf(xv0[dd], c4.w, a0[3]);
                a1[0] = fmaf(xv1[dd], c4.x, a1[0]);
                a1[1] = fmaf(xv1[dd], c4.y, a1[1]);
                a1[2] = fmaf(xv1[dd], c4.z, a1[2]);
                a1[3] = fmaf(xv1[dd], c4.w, a1[3]);
            }
        }
        int p0 = 2 * pg, ks = kg * 4;
#pragma unroll
        for (int j = 0; j < 4; j++) {
            sA[p0 * ASTR + ks + j]       = a0[j];
            sA[(p0 + 1) * ASTR + ks + j] = a1[j];
        }
        if (kg == 0) { sXn[p0] = xn0; sXn[p0 + 1] = xn1; }
    }
    __syncthreads();

    {
        int warp = t >> 5, lane = t & 31;
        float sc = scale[lane], c2v = g_c2[lane];
        for (int pi = 0; pi < 8; pi++) {
            int p = warp * 8 + pi;
            float sl = sc * (sXn[p] - 2.f * sA[p * ASTR + lane] + c2v);
            float mx = sl;
#pragma unroll
            for (int o = 16; o > 0; o >>= 1) mx = fmaxf(mx, __shfl_xor_sync(0xffffffffu, mx, o));
            float e = __expf(sl - mx);
            float se = e;
#pragma unroll
            for (int o = 16; o > 0; o >>= 1) se += __shfl_xor_sync(0xffffffffu, se, o);
            sA[p * ASTR + lane] = e / se;
        }
    }
    __syncthreads();
    if (t < 32) {
        float s = 0.f;
        for (int p = 0; p < 64; p++) s += sA[p * ASTR + t];
        atomicAdd(&g_sumA[bz * 32 + t], s);
    }

    float acc[32];
#pragma unroll
    for (int k = 0; k < 32; k++) acc[k] = 0.f;
    for (int p = 0; p < 64; p++) {
        float x = sX[p * XSTR + t];
#pragma unroll
        for (int kq = 0; kq < 8; kq++) {
            float4 a4 = *(const float4*)&sA[p * ASTR + kq * 4];
            acc[kq * 4 + 0] = fmaf(a4.x, x, acc[kq * 4 + 0]);
            acc[kq * 4 + 1] = fmaf(a4.y, x, acc[kq * 4 + 1]);
            acc[kq * 4 + 2] = fmaf(a4.z, x, acc[kq * 4 + 2]);
            acc[kq * 4 + 3] = fmaf(a4.w, x, acc[kq * 4 + 3]);
        }
    }
    float* Eb = g_E + (size_t)bz * 8192;
#pragma unroll
    for (int k = 0; k < 32; k++) atomicAdd(&Eb[k * 256 + t], acc[k]);
}

__global__ __launch_bounds__(256) void enc_fin_kernel(const float* __restrict__ cw)
{
    __shared__ float red[256];
    int bz = blockIdx.x, t = threadIdx.x;
    float ss = 0.f;
    for (int j = t; j < 8192; j += 256) {
        float v = g_E[bz * 8192 + j] - g_sumA[bz * 32 + (j >> 8)] * cw[j];
        v = fmaxf(v, 0.f);
        g_En[bz * 8192 + j] = v;
        ss += v * v;
    }
    red[t] = ss;
    __syncthreads();
    for (int s = 128; s > 0; s >>= 1) {
        if (t < s) red[t] += red[t + s];
        __syncthreads();
    }
    float rinv = 1.f / fmaxf(sqrtf(red[0]), 1e-12f);
    for (int j = t; j < 8192; j += 256) g_En[bz * 8192 + j] *= rinv;
}

__global__ __launch_bounds__(256) void ctx_gemv_kernel(const float* __restrict__ lin_w,
                                                       const float* __restrict__ lin_b)
{
    __shared__ float red[8][256];
    int o = blockIdx.x, t = threadIdx.x;
    float acc[8];
#pragma unroll
    for (int b = 0; b < 8; b++) acc[b] = 0.f;
    const float* wrow = lin_w + (size_t)o * 8192;
    for (int j = t; j < 8192; j += 256) {
        float w = wrow[j];
#pragma unroll
        for (int b = 0; b < 8; b++) acc[b] = fmaf(w, g_En[b * 8192 + j], acc[b]);
    }
#pragma unroll
    for (int b = 0; b < 8; b++) red[b][t] = acc[b];
    __syncthreads();
    for (int s = 128; s > 0; s >>= 1) {
        if (t < s) {
#pragma unroll
            for (int b = 0; b < 8; b++) red[b][t] += red[b][t + s];
        }
        __syncthreads();
    }
    if (t < 8) {
        float z = red[t][0] + lin_b[o];
        g_ctx[t * 256 + o] = 1.f / (1.f + expf(-z));
    }
}

// ---------------- final: float4 tiled transpose + ctx scale ----------------
__global__ __launch_bounds__(256) void final_kernel(float* __restrict__ out)
{
    __shared__ float tile[32][33];
    int bz = blockIdx.z;
    int d0 = blockIdx.x * 32, n0 = blockIdx.y * 32;
    int t = threadIdx.x;
    int nr = t >> 3, q4 = (t & 7) * 4;
    const float* h = g_h + (size_t)bz * NQ * 256;
    float4 v = *(const float4*)&h[(size_t)(n0 + nr) * 256 + d0 + q4];
    tile[q4 + 0][nr] = v.x; tile[q4 + 1][nr] = v.y;
    tile[q4 + 2][nr] = v.z; tile[q4 + 3][nr] = v.w;
    __syncthreads();
    int dr = nr;
    float cx = g_ctx[bz * 256 + d0 + dr];
    float4 w = make_float4(tile[dr][q4 + 0] * cx, tile[dr][q4 + 1] * cx,
                           tile[dr][q4 + 2] * cx, tile[dr][q4 + 3] * cx);
    float* ob = out + (size_t)bz * 256 * NQ;
    *(float4*)&ob[(size_t)(d0 + dr) * NQ + n0 + q4] = w;
}

// ===================== launcher =====================
extern "C" void kernel_launch(void* const* d_in, const int* in_sizes, int n_in,
                              void* d_out, int out_size)
{
    (void)in_sizes; (void)n_in; (void)out_size;
    const float* unknown      = (const float*)d_in[0];
    const float* known        = (const float*)d_in[1];
    const float* unknow_feats = (const float*)d_in[2];
    const float* known_feats  = (const float*)d_in[3];
    const float* conv_w1 = (const float*)d_in[4];
    const float* conv_b1 = (const float*)d_in[5];
    const float* bn_g1 = (const float*)d_in[6];
    const float* bn_b1 = (const float*)d_in[7];
    const float* bn_m1 = (const float*)d_in[8];
    const float* bn_v1 = (const float*)d_in[9];
    const float* conv_w2 = (const float*)d_in[10];
    const float* conv_b2 = (const float*)d_in[11];
    const float* bn_g2 = (const float*)d_in[12];
    const float* bn_b2 = (const float*)d_in[13];
    const float* bn_m2 = (const float*)d_in[14];
    const float* bn_v2 = (const float*)d_in[15];
    const float* enc_cw    = (const float*)d_in[16];
    const float* enc_scale = (const float*)d_in[17];
    const float* lin_w     = (const float*)d_in[18];
    const float* lin_b     = (const float*)d_in[19];
    float* out = (float*)d_out;

    const int SMEMSZ = 6 * 8192 + 1024;   // 3 stages x (A 8KB + B 8KB) + alpha/beta
    static int attr_done = 0;
    if (!attr_done) {
        cudaFuncSetAttribute(gemm_mma<1>, cudaFuncAttributeMaxDynamicSharedMemorySize, SMEMSZ);
        cudaFuncSetAttribute(gemm_mma<2>, cudaFuncAttributeMaxDynamicSharedMemorySize, SMEMSZ);
        cudaFuncSetAttribute(encoding_kernel, cudaFuncAttributeMaxDynamicSharedMemorySize, ENC_SMEM);
        attr_done = 1;
    }

    front_kernel<<<FR_TOTAL, 256>>>(unknown, known, unknow_feats, known_feats,
                                    conv_w1, conv_w2,
                                    conv_b1, bn_g1, bn_b1, bn_m1, bn_v1,
                                    conv_b2, bn_g2, bn_b2, bn_m2, bn_v2, enc_cw);
    interp_kernel<<<dim3(NQ / 8, B_), 256>>>();
    gemm_mma<1><<<dim3(2, 512), 256, SMEMSZ>>>();
    gemm_mma<2><<<dim3(2, 512), 256, SMEMSZ>>>();
    encoding_kernel<<<dim3(NQ / 64, B_), 256, ENC_SMEM>>>(enc_cw, enc_scale);
    enc_fin_kernel<<<B_, 256>>>(enc_cw);
    ctx_gemv_kernel<<<256, 256>>>(lin_w, lin_b);
    final_kernel<<<dim3(8, NQ / 32, B_), 256>>>(out);
}